// round 2
// baseline (speedup 1.0000x reference)
#include <cuda_runtime.h>
#include <cuda_bf16.h>
#include <math.h>

// Problem constants
#define BB 4
#define SS 1024
#define EE 512
#define NHH 8
#define DD 64
#define NTOK (BB*SS)          // 4096
#define TOKE ((long)NTOK*EE)  // 2,097,152

// ------------------------- scratch (device globals) -------------------------
__device__ float g_q[NTOK*EE];
__device__ float g_k[NTOK*EE];
__device__ float g_v[NTOK*EE];
__device__ float g_scores[(long)BB*NHH*SS*SS];   // 33,554,432 floats
__device__ float g_att[NTOK*EE];
__device__ float g_tmp[NTOK*EE];
__device__ float g_body[NTOK*EE];
__device__ float g_limb[NTOK*EE];
__device__ float g_crossB[NTOK*EE];
__device__ float g_crossL[NTOK*EE];
__device__ float g_mixB[NTOK*EE];
__device__ float g_mixL[NTOK*EE];
__device__ float g_hid[(long)NTOK*4*EE];         // 4096 x 2048
__device__ float g_ffn[NTOK*EE];

// ------------------------- generic strided GEMM -------------------------
// C[i,j] = act( alpha * sum_l A[i,l]*B[l,j] + bias[j] )
// A is l-contiguous (row stride lda). B: if BT, element (l,j) at j*ldb+l,
// else at l*ldb+j. Batch z decomposed as (b = z/nh, h = z%nh) with separate
// offsets per operand.
#define BM 64
#define BN 64
#define BKK 16
#define TM 4
#define TN 4

template<bool BT, bool GELU_ACT>
__global__ __launch_bounds__(256) void gemm_k(
    const float* __restrict__ A, const float* __restrict__ Bm,
    const float* __restrict__ bias, float* __restrict__ C,
    int K, int lda, int ldb, int ldc,
    long aB, long aH, long bB, long bH, long cB, long cH, int nh,
    float alpha, const unsigned* __restrict__ tptr)
{
    __shared__ float As[BKK][BM + 1];
    __shared__ float Bs[BKK][BN + 1];

    int z = blockIdx.z;
    int bb = z / nh, hh = z % nh;
    A  += bb * aB + hh * aH;
    Bm += bb * bB + hh * bH;
    C  += bb * cB + hh * cH;

    int i0 = blockIdx.y * BM;
    int j0 = blockIdx.x * BN;
    int tid = threadIdx.x;
    int ty = tid >> 4, tx = tid & 15;

    float acc[TM][TN] = {};

    for (int l0 = 0; l0 < K; l0 += BKK) {
        // A tile: [BM x BKK], contiguous along l
        #pragma unroll
        for (int t = tid; t < BM * BKK; t += 256) {
            int r = t >> 4, c = t & 15;
            As[c][r] = A[(long)(i0 + r) * lda + (l0 + c)];
        }
        // B tile
        if (BT) {
            #pragma unroll
            for (int t = tid; t < BN * BKK; t += 256) {
                int j = t >> 4, l = t & 15;
                Bs[l][j] = Bm[(long)(j0 + j) * ldb + (l0 + l)];
            }
        } else {
            #pragma unroll
            for (int t = tid; t < BKK * BN; t += 256) {
                int l = t >> 6, j = t & 63;
                Bs[l][j] = Bm[(long)(l0 + l) * ldb + (j0 + j)];
            }
        }
        __syncthreads();

        #pragma unroll
        for (int l = 0; l < BKK; l++) {
            float ra[TM], rb[TN];
            #pragma unroll
            for (int u = 0; u < TM; u++) ra[u] = As[l][ty * TM + u];
            #pragma unroll
            for (int v = 0; v < TN; v++) rb[v] = Bs[l][tx * TN + v];
            #pragma unroll
            for (int u = 0; u < TM; u++)
                #pragma unroll
                for (int v = 0; v < TN; v++)
                    acc[u][v] = fmaf(ra[u], rb[v], acc[u][v]);
        }
        __syncthreads();
    }

    float a = alpha;
    if (tptr) {
        unsigned u = *tptr;
        float f = __uint_as_float(u);
        float temp = (f > 1e-6f && f < 1e6f) ? f : (float)(int)u;
        a /= temp;
    }

    #pragma unroll
    for (int u = 0; u < TM; u++) {
        int i = i0 + ty * TM + u;
        #pragma unroll
        for (int v = 0; v < TN; v++) {
            int j = j0 + tx * TN + v;
            float val = acc[u][v] * a;
            if (bias) val += bias[j];
            if (GELU_ACT) val = 0.5f * val * (1.f + erff(val * 0.70710678118654752f));
            C[(long)i * ldc + j] = val;
        }
    }
}

// ------------------------- softmax over rows of 1024 -------------------------
__global__ void softmax_k(float* __restrict__ data)
{
    int gwarp = (blockIdx.x * blockDim.x + threadIdx.x) >> 5;
    int lane = threadIdx.x & 31;
    float* row = data + (long)gwarp * SS;

    float4 v[8];
    float m = -1e30f;
    #pragma unroll
    for (int i = 0; i < 8; i++) {
        v[i] = ((const float4*)row)[lane + i * 32];
        m = fmaxf(m, fmaxf(fmaxf(v[i].x, v[i].y), fmaxf(v[i].z, v[i].w)));
    }
    #pragma unroll
    for (int o = 16; o; o >>= 1) m = fmaxf(m, __shfl_xor_sync(0xffffffffu, m, o));

    float s = 0.f;
    #pragma unroll
    for (int i = 0; i < 8; i++) {
        v[i].x = __expf(v[i].x - m);
        v[i].y = __expf(v[i].y - m);
        v[i].z = __expf(v[i].z - m);
        v[i].w = __expf(v[i].w - m);
        s += v[i].x + v[i].y + v[i].z + v[i].w;
    }
    #pragma unroll
    for (int o = 16; o; o >>= 1) s += __shfl_xor_sync(0xffffffffu, s, o);
    float inv = 1.f / s;
    #pragma unroll
    for (int i = 0; i < 8; i++) {
        v[i].x *= inv; v[i].y *= inv; v[i].z *= inv; v[i].w *= inv;
        ((float4*)row)[lane + i * 32] = v[i];
    }
}

// ------------------------- residual + layernorm -------------------------
// one block (128 threads) per row of E=512; res may be null
__global__ void ln_k(const float* __restrict__ x, const float* __restrict__ res,
                     const float* __restrict__ gamma, const float* __restrict__ beta,
                     float* __restrict__ out)
{
    long row = blockIdx.x;
    int t = threadIdx.x;
    float4 v = ((const float4*)(x + row * EE))[t];
    if (res) {
        float4 r = ((const float4*)(res + row * EE))[t];
        v.x += r.x; v.y += r.y; v.z += r.z; v.w += r.w;
    }
    float s = v.x + v.y + v.z + v.w;
    float q = v.x * v.x + v.y * v.y + v.z * v.z + v.w * v.w;
    #pragma unroll
    for (int o = 16; o; o >>= 1) {
        s += __shfl_xor_sync(0xffffffffu, s, o);
        q += __shfl_xor_sync(0xffffffffu, q, o);
    }
    __shared__ float shS[4], shQ[4];
    int w = t >> 5;
    if ((t & 31) == 0) { shS[w] = s; shQ[w] = q; }
    __syncthreads();
    s = shS[0] + shS[1] + shS[2] + shS[3];
    q = shQ[0] + shQ[1] + shQ[2] + shQ[3];
    float mean = s * (1.f / EE);
    float var = q * (1.f / EE) - mean * mean;
    float rstd = rsqrtf(var + 1e-5f);

    float4 g = ((const float4*)gamma)[t];
    float4 b = ((const float4*)beta)[t];
    float4 o;
    o.x = (v.x - mean) * rstd * g.x + b.x;
    o.y = (v.y - mean) * rstd * g.y + b.y;
    o.z = (v.z - mean) * rstd * g.z + b.z;
    o.w = (v.w - mean) * rstd * g.w + b.w;
    ((float4*)(out + row * EE))[t] = o;
}

// ------------------------- gate (softmax over 2) + mix -------------------------
__global__ void gate_mix_k(const float* __restrict__ x, const float* __restrict__ cr,
                           const float* __restrict__ gw, const float* __restrict__ gb,
                           float* __restrict__ out)
{
    long row = blockIdx.x;
    int t = threadIdx.x;
    float4 xv = ((const float4*)(x + row * EE))[t];
    float4 cv = ((const float4*)(cr + row * EE))[t];

    int k0 = t * 4;
    float l0 = 0.f, l1 = 0.f;
    float xs[4] = {xv.x, xv.y, xv.z, xv.w};
    float cs[4] = {cv.x, cv.y, cv.z, cv.w};
    #pragma unroll
    for (int e = 0; e < 4; e++) {
        int k = k0 + e;
        l0 += xs[e] * gw[k * 2 + 0] + cs[e] * gw[(EE + k) * 2 + 0];
        l1 += xs[e] * gw[k * 2 + 1] + cs[e] * gw[(EE + k) * 2 + 1];
    }
    #pragma unroll
    for (int o = 16; o; o >>= 1) {
        l0 += __shfl_xor_sync(0xffffffffu, l0, o);
        l1 += __shfl_xor_sync(0xffffffffu, l1, o);
    }
    __shared__ float sh0[4], sh1[4];
    int w = t >> 5;
    if ((t & 31) == 0) { sh0[w] = l0; sh1[w] = l1; }
    __syncthreads();
    l0 = sh0[0] + sh0[1] + sh0[2] + sh0[3] + gb[0];
    l1 = sh1[0] + sh1[1] + sh1[2] + sh1[3] + gb[1];
    float m = fmaxf(l0, l1);
    float e0 = __expf(l0 - m), e1 = __expf(l1 - m);
    float g0 = e0 / (e0 + e1), g1 = e1 / (e0 + e1);

    float4 o;
    o.x = xv.x * g0 + cv.x * g1;
    o.y = xv.y * g0 + cv.y * g1;
    o.z = xv.z * g0 + cv.z * g1;
    o.w = xv.w * g0 + cv.w * g1;
    ((float4*)(out + row * EE))[t] = o;
}

// ------------------------- host orchestration -------------------------
static float* sym(const void* s) {
    void* p = nullptr;
    cudaGetSymbolAddress(&p, s);
    return (float*)p;
}

// dense (batch-1) gemm helper: C[M x N] = act(A[M x K] @ W[K x N] + bias)
static void dense_gemm(const float* A, const float* W, const float* bias, float* C,
                       int M, int N, int K, bool gelu)
{
    dim3 grid(N / BN, M / BM, 1);
    if (gelu)
        gemm_k<false, true><<<grid, 256>>>(A, W, bias, C, K, K, N, N,
                                           0, 0, 0, 0, 0, 0, 1, 1.f, nullptr);
    else
        gemm_k<false, false><<<grid, 256>>>(A, W, bias, C, K, K, N, N,
                                            0, 0, 0, 0, 0, 0, 1, 1.f, nullptr);
}

struct Weights {
    const float *qw, *qb, *kw, *kb, *vw, *vb, *ow, *ob;
    const unsigned* temp;
};

// full MHA: out = attn(i, qx, kx, vx) using scratch q/k/v/scores/att
static void run_attn(int i, const float* qx, const float* kx, const float* vx,
                     const Weights& W, float* out)
{
    float* q = sym(g_q);
    float* k = sym(g_k);
    float* v = sym(g_v);
    float* sc = sym(g_scores);
    float* att = sym(g_att);
    long we = (long)i * EE * EE;
    long be = (long)i * EE;

    dense_gemm(qx, W.qw + we, W.qb + be, q, NTOK, EE, EE, false);
    dense_gemm(kx, W.kw + we, W.kb + be, k, NTOK, EE, EE, false);
    dense_gemm(vx, W.vw + we, W.vb + be, v, NTOK, EE, EE, false);

    // scores[b,h,q,k] = alpha * Q . K    (NT, batched over B*NH)
    {
        dim3 grid(SS / BN, SS / BM, BB * NHH);
        gemm_k<true, false><<<grid, 256>>>(
            q, k, nullptr, sc, DD,
            EE, EE, SS,
            (long)SS * EE, DD,            // A offsets (b,h)
            (long)SS * EE, DD,            // B offsets
            (long)NHH * SS * SS, (long)SS * SS,  // C offsets
            NHH, 0.125f, W.temp);
    }
    // softmax over rows (B*NH*S rows of S)
    softmax_k<<<(BB * NHH * SS) / 8, 256>>>(sc);

    // att[b,q,h*D+d] = P @ V (NN, batched)
    {
        dim3 grid(DD / BN, SS / BM, BB * NHH);
        gemm_k<false, false><<<grid, 256>>>(
            sc, v, nullptr, att, SS,
            SS, EE, EE,
            (long)NHH * SS * SS, (long)SS * SS,
            (long)SS * EE, DD,
            (long)SS * EE, DD,
            NHH, 1.f, nullptr);
    }
    // output projection
    dense_gemm(att, W.ow + we, W.ob + be, out, NTOK, EE, EE, false);
}

extern "C" void kernel_launch(void* const* d_in, const int* in_sizes, int n_in,
                              void* d_out, int out_size)
{
    const float* body_feats = (const float*)d_in[0];
    const float* limb_feats = (const float*)d_in[1];
    Weights W;
    W.qw = (const float*)d_in[2];  W.qb = (const float*)d_in[3];
    W.kw = (const float*)d_in[4];  W.kb = (const float*)d_in[5];
    W.vw = (const float*)d_in[6];  W.vb = (const float*)d_in[7];
    W.ow = (const float*)d_in[8];  W.ob = (const float*)d_in[9];
    const float* ffn_w1 = (const float*)d_in[10];
    const float* ffn_b1 = (const float*)d_in[11];
    const float* ffn_w2 = (const float*)d_in[12];
    const float* ffn_b2 = (const float*)d_in[13];
    const float* nsc = (const float*)d_in[14];
    const float* nbi = (const float*)d_in[15];
    const float* gw = (const float*)d_in[16];
    const float* gb = (const float*)d_in[17];
    W.temp = (const unsigned*)d_in[18];

    float* out = (float*)d_out;
    float* out_body = out;
    float* out_limb = out + TOKE;

    float* tmp   = sym(g_tmp);
    float* body  = sym(g_body);
    float* limb  = sym(g_limb);
    float* crB   = sym(g_crossB);
    float* crL   = sym(g_crossL);
    float* mixB  = sym(g_mixB);
    float* mixL  = sym(g_mixL);
    float* hid   = sym(g_hid);
    float* ffn   = sym(g_ffn);

    // self attentions + norm1
    run_attn(0, body_feats, body_feats, body_feats, W, tmp);
    ln_k<<<NTOK, 128>>>(body_feats, tmp, nsc + 0 * EE, nbi + 0 * EE, body);

    run_attn(1, limb_feats, limb_feats, limb_feats, W, tmp);
    ln_k<<<NTOK, 128>>>(limb_feats, tmp, nsc + 3 * EE, nbi + 3 * EE, limb);

    // cross attentions
    run_attn(2, body, limb, limb, W, crB);
    run_attn(3, limb, body, body, W, crL);

    // gating + mix, then norm2_body applied to BOTH streams (faithful to ref)
    gate_mix_k<<<NTOK, 128>>>(body, crB, gw, gb, mixB);
    gate_mix_k<<<NTOK, 128>>>(limb, crL, gw, gb, mixL);
    ln_k<<<NTOK, 128>>>(mixB, nullptr, nsc + 1 * EE, nbi + 1 * EE, body);
    ln_k<<<NTOK, 128>>>(mixL, nullptr, nsc + 1 * EE, nbi + 1 * EE, limb);

    // FFN body: ln2(body + ffn0(body)) -> out_body
    dense_gemm(body, ffn_w1 + 0, ffn_b1 + 0, hid, NTOK, 4 * EE, EE, true);
    dense_gemm(hid, ffn_w2 + 0, ffn_b2 + 0, ffn, NTOK, EE, 4 * EE, false);
    ln_k<<<NTOK, 128>>>(body, ffn, nsc + 2 * EE, nbi + 2 * EE, out_body);

    // FFN limb: ln5(limb + ffn1(limb)) -> out_limb
    dense_gemm(limb, ffn_w1 + (long)EE * 4 * EE, ffn_b1 + 4 * EE, hid, NTOK, 4 * EE, EE, true);
    dense_gemm(hid, ffn_w2 + (long)4 * EE * EE, ffn_b2 + EE, ffn, NTOK, EE, 4 * EE, false);
    ln_k<<<NTOK, 128>>>(limb, ffn, nsc + 5 * EE, nbi + 5 * EE, out_limb);
}

// round 3
// speedup vs baseline: 1.1171x; 1.1171x over previous
#include <cuda_runtime.h>
#include <cuda_bf16.h>
#include <math.h>

// Problem constants
#define BB 4
#define SS 1024
#define EE 512
#define NHH 8
#define DD 64
#define NTOK (BB*SS)          // 4096
#define TOKE ((long)NTOK*EE)  // 2,097,152

// ------------------------- scratch (device globals) -------------------------
__device__ float g_q[NTOK*EE];
__device__ float g_k[NTOK*EE];
__device__ float g_v[NTOK*EE];
__device__ float g_scores[(long)BB*NHH*SS*SS];   // 33,554,432 floats
__device__ float g_att[NTOK*EE];
__device__ float g_tmp[NTOK*EE];
__device__ float g_body[NTOK*EE];
__device__ float g_limb[NTOK*EE];
__device__ float g_crossB[NTOK*EE];
__device__ float g_crossL[NTOK*EE];
__device__ float g_mixB[NTOK*EE];
__device__ float g_mixL[NTOK*EE];
__device__ float g_hid[(long)NTOK*4*EE];         // 4096 x 2048
__device__ float g_ffn[NTOK*EE];

// ------------------------- f32x2 helpers -------------------------
typedef unsigned long long ull;

__device__ __forceinline__ void ffma2(ull& d, ull a, ull b) {
    asm("fma.rn.f32x2 %0, %1, %2, %0;" : "+l"(d) : "l"(a), "l"(b));
}
__device__ __forceinline__ void unpack2(float& x, float& y, ull v) {
    asm("mov.b64 {%0, %1}, %2;" : "=f"(x), "=f"(y) : "l"(v));
}

// ------------------------- generic strided GEMM (f32x2) -------------------------
// C[i,j] = act( alpha * sum_l A[i,l]*B[l,j] + bias[j] )
// A row-major (l-contiguous, stride lda). B: if BT, element (l,j) at j*ldb+l,
// else l*ldb+j. Batch z = (b,h) with per-operand offsets.
// Tile: BM=16*TM rows x BN=16*TN cols, BK=16, 256 threads (16x16), TMxTN microtile.
// A tile stored VALUE-DUPLICATED in smem so ulonglong2 loads give (a,a) pairs
// for fma.rn.f32x2 with zero packing MOVs.

template<int TM, int TN, bool BT, bool GELU_ACT>
__global__ __launch_bounds__(256) void gemm2_k(
    const float* __restrict__ A, const float* __restrict__ Bm,
    const float* __restrict__ bias, float* __restrict__ C,
    int K, int lda, int ldb, int ldc,
    long aB, long aH, long bB, long bH, long cB, long cH, int nh,
    float alpha, const unsigned* __restrict__ tptr)
{
    constexpr int BM = 16 * TM;
    constexpr int BN = 16 * TN;
    constexpr int BK = 16;
    constexpr int ASTR = 2 * BM + 8;   // duplicated row stride (floats), 16B-aligned
    constexpr int BSTR = BN + 4;       // 16B-aligned row stride

    __shared__ __align__(16) float As[BK * ASTR];
    __shared__ __align__(16) float Bs[BK * BSTR];

    int z = blockIdx.z;
    int bb = z / nh, hh = z % nh;
    A  += bb * aB + hh * aH;
    Bm += bb * bB + hh * bH;
    C  += bb * cB + hh * cH;

    int i0 = blockIdx.y * BM;
    int j0 = blockIdx.x * BN;
    int tid = threadIdx.x;
    int ty = tid >> 4, tx = tid & 15;

    ull acc[TM][TN / 2];
    #pragma unroll
    for (int u = 0; u < TM; u++)
        #pragma unroll
        for (int v = 0; v < TN / 2; v++) acc[u][v] = 0ull;

    for (int l0 = 0; l0 < K; l0 += BK) {
        // ---- A tile: BM x BK, loaded as float4 along K, stored duplicated ----
        #pragma unroll
        for (int it = 0; it < (BM * 4) / 256; it++) {
            int idx = tid + it * 256;
            int r = idx >> 2, c4 = idx & 3;
            float4 v = *(const float4*)&A[(long)(i0 + r) * lda + (l0 + c4 * 4)];
            *(float2*)&As[(c4 * 4 + 0) * ASTR + 2 * r] = make_float2(v.x, v.x);
            *(float2*)&As[(c4 * 4 + 1) * ASTR + 2 * r] = make_float2(v.y, v.y);
            *(float2*)&As[(c4 * 4 + 2) * ASTR + 2 * r] = make_float2(v.z, v.z);
            *(float2*)&As[(c4 * 4 + 3) * ASTR + 2 * r] = make_float2(v.w, v.w);
        }
        // ---- B tile ----
        if (BT) {
            // BN rows (j) x BK (l): float4 along l, transpose-store
            #pragma unroll
            for (int it = 0; it < (BN * 4) / 256; it++) {
                int idx = tid + it * 256;
                int r = idx >> 2, c4 = idx & 3;
                float4 v = *(const float4*)&Bm[(long)(j0 + r) * ldb + (l0 + c4 * 4)];
                Bs[(c4 * 4 + 0) * BSTR + r] = v.x;
                Bs[(c4 * 4 + 1) * BSTR + r] = v.y;
                Bs[(c4 * 4 + 2) * BSTR + r] = v.z;
                Bs[(c4 * 4 + 3) * BSTR + r] = v.w;
            }
        } else {
            // BK rows (l) x BN (j): float4 along j, direct store
            #pragma unroll
            for (int it = 0; it < (BN * 4) / 256; it++) {
                int idx = tid + it * 256;
                int r = idx / (BN / 4), c4 = idx % (BN / 4);
                float4 v = *(const float4*)&Bm[(long)(l0 + r) * ldb + (j0 + c4 * 4)];
                *(float4*)&Bs[r * BSTR + c4 * 4] = v;
            }
        }
        __syncthreads();

        #pragma unroll
        for (int l = 0; l < BK; l++) {
            ull ra[TM];
            const ulonglong2* pa = (const ulonglong2*)&As[l * ASTR + ty * 2 * TM];
            #pragma unroll
            for (int i = 0; i < TM / 2; i++) {
                ulonglong2 t = pa[i];
                ra[2 * i] = t.x; ra[2 * i + 1] = t.y;
            }
            ull rb[TN / 2];
            const ulonglong2* pb = (const ulonglong2*)&Bs[l * BSTR + tx * TN];
            #pragma unroll
            for (int i = 0; i < TN / 4; i++) {
                ulonglong2 t = pb[i];
                rb[2 * i] = t.x; rb[2 * i + 1] = t.y;
            }
            #pragma unroll
            for (int u = 0; u < TM; u++)
                #pragma unroll
                for (int v = 0; v < TN / 2; v++)
                    ffma2(acc[u][v], ra[u], rb[v]);
        }
        __syncthreads();
    }

    float a = alpha;
    if (tptr) {
        unsigned u = *tptr;
        float f = __uint_as_float(u);
        float temp = (f > 1e-6f && f < 1e6f) ? f : (float)(int)u;
        a /= temp;
    }

    #pragma unroll
    for (int u = 0; u < TM; u++) {
        int i = i0 + ty * TM + u;
        #pragma unroll
        for (int v = 0; v < TN / 2; v++) {
            int j = j0 + tx * TN + 2 * v;
            float x, y;
            unpack2(x, y, acc[u][v]);
            x *= a; y *= a;
            if (bias) { x += bias[j]; y += bias[j + 1]; }
            if (GELU_ACT) {
                x = 0.5f * x * (1.f + erff(x * 0.70710678118654752f));
                y = 0.5f * y * (1.f + erff(y * 0.70710678118654752f));
            }
            *(float2*)&C[(long)i * ldc + j] = make_float2(x, y);
        }
    }
}

// ------------------------- softmax over rows of 1024 -------------------------
__global__ void softmax_k(float* __restrict__ data)
{
    int gwarp = (blockIdx.x * blockDim.x + threadIdx.x) >> 5;
    int lane = threadIdx.x & 31;
    float* row = data + (long)gwarp * SS;

    float4 v[8];
    float m = -1e30f;
    #pragma unroll
    for (int i = 0; i < 8; i++) {
        v[i] = ((const float4*)row)[lane + i * 32];
        m = fmaxf(m, fmaxf(fmaxf(v[i].x, v[i].y), fmaxf(v[i].z, v[i].w)));
    }
    #pragma unroll
    for (int o = 16; o; o >>= 1) m = fmaxf(m, __shfl_xor_sync(0xffffffffu, m, o));

    float s = 0.f;
    #pragma unroll
    for (int i = 0; i < 8; i++) {
        v[i].x = __expf(v[i].x - m);
        v[i].y = __expf(v[i].y - m);
        v[i].z = __expf(v[i].z - m);
        v[i].w = __expf(v[i].w - m);
        s += v[i].x + v[i].y + v[i].z + v[i].w;
    }
    #pragma unroll
    for (int o = 16; o; o >>= 1) s += __shfl_xor_sync(0xffffffffu, s, o);
    float inv = 1.f / s;
    #pragma unroll
    for (int i = 0; i < 8; i++) {
        v[i].x *= inv; v[i].y *= inv; v[i].z *= inv; v[i].w *= inv;
        ((float4*)row)[lane + i * 32] = v[i];
    }
}

// ------------------------- residual + layernorm -------------------------
__global__ void ln_k(const float* __restrict__ x, const float* __restrict__ res,
                     const float* __restrict__ gamma, const float* __restrict__ beta,
                     float* __restrict__ out)
{
    long row = blockIdx.x;
    int t = threadIdx.x;
    float4 v = ((const float4*)(x + row * EE))[t];
    if (res) {
        float4 r = ((const float4*)(res + row * EE))[t];
        v.x += r.x; v.y += r.y; v.z += r.z; v.w += r.w;
    }
    float s = v.x + v.y + v.z + v.w;
    float q = v.x * v.x + v.y * v.y + v.z * v.z + v.w * v.w;
    #pragma unroll
    for (int o = 16; o; o >>= 1) {
        s += __shfl_xor_sync(0xffffffffu, s, o);
        q += __shfl_xor_sync(0xffffffffu, q, o);
    }
    __shared__ float shS[4], shQ[4];
    int w = t >> 5;
    if ((t & 31) == 0) { shS[w] = s; shQ[w] = q; }
    __syncthreads();
    s = shS[0] + shS[1] + shS[2] + shS[3];
    q = shQ[0] + shQ[1] + shQ[2] + shQ[3];
    float mean = s * (1.f / EE);
    float var = q * (1.f / EE) - mean * mean;
    float rstd = rsqrtf(var + 1e-5f);

    float4 g = ((const float4*)gamma)[t];
    float4 b = ((const float4*)beta)[t];
    float4 o;
    o.x = (v.x - mean) * rstd * g.x + b.x;
    o.y = (v.y - mean) * rstd * g.y + b.y;
    o.z = (v.z - mean) * rstd * g.z + b.z;
    o.w = (v.w - mean) * rstd * g.w + b.w;
    ((float4*)(out + row * EE))[t] = o;
}

// ------------------------- gate (softmax over 2) + mix -------------------------
__global__ void gate_mix_k(const float* __restrict__ x, const float* __restrict__ cr,
                           const float* __restrict__ gw, const float* __restrict__ gb,
                           float* __restrict__ out)
{
    long row = blockIdx.x;
    int t = threadIdx.x;
    float4 xv = ((const float4*)(x + row * EE))[t];
    float4 cv = ((const float4*)(cr + row * EE))[t];

    int k0 = t * 4;
    float l0 = 0.f, l1 = 0.f;
    float xs[4] = {xv.x, xv.y, xv.z, xv.w};
    float cs[4] = {cv.x, cv.y, cv.z, cv.w};
    #pragma unroll
    for (int e = 0; e < 4; e++) {
        int k = k0 + e;
        l0 += xs[e] * gw[k * 2 + 0] + cs[e] * gw[(EE + k) * 2 + 0];
        l1 += xs[e] * gw[k * 2 + 1] + cs[e] * gw[(EE + k) * 2 + 1];
    }
    #pragma unroll
    for (int o = 16; o; o >>= 1) {
        l0 += __shfl_xor_sync(0xffffffffu, l0, o);
        l1 += __shfl_xor_sync(0xffffffffu, l1, o);
    }
    __shared__ float sh0[4], sh1[4];
    int w = t >> 5;
    if ((t & 31) == 0) { sh0[w] = l0; sh1[w] = l1; }
    __syncthreads();
    l0 = sh0[0] + sh0[1] + sh0[2] + sh0[3] + gb[0];
    l1 = sh1[0] + sh1[1] + sh1[2] + sh1[3] + gb[1];
    float m = fmaxf(l0, l1);
    float e0 = __expf(l0 - m), e1 = __expf(l1 - m);
    float g0 = e0 / (e0 + e1), g1 = e1 / (e0 + e1);

    float4 o;
    o.x = xv.x * g0 + cv.x * g1;
    o.y = xv.y * g0 + cv.y * g1;
    o.z = xv.z * g0 + cv.z * g1;
    o.w = xv.w * g0 + cv.w * g1;
    ((float4*)(out + row * EE))[t] = o;
}

// ------------------------- host orchestration -------------------------
static float* sym(const void* s) {
    void* p = nullptr;
    cudaGetSymbolAddress(&p, s);
    return (float*)p;
}

// dense (batch-1) gemm: C[M x N] = act(A[M x K] @ W[K x N] + bias). N % 128 == 0.
static void dense_gemm(const float* A, const float* W, const float* bias, float* C,
                       int M, int N, int K, bool gelu)
{
    dim3 grid(N / 128, M / 128, 1);
    if (gelu)
        gemm2_k<8, 8, false, true><<<grid, 256>>>(A, W, bias, C, K, K, N, N,
                                                  0, 0, 0, 0, 0, 0, 1, 1.f, nullptr);
    else
        gemm2_k<8, 8, false, false><<<grid, 256>>>(A, W, bias, C, K, K, N, N,
                                                   0, 0, 0, 0, 0, 0, 1, 1.f, nullptr);
}

struct Weights {
    const float *qw, *qb, *kw, *kb, *vw, *vb, *ow, *ob;
    const unsigned* temp;
};

static void run_attn(int i, const float* qx, const float* kx, const float* vx,
                     const Weights& W, float* out)
{
    float* q = sym(g_q);
    float* k = sym(g_k);
    float* v = sym(g_v);
    float* sc = sym(g_scores);
    float* att = sym(g_att);
    long we = (long)i * EE * EE;
    long be = (long)i * EE;

    dense_gemm(qx, W.qw + we, W.qb + be, q, NTOK, EE, EE, false);
    dense_gemm(kx, W.kw + we, W.kb + be, k, NTOK, EE, EE, false);
    dense_gemm(vx, W.vw + we, W.vb + be, v, NTOK, EE, EE, false);

    // scores[b,h,q,k] = alpha * Q . K    (NT, batched over B*NH)
    {
        dim3 grid(SS / 128, SS / 128, BB * NHH);
        gemm2_k<8, 8, true, false><<<grid, 256>>>(
            q, k, nullptr, sc, DD,
            EE, EE, SS,
            (long)SS * EE, DD,
            (long)SS * EE, DD,
            (long)NHH * SS * SS, (long)SS * SS,
            NHH, 0.125f, W.temp);
    }
    softmax_k<<<(BB * NHH * SS) / 8, 256>>>(sc);

    // att[b,q,h*D+d] = P @ V (NN, batched). N=64 -> TN=4 config (BN=64).
    {
        dim3 grid(1, SS / 128, BB * NHH);
        gemm2_k<8, 4, false, false><<<grid, 256>>>(
            sc, v, nullptr, att, SS,
            SS, EE, EE,
            (long)NHH * SS * SS, (long)SS * SS,
            (long)SS * EE, DD,
            (long)SS * EE, DD,
            NHH, 1.f, nullptr);
    }
    dense_gemm(att, W.ow + we, W.ob + be, out, NTOK, EE, EE, false);
}

extern "C" void kernel_launch(void* const* d_in, const int* in_sizes, int n_in,
                              void* d_out, int out_size)
{
    const float* body_feats = (const float*)d_in[0];
    const float* limb_feats = (const float*)d_in[1];
    Weights W;
    W.qw = (const float*)d_in[2];  W.qb = (const float*)d_in[3];
    W.kw = (const float*)d_in[4];  W.kb = (const float*)d_in[5];
    W.vw = (const float*)d_in[6];  W.vb = (const float*)d_in[7];
    W.ow = (const float*)d_in[8];  W.ob = (const float*)d_in[9];
    const float* ffn_w1 = (const float*)d_in[10];
    const float* ffn_b1 = (const float*)d_in[11];
    const float* ffn_w2 = (const float*)d_in[12];
    const float* ffn_b2 = (const float*)d_in[13];
    const float* nsc = (const float*)d_in[14];
    const float* nbi = (const float*)d_in[15];
    const float* gw = (const float*)d_in[16];
    const float* gb = (const float*)d_in[17];
    W.temp = (const unsigned*)d_in[18];

    float* out = (float*)d_out;
    float* out_body = out;
    float* out_limb = out + TOKE;

    float* tmp   = sym(g_tmp);
    float* body  = sym(g_body);
    float* limb  = sym(g_limb);
    float* crB   = sym(g_crossB);
    float* crL   = sym(g_crossL);
    float* mixB  = sym(g_mixB);
    float* mixL  = sym(g_mixL);
    float* hid   = sym(g_hid);
    float* ffn   = sym(g_ffn);

    // self attentions + norm1
    run_attn(0, body_feats, body_feats, body_feats, W, tmp);
    ln_k<<<NTOK, 128>>>(body_feats, tmp, nsc + 0 * EE, nbi + 0 * EE, body);

    run_attn(1, limb_feats, limb_feats, limb_feats, W, tmp);
    ln_k<<<NTOK, 128>>>(limb_feats, tmp, nsc + 3 * EE, nbi + 3 * EE, limb);

    // cross attentions
    run_attn(2, body, limb, limb, W, crB);
    run_attn(3, limb, body, body, W, crL);

    // gating + mix, then norm2_body applied to BOTH streams (faithful to ref)
    gate_mix_k<<<NTOK, 128>>>(body, crB, gw, gb, mixB);
    gate_mix_k<<<NTOK, 128>>>(limb, crL, gw, gb, mixL);
    ln_k<<<NTOK, 128>>>(mixB, nullptr, nsc + 1 * EE, nbi + 1 * EE, body);
    ln_k<<<NTOK, 128>>>(mixL, nullptr, nsc + 1 * EE, nbi + 1 * EE, limb);

    // FFN body: ln2(body + ffn0(body)) -> out_body
    dense_gemm(body, ffn_w1 + 0, ffn_b1 + 0, hid, NTOK, 4 * EE, EE, true);
    dense_gemm(hid, ffn_w2 + 0, ffn_b2 + 0, ffn, NTOK, EE, 4 * EE, false);
    ln_k<<<NTOK, 128>>>(body, ffn, nsc + 2 * EE, nbi + 2 * EE, out_body);

    // FFN limb: ln5(limb + ffn1(limb)) -> out_limb
    dense_gemm(limb, ffn_w1 + (long)EE * 4 * EE, ffn_b1 + 4 * EE, hid, NTOK, 4 * EE, EE, true);
    dense_gemm(hid, ffn_w2 + (long)4 * EE * EE, ffn_b2 + EE, ffn, NTOK, EE, 4 * EE, false);
    ln_k<<<NTOK, 128>>>(limb, ffn, nsc + 5 * EE, nbi + 5 * EE, out_limb);
}

// round 5
// speedup vs baseline: 2.3487x; 2.1026x over previous
#include <cuda_runtime.h>
#include <cuda_bf16.h>
#include <math.h>

typedef unsigned int u32;
typedef unsigned long long u64;

#define BB 4
#define SS 1024
#define EE 512
#define NHH 8
#define DD 64
#define NTOK (BB*SS)          // 4096
#define TOKE ((long)NTOK*EE)  // 2,097,152
#define NB (BB*NHH)           // 32

// ------------------------- fp32 scratch -------------------------
__device__ float g_q[NTOK*EE];
__device__ float g_k[NTOK*EE];
__device__ float g_v[NTOK*EE];
__device__ float g_scores[(long)NB*SS*SS];
__device__ float g_att[NTOK*EE];
__device__ float g_tmp[NTOK*EE];
__device__ float g_body[NTOK*EE];
__device__ float g_limb[NTOK*EE];
__device__ float g_crossB[NTOK*EE];
__device__ float g_crossL[NTOK*EE];
__device__ float g_mixB[NTOK*EE];
__device__ float g_mixL[NTOK*EE];
__device__ float g_hid[(long)NTOK*4*EE];
__device__ float g_ffn[NTOK*EE];

// ------------------------- bf16 split scratch (16B aligned) -------------------------
__device__ __align__(16) __nv_bfloat16 g_in1h[NTOK*EE], g_in1l[NTOK*EE];
__device__ __align__(16) __nv_bfloat16 g_in2h[NTOK*EE], g_in2l[NTOK*EE];
__device__ __align__(16) __nv_bfloat16 g_qh[NTOK*EE],  g_ql[NTOK*EE];
__device__ __align__(16) __nv_bfloat16 g_kh[NTOK*EE],  g_kl[NTOK*EE];
__device__ __align__(16) __nv_bfloat16 g_vth[NTOK*EE], g_vtl[NTOK*EE];   // V^T per head
__device__ __align__(16) __nv_bfloat16 g_atth[NTOK*EE], g_attl[NTOK*EE];
__device__ __align__(16) __nv_bfloat16 g_ph[(long)NB*SS*SS], g_pl[(long)NB*SS*SS];
__device__ __align__(16) __nv_bfloat16 g_hidh[(long)NTOK*4*EE], g_hidl[(long)NTOK*4*EE];
__device__ __align__(16) __nv_bfloat16 g_qwth[4*EE*EE], g_qwtl[4*EE*EE];
__device__ __align__(16) __nv_bfloat16 g_kwth[4*EE*EE], g_kwtl[4*EE*EE];
__device__ __align__(16) __nv_bfloat16 g_vwth[4*EE*EE], g_vwtl[4*EE*EE];
__device__ __align__(16) __nv_bfloat16 g_owth[4*EE*EE], g_owtl[4*EE*EE];
__device__ __align__(16) __nv_bfloat16 g_w1th[(long)2*EE*4*EE], g_w1tl[(long)2*EE*4*EE];
__device__ __align__(16) __nv_bfloat16 g_w2th[(long)2*EE*4*EE], g_w2tl[(long)2*EE*4*EE];

// ------------------------- mma/ldmatrix helpers -------------------------
__device__ __forceinline__ u32 s2u(const void* p) {
    u32 a;
    asm("{ .reg .u64 t; cvta.to.shared.u64 t, %1; cvt.u32.u64 %0, t; }" : "=r"(a) : "l"(p));
    return a;
}
__device__ __forceinline__ void ldsm_x4(u32 r[4], u32 addr) {
    asm volatile("ldmatrix.sync.aligned.m8n8.x4.shared.b16 {%0,%1,%2,%3}, [%4];"
                 : "=r"(r[0]), "=r"(r[1]), "=r"(r[2]), "=r"(r[3]) : "r"(addr));
}
__device__ __forceinline__ void ldsm_x2(u32 r[2], u32 addr) {
    asm volatile("ldmatrix.sync.aligned.m8n8.x2.shared.b16 {%0,%1}, [%2];"
                 : "=r"(r[0]), "=r"(r[1]) : "r"(addr));
}
__device__ __forceinline__ void mma16816(float c[4], const u32 a[4], const u32 b[2]) {
    asm volatile(
        "mma.sync.aligned.m16n8k16.row.col.f32.bf16.bf16.f32 "
        "{%0,%1,%2,%3}, {%4,%5,%6,%7}, {%8,%9}, {%0,%1,%2,%3};"
        : "+f"(c[0]), "+f"(c[1]), "+f"(c[2]), "+f"(c[3])
        : "r"(a[0]), "r"(a[1]), "r"(a[2]), "r"(a[3]), "r"(b[0]), "r"(b[1]));
}

// ------------------------- bf16-split tensor-core GEMM -------------------------
// C[i,j] = act(alpha * sum_l A[i,l]*B[j,l] + bias[j])   i.e. D = A @ B^T
// A: [M x K] bf16 hi/lo (row stride lda). B: [N x K] bf16 hi/lo (row stride ldb).
// Block tile 128 x BN (BN = 2*WN), BK=32. 256 threads = 8 warps (4 m x 2 n),
// warp tile 32 x WN. Batch z=(b,h) with per-operand elem offsets.
template<int WN, bool GELU>
__global__ void __launch_bounds__(256) gemm_mma(
    const __nv_bfloat16* __restrict__ Ah, const __nv_bfloat16* __restrict__ Al,
    const __nv_bfloat16* __restrict__ Bh, const __nv_bfloat16* __restrict__ Bl,
    const float* __restrict__ bias, float* __restrict__ C,
    int K, int lda, int ldb, int ldc,
    long aB, long aH, long bB, long bH, long cB, long cH, int nh,
    float alpha, const unsigned* __restrict__ tptr)
{
    constexpr int BN = 2 * WN;
    constexpr int STR = 40;   // padded row stride (elems); 80B, ldmatrix conflict-free

    __shared__ __align__(16) __nv_bfloat16 sAh[128 * STR], sAl[128 * STR];
    __shared__ __align__(16) __nv_bfloat16 sBh[BN * STR],  sBl[BN * STR];

    int z = blockIdx.z;
    int bb = z / nh, hh = z - bb * nh;
    Ah += bb * aB + hh * aH;  Al += bb * aB + hh * aH;
    Bh += bb * bB + hh * bH;  Bl += bb * bB + hh * bH;
    C  += bb * cB + hh * cH;

    int i0 = blockIdx.y * 128;
    int j0 = blockIdx.x * BN;
    int tid = threadIdx.x;
    int lane = tid & 31, wid = tid >> 5;
    int wm = wid & 3, wn = wid >> 2;

    float acc[2][WN / 8][4] = {};

    for (int kc = 0; kc < K; kc += 32) {
        // ---- A tiles: 128 rows x 32 (4 segs of 8 bf16) ----
        #pragma unroll
        for (int t = 0; t < 2; t++) {
            int idx = tid + t * 256;
            int r = idx >> 2, sg = idx & 3;
            long go = (long)(i0 + r) * lda + kc + sg * 8;
            *(uint4*)&sAh[r * STR + sg * 8] = *(const uint4*)(Ah + go);
            *(uint4*)&sAl[r * STR + sg * 8] = *(const uint4*)(Al + go);
        }
        // ---- B tiles: BN rows x 32 ----
        #pragma unroll
        for (int t = 0; t < BN / 64; t++) {
            int idx = tid + t * 256;
            int r = idx >> 2, sg = idx & 3;
            long go = (long)(j0 + r) * ldb + kc + sg * 8;
            *(uint4*)&sBh[r * STR + sg * 8] = *(const uint4*)(Bh + go);
            *(uint4*)&sBl[r * STR + sg * 8] = *(const uint4*)(Bl + go);
        }
        __syncthreads();

        #pragma unroll
        for (int ks = 0; ks < 2; ks++) {
            u32 afh[2][4], afl[2][4];
            #pragma unroll
            for (int mt = 0; mt < 2; mt++) {
                int row = wm * 32 + mt * 16 + (lane & 15);
                int col = ks * 16 + (lane >> 4) * 8;
                ldsm_x4(afh[mt], s2u(&sAh[row * STR + col]));
                ldsm_x4(afl[mt], s2u(&sAl[row * STR + col]));
            }
            #pragma unroll
            for (int nt = 0; nt < WN / 8; nt++) {
                int brow = wn * WN + nt * 8 + (lane & 7);
                int bcol = ks * 16 + ((lane >> 3) & 1) * 8;
                u32 bh[2], bl[2];
                ldsm_x2(bh, s2u(&sBh[brow * STR + bcol]));
                ldsm_x2(bl, s2u(&sBl[brow * STR + bcol]));
                #pragma unroll
                for (int mt = 0; mt < 2; mt++) {
                    mma16816(acc[mt][nt], afh[mt], bh);
                    mma16816(acc[mt][nt], afh[mt], bl);
                    mma16816(acc[mt][nt], afl[mt], bh);
                }
            }
        }
        __syncthreads();
    }

    float scl = alpha;
    if (tptr) {
        unsigned u = *tptr;
        float f = __uint_as_float(u);
        float temp = (f > 1e-6f && f < 1e6f) ? f : (float)(int)u;
        scl /= temp;
    }

    // ---- epilogue ----
    int grp = lane >> 2, qd = lane & 3;
    #pragma unroll
    for (int mt = 0; mt < 2; mt++) {
        #pragma unroll
        for (int nt = 0; nt < WN / 8; nt++) {
            int n = j0 + wn * WN + nt * 8 + qd * 2;
            float b0 = 0.f, b1 = 0.f;
            if (bias) { b0 = bias[n]; b1 = bias[n + 1]; }
            #pragma unroll
            for (int rh = 0; rh < 2; rh++) {
                int m = i0 + wm * 32 + mt * 16 + grp + rh * 8;
                float x = acc[mt][nt][rh * 2 + 0] * scl + b0;
                float y = acc[mt][nt][rh * 2 + 1] * scl + b1;
                if (GELU) {
                    x = 0.5f * x * (1.f + erff(x * 0.70710678118654752f));
                    y = 0.5f * y * (1.f + erff(y * 0.70710678118654752f));
                }
                *(float2*)&C[(long)m * ldc + n] = make_float2(x, y);
            }
        }
    }
}

// ------------------------- elementwise hi/lo split -------------------------
__global__ void split_k(const float* __restrict__ x, __nv_bfloat16* __restrict__ h,
                        __nv_bfloat16* __restrict__ l, long n)
{
    long i = ((long)blockIdx.x * blockDim.x + threadIdx.x) * 4;
    if (i >= n) return;
    float4 v = *(const float4*)(x + i);
    float vv[4] = {v.x, v.y, v.z, v.w};
    u32 hp[2] = {0, 0}, lp[2] = {0, 0};
    #pragma unroll
    for (int e = 0; e < 4; e++) {
        __nv_bfloat16 hb = __float2bfloat16(vv[e]);
        __nv_bfloat16 lb = __float2bfloat16(vv[e] - __bfloat162float(hb));
        hp[e >> 1] |= (u32)__bfloat16_as_ushort(hb) << ((e & 1) * 16);
        lp[e >> 1] |= (u32)__bfloat16_as_ushort(lb) << ((e & 1) * 16);
    }
    *(uint2*)(h + i) = make_uint2(hp[0], hp[1]);
    *(uint2*)(l + i) = make_uint2(lp[0], lp[1]);
}

// ------------------------- transpose + split -------------------------
__global__ void tsplit_k(const float* __restrict__ src, __nv_bfloat16* __restrict__ h,
                         __nv_bfloat16* __restrict__ l,
                         int lds, int ldd, long sB, long sH, long dB, long dH, int nh)
{
    __shared__ float sm[32][33];
    int z = blockIdx.z;
    int bb = z / nh, hh = z - bb * nh;
    src += bb * sB + hh * sH;
    h   += bb * dB + hh * dH;
    l   += bb * dB + hh * dH;
    int r0 = blockIdx.y * 32, c0 = blockIdx.x * 32;
    int tx = threadIdx.x, ty = threadIdx.y;
    #pragma unroll
    for (int i = 0; i < 4; i++)
        sm[ty + 8 * i][tx] = src[(long)(r0 + ty + 8 * i) * lds + c0 + tx];
    __syncthreads();
    #pragma unroll
    for (int i = 0; i < 4; i++) {
        int n = c0 + ty + 8 * i, k = r0 + tx;
        float v = sm[tx][ty + 8 * i];
        __nv_bfloat16 hv = __float2bfloat16(v);
        __nv_bfloat16 lv = __float2bfloat16(v - __bfloat162float(hv));
        h[(long)n * ldd + k] = hv;
        l[(long)n * ldd + k] = lv;
    }
}

// ------------------------- softmax (rows of 1024) -> bf16 hi/lo -------------------------
__global__ void softmax_split_k(const float* __restrict__ sc,
                                __nv_bfloat16* __restrict__ ph, __nv_bfloat16* __restrict__ pl)
{
    long gwarp = ((long)blockIdx.x * blockDim.x + threadIdx.x) >> 5;
    int lane = threadIdx.x & 31;
    const float* row = sc + gwarp * SS;
    long ob = gwarp * SS;

    float4 v[8];
    float m = -1e30f;
    #pragma unroll
    for (int i = 0; i < 8; i++) {
        v[i] = ((const float4*)row)[lane + i * 32];
        m = fmaxf(m, fmaxf(fmaxf(v[i].x, v[i].y), fmaxf(v[i].z, v[i].w)));
    }
    #pragma unroll
    for (int o = 16; o; o >>= 1) m = fmaxf(m, __shfl_xor_sync(0xffffffffu, m, o));
    float s = 0.f;
    #pragma unroll
    for (int i = 0; i < 8; i++) {
        v[i].x = __expf(v[i].x - m); v[i].y = __expf(v[i].y - m);
        v[i].z = __expf(v[i].z - m); v[i].w = __expf(v[i].w - m);
        s += v[i].x + v[i].y + v[i].z + v[i].w;
    }
    #pragma unroll
    for (int o = 16; o; o >>= 1) s += __shfl_xor_sync(0xffffffffu, s, o);
    float inv = 1.f / s;
    #pragma unroll
    for (int i = 0; i < 8; i++) {
        float vv[4] = {v[i].x * inv, v[i].y * inv, v[i].z * inv, v[i].w * inv};
        u32 hp[2] = {0, 0}, lp[2] = {0, 0};
        #pragma unroll
        for (int e = 0; e < 4; e++) {
            __nv_bfloat16 hb = __float2bfloat16(vv[e]);
            __nv_bfloat16 lb = __float2bfloat16(vv[e] - __bfloat162float(hb));
            hp[e >> 1] |= (u32)__bfloat16_as_ushort(hb) << ((e & 1) * 16);
            lp[e >> 1] |= (u32)__bfloat16_as_ushort(lb) << ((e & 1) * 16);
        }
        long off = ob + (long)(lane + i * 32) * 4;
        *(uint2*)(ph + off) = make_uint2(hp[0], hp[1]);
        *(uint2*)(pl + off) = make_uint2(lp[0], lp[1]);
    }
}

// ------------------------- residual + layernorm -------------------------
__global__ void ln_k(const float* __restrict__ x, const float* __restrict__ res,
                     const float* __restrict__ gamma, const float* __restrict__ beta,
                     float* __restrict__ out)
{
    long row = blockIdx.x;
    int t = threadIdx.x;
    float4 v = ((const float4*)(x + row * EE))[t];
    if (res) {
        float4 r = ((const float4*)(res + row * EE))[t];
        v.x += r.x; v.y += r.y; v.z += r.z; v.w += r.w;
    }
    float s = v.x + v.y + v.z + v.w;
    float q = v.x * v.x + v.y * v.y + v.z * v.z + v.w * v.w;
    #pragma unroll
    for (int o = 16; o; o >>= 1) {
        s += __shfl_xor_sync(0xffffffffu, s, o);
        q += __shfl_xor_sync(0xffffffffu, q, o);
    }
    __shared__ float shS[4], shQ[4];
    int w = t >> 5;
    if ((t & 31) == 0) { shS[w] = s; shQ[w] = q; }
    __syncthreads();
    s = shS[0] + shS[1] + shS[2] + shS[3];
    q = shQ[0] + shQ[1] + shQ[2] + shQ[3];
    float mean = s * (1.f / EE);
    float var = q * (1.f / EE) - mean * mean;
    float rstd = rsqrtf(var + 1e-5f);
    float4 g = ((const float4*)gamma)[t];
    float4 b = ((const float4*)beta)[t];
    float4 o;
    o.x = (v.x - mean) * rstd * g.x + b.x;
    o.y = (v.y - mean) * rstd * g.y + b.y;
    o.z = (v.z - mean) * rstd * g.z + b.z;
    o.w = (v.w - mean) * rstd * g.w + b.w;
    ((float4*)(out + row * EE))[t] = o;
}

// ------------------------- gate + mix -------------------------
__global__ void gate_mix_k(const float* __restrict__ x, const float* __restrict__ cr,
                           const float* __restrict__ gw, const float* __restrict__ gb,
                           float* __restrict__ out)
{
    long row = blockIdx.x;
    int t = threadIdx.x;
    float4 xv = ((const float4*)(x + row * EE))[t];
    float4 cv = ((const float4*)(cr + row * EE))[t];
    int k0 = t * 4;
    float l0 = 0.f, l1 = 0.f;
    float xs[4] = {xv.x, xv.y, xv.z, xv.w};
    float cs[4] = {cv.x, cv.y, cv.z, cv.w};
    #pragma unroll
    for (int e = 0; e < 4; e++) {
        int k = k0 + e;
        l0 += xs[e] * gw[k * 2 + 0] + cs[e] * gw[(EE + k) * 2 + 0];
        l1 += xs[e] * gw[k * 2 + 1] + cs[e] * gw[(EE + k) * 2 + 1];
    }
    #pragma unroll
    for (int o = 16; o; o >>= 1) {
        l0 += __shfl_xor_sync(0xffffffffu, l0, o);
        l1 += __shfl_xor_sync(0xffffffffu, l1, o);
    }
    __shared__ float sh0[4], sh1[4];
    int w = t >> 5;
    if ((t & 31) == 0) { sh0[w] = l0; sh1[w] = l1; }
    __syncthreads();
    l0 = sh0[0] + sh0[1] + sh0[2] + sh0[3] + gb[0];
    l1 = sh1[0] + sh1[1] + sh1[2] + sh1[3] + gb[1];
    float m = fmaxf(l0, l1);
    float e0 = __expf(l0 - m), e1 = __expf(l1 - m);
    float g0 = e0 / (e0 + e1), g1 = e1 / (e0 + e1);
    float4 o;
    o.x = xv.x * g0 + cv.x * g1;
    o.y = xv.y * g0 + cv.y * g1;
    o.z = xv.z * g0 + cv.z * g1;
    o.w = xv.w * g0 + cv.w * g1;
    ((float4*)(out + row * EE))[t] = o;
}

// ------------------------- host orchestration -------------------------
static float* sym(const void* s) {
    void* p = nullptr;
    cudaGetSymbolAddress(&p, s);
    return (float*)p;
}
static __nv_bfloat16* symb(const void* s) {
    void* p = nullptr;
    cudaGetSymbolAddress(&p, s);
    return (__nv_bfloat16*)p;
}

struct Weights {
    const float *qb, *kb, *vb, *ob;
    const unsigned* temp;
};

static void splitv(const float* x, __nv_bfloat16* h, __nv_bfloat16* l, long n) {
    split_k<<<(unsigned)(n / 1024), 256>>>(x, h, l, n);
}

// dense (batch-1): C[M x N] = act(A @ B^T + bias)
static void dense_tc(const __nv_bfloat16* ah, const __nv_bfloat16* al,
                     const __nv_bfloat16* bh, const __nv_bfloat16* bl,
                     const float* bias, float* C, int M, int N, int K, bool gelu) {
    dim3 grid(N / 128, M / 128, 1);
    if (gelu)
        gemm_mma<64, true><<<grid, 256>>>(ah, al, bh, bl, bias, C,
            K, K, K, N, 0, 0, 0, 0, 0, 0, 1, 1.f, nullptr);
    else
        gemm_mma<64, false><<<grid, 256>>>(ah, al, bh, bl, bias, C,
            K, K, K, N, 0, 0, 0, 0, 0, 0, 1, 1.f, nullptr);
}

static void run_attn(int i, const float* qx, const float* kx,
                     const Weights& W, float* out)
{
    __nv_bfloat16 *in1h = symb(g_in1h), *in1l = symb(g_in1l);
    __nv_bfloat16 *in2h = symb(g_in2h), *in2l = symb(g_in2l);
    __nv_bfloat16 *qh = symb(g_qh), *ql = symb(g_ql);
    __nv_bfloat16 *kh = symb(g_kh), *kl = symb(g_kl);
    __nv_bfloat16 *vth = symb(g_vth), *vtl = symb(g_vtl);
    __nv_bfloat16 *atth = symb(g_atth), *attl = symb(g_attl);
    __nv_bfloat16 *ph = symb(g_ph), *pl = symb(g_pl);
    float *q = sym(g_q), *k = sym(g_k), *v = sym(g_v);
    float *sc = sym(g_scores), *att = sym(g_att);
    long wo = (long)i * EE * EE;
    long bo = (long)i * EE;

    splitv(qx, in1h, in1l, TOKE);
    splitv(kx, in2h, in2l, TOKE);

    dense_tc(in1h, in1l, symb(g_qwth) + wo, symb(g_qwtl) + wo, W.qb + bo, q, NTOK, EE, EE, false);
    dense_tc(in2h, in2l, symb(g_kwth) + wo, symb(g_kwtl) + wo, W.kb + bo, k, NTOK, EE, EE, false);
    dense_tc(in2h, in2l, symb(g_vwth) + wo, symb(g_vwtl) + wo, W.vb + bo, v, NTOK, EE, EE, false);

    splitv(q, qh, ql, TOKE);
    splitv(k, kh, kl, TOKE);
    {   // V^T per head: [b,h,d,s]
        dim3 grid(DD / 32, SS / 32, NB);
        tsplit_k<<<grid, dim3(32, 8)>>>(v, vth, vtl, EE, SS,
            (long)SS * EE, DD, (long)NHH * DD * SS, (long)DD * SS, NHH);
    }

    // scores = alpha/temp * Q K^T (K=64)
    {
        dim3 grid(SS / 128, SS / 128, NB);
        gemm_mma<64, false><<<grid, 256>>>(qh, ql, kh, kl, nullptr, sc,
            DD, EE, EE, SS,
            (long)SS * EE, DD, (long)SS * EE, DD,
            (long)NHH * SS * SS, (long)SS * SS, NHH, 0.125f, W.temp);
    }
    softmax_split_k<<<NB * SS / 8, 256>>>(sc, ph, pl);

    // att = P @ V  (N=64, K=1024)
    {
        dim3 grid(1, SS / 128, NB);
        gemm_mma<32, false><<<grid, 256>>>(ph, pl, vth, vtl, nullptr, att,
            SS, SS, SS, EE,
            (long)NHH * SS * SS, (long)SS * SS,
            (long)NHH * DD * SS, (long)DD * SS,
            (long)SS * EE, DD, NHH, 1.f, nullptr);
    }
    splitv(att, atth, attl, TOKE);
    dense_tc(atth, attl, symb(g_owth) + wo, symb(g_owtl) + wo, W.ob + bo, out, NTOK, EE, EE, false);
}

extern "C" void kernel_launch(void* const* d_in, const int* in_sizes, int n_in,
                              void* d_out, int out_size)
{
    const float* body_feats = (const float*)d_in[0];
    const float* limb_feats = (const float*)d_in[1];
    const float* attn_qw = (const float*)d_in[2];
    const float* attn_qb = (const float*)d_in[3];
    const float* attn_kw = (const float*)d_in[4];
    const float* attn_kb = (const float*)d_in[5];
    const float* attn_vw = (const float*)d_in[6];
    const float* attn_vb = (const float*)d_in[7];
    const float* attn_ow = (const float*)d_in[8];
    const float* attn_ob = (const float*)d_in[9];
    const float* ffn_w1 = (const float*)d_in[10];
    const float* ffn_b1 = (const float*)d_in[11];
    const float* ffn_w2 = (const float*)d_in[12];
    const float* ffn_b2 = (const float*)d_in[13];
    const float* nsc = (const float*)d_in[14];
    const float* nbi = (const float*)d_in[15];
    const float* gw = (const float*)d_in[16];
    const float* gb = (const float*)d_in[17];

    Weights W;
    W.qb = attn_qb; W.kb = attn_kb; W.vb = attn_vb; W.ob = attn_ob;
    W.temp = (const unsigned*)d_in[18];

    float* out = (float*)d_out;
    float* out_body = out;
    float* out_limb = out + TOKE;

    float* tmp  = sym(g_tmp);
    float* body = sym(g_body);
    float* limb = sym(g_limb);
    float* crB  = sym(g_crossB);
    float* crL  = sym(g_crossL);
    float* mixB = sym(g_mixB);
    float* mixL = sym(g_mixL);
    float* hid  = sym(g_hid);
    float* ffn  = sym(g_ffn);
    __nv_bfloat16 *in1h = symb(g_in1h), *in1l = symb(g_in1l);
    __nv_bfloat16 *hidh = symb(g_hidh), *hidl = symb(g_hidl);

    // ---- weight transposes + splits ----
    {
        dim3 blk(32, 8);
        dim3 gE(EE / 32, EE / 32, 4);
        tsplit_k<<<gE, blk>>>(attn_qw, symb(g_qwth), symb(g_qwtl), EE, EE,
                              (long)EE * EE, 0, (long)EE * EE, 0, 1);
        tsplit_k<<<gE, blk>>>(attn_kw, symb(g_kwth), symb(g_kwtl), EE, EE,
                              (long)EE * EE, 0, (long)EE * EE, 0, 1);
        tsplit_k<<<gE, blk>>>(attn_vw, symb(g_vwth), symb(g_vwtl), EE, EE,
                              (long)EE * EE, 0, (long)EE * EE, 0, 1);
        tsplit_k<<<gE, blk>>>(attn_ow, symb(g_owth), symb(g_owtl), EE, EE,
                              (long)EE * EE, 0, (long)EE * EE, 0, 1);
        dim3 g1(4 * EE / 32, EE / 32, 2);
        tsplit_k<<<g1, blk>>>(ffn_w1, symb(g_w1th), symb(g_w1tl), 4 * EE, EE,
                              (long)EE * 4 * EE, 0, (long)EE * 4 * EE, 0, 1);
        dim3 g2(EE / 32, 4 * EE / 32, 2);
        tsplit_k<<<g2, blk>>>(ffn_w2, symb(g_w2th), symb(g_w2tl), EE, 4 * EE,
                              (long)EE * 4 * EE, 0, (long)EE * 4 * EE, 0, 1);
    }

    // ---- self attentions + norm1 ----
    run_attn(0, body_feats, body_feats, W, tmp);
    ln_k<<<NTOK, 128>>>(body_feats, tmp, nsc + 0 * EE, nbi + 0 * EE, body);

    run_attn(1, limb_feats, limb_feats, W, tmp);
    ln_k<<<NTOK, 128>>>(limb_feats, tmp, nsc + 3 * EE, nbi + 3 * EE, limb);

    // ---- cross attentions ----
    run_attn(2, body, limb, W, crB);
    run_attn(3, limb, body, W, crL);

    // ---- gates + norm2(body) on both streams (faithful to reference) ----
    gate_mix_k<<<NTOK, 128>>>(body, crB, gw, gb, mixB);
    gate_mix_k<<<NTOK, 128>>>(limb, crL, gw, gb, mixL);
    ln_k<<<NTOK, 128>>>(mixB, nullptr, nsc + 1 * EE, nbi + 1 * EE, body);
    ln_k<<<NTOK, 128>>>(mixL, nullptr, nsc + 1 * EE, nbi + 1 * EE, limb);

    // ---- FFN body ----
    splitv(body, in1h, in1l, TOKE);
    dense_tc(in1h, in1l, symb(g_w1th), symb(g_w1tl), ffn_b1, hid, NTOK, 4 * EE, EE, true);
    splitv(hid, hidh, hidl, (long)NTOK * 4 * EE);
    dense_tc(hidh, hidl, symb(g_w2th), symb(g_w2tl), ffn_b2, ffn, NTOK, EE, 4 * EE, false);
    ln_k<<<NTOK, 128>>>(body, ffn, nsc + 2 * EE, nbi + 2 * EE, out_body);

    // ---- FFN limb ----
    splitv(limb, in1h, in1l, TOKE);
    dense_tc(in1h, in1l, symb(g_w1th) + (long)4 * EE * EE, symb(g_w1tl) + (long)4 * EE * EE,
             ffn_b1 + 4 * EE, hid, NTOK, 4 * EE, EE, true);
    splitv(hid, hidh, hidl, (long)NTOK * 4 * EE);
    dense_tc(hidh, hidl, symb(g_w2th) + (long)4 * EE * EE, symb(g_w2tl) + (long)4 * EE * EE,
             ffn_b2 + EE, ffn, NTOK, EE, 4 * EE, false);
    ln_k<<<NTOK, 128>>>(limb, ffn, nsc + 5 * EE, nbi + 5 * EE, out_limb);
}

// round 7
// speedup vs baseline: 2.8314x; 1.2055x over previous
#include <cuda_runtime.h>
#include <cuda_bf16.h>
#include <math.h>

typedef unsigned int u32;
typedef unsigned long long u64;

#define BB 4
#define SS 1024
#define EE 512
#define NHH 8
#define DD 64
#define NTOK (BB*SS)          // 4096
#define TOKE ((long)NTOK*EE)  // 2,097,152
#define NB (BB*NHH)           // 32

// ------------------------- fp32 scratch -------------------------
__device__ float g_v[NTOK*EE];
__device__ float g_scores[(long)NB*SS*SS];
__device__ float g_tmp[NTOK*EE];
__device__ float g_body[NTOK*EE];
__device__ float g_limb[NTOK*EE];
__device__ float g_crossB[NTOK*EE];
__device__ float g_crossL[NTOK*EE];
__device__ float g_mixB[NTOK*EE];
__device__ float g_mixL[NTOK*EE];
__device__ float g_ffn[NTOK*EE];

// ------------------------- bf16 split scratch (16B aligned) -------------------------
__device__ __align__(16) __nv_bfloat16 g_bfh[NTOK*EE], g_bfl[NTOK*EE];   // body_feats split
__device__ __align__(16) __nv_bfloat16 g_lfh[NTOK*EE], g_lfl[NTOK*EE];   // limb_feats split
__device__ __align__(16) __nv_bfloat16 g_bodyh[NTOK*EE], g_bodyl[NTOK*EE];
__device__ __align__(16) __nv_bfloat16 g_limbh[NTOK*EE], g_limbl[NTOK*EE];
__device__ __align__(16) __nv_bfloat16 g_qh[NTOK*EE],  g_ql[NTOK*EE];
__device__ __align__(16) __nv_bfloat16 g_kh[NTOK*EE],  g_kl[NTOK*EE];
__device__ __align__(16) __nv_bfloat16 g_vth[NTOK*EE], g_vtl[NTOK*EE];   // V^T per head
__device__ __align__(16) __nv_bfloat16 g_atth[NTOK*EE], g_attl[NTOK*EE];
__device__ __align__(16) __nv_bfloat16 g_ph[(long)NB*SS*SS], g_pl[(long)NB*SS*SS];
__device__ __align__(16) __nv_bfloat16 g_hidh[(long)NTOK*4*EE], g_hidl[(long)NTOK*4*EE];
__device__ __align__(16) __nv_bfloat16 g_qwth[4*EE*EE], g_qwtl[4*EE*EE];
__device__ __align__(16) __nv_bfloat16 g_kwth[4*EE*EE], g_kwtl[4*EE*EE];
__device__ __align__(16) __nv_bfloat16 g_vwth[4*EE*EE], g_vwtl[4*EE*EE];
__device__ __align__(16) __nv_bfloat16 g_owth[4*EE*EE], g_owtl[4*EE*EE];
__device__ __align__(16) __nv_bfloat16 g_w1th[(long)2*EE*4*EE], g_w1tl[(long)2*EE*4*EE];
__device__ __align__(16) __nv_bfloat16 g_w2th[(long)2*EE*4*EE], g_w2tl[(long)2*EE*4*EE];

// ------------------------- asm helpers -------------------------
__device__ __forceinline__ u32 s2u(const void* p) {
    u32 a;
    asm("{ .reg .u64 t; cvta.to.shared.u64 t, %1; cvt.u32.u64 %0, t; }" : "=r"(a) : "l"(p));
    return a;
}
__device__ __forceinline__ void cpa16(u32 saddr, const void* g) {
    asm volatile("cp.async.cg.shared.global [%0], [%1], 16;" :: "r"(saddr), "l"(g));
}
__device__ __forceinline__ void cpcommit() { asm volatile("cp.async.commit_group;"); }
__device__ __forceinline__ void cpwait1()  { asm volatile("cp.async.wait_group 1;"); }
__device__ __forceinline__ void cpwait0()  { asm volatile("cp.async.wait_group 0;"); }

__device__ __forceinline__ void ldsm_x4(u32 r[4], u32 addr) {
    asm volatile("ldmatrix.sync.aligned.m8n8.x4.shared.b16 {%0,%1,%2,%3}, [%4];"
                 : "=r"(r[0]), "=r"(r[1]), "=r"(r[2]), "=r"(r[3]) : "r"(addr));
}
__device__ __forceinline__ void ldsm_x2(u32 r[2], u32 addr) {
    asm volatile("ldmatrix.sync.aligned.m8n8.x2.shared.b16 {%0,%1}, [%2];"
                 : "=r"(r[0]), "=r"(r[1]) : "r"(addr));
}
__device__ __forceinline__ void mma16816(float c[4], const u32 a[4], const u32 b[2]) {
    asm volatile(
        "mma.sync.aligned.m16n8k16.row.col.f32.bf16.bf16.f32 "
        "{%0,%1,%2,%3}, {%4,%5,%6,%7}, {%8,%9}, {%0,%1,%2,%3};"
        : "+f"(c[0]), "+f"(c[1]), "+f"(c[2]), "+f"(c[3])
        : "r"(a[0]), "r"(a[1]), "r"(a[2]), "r"(a[3]), "r"(b[0]), "r"(b[1]));
}

// ------------------------- bf16-split tensor-core GEMM, cp.async pipelined -----
// C[i,j] = act(alpha * sum_l A[i,l]*B[j,l] + bias[j])   i.e. D = A @ B^T
// OMODE: 0 = write fp32 C; 2 = write bf16 hi/lo (Ch, Cl) only.
// Block tile 128 x BN (BN=2*WN), BK=32, 2-stage cp.async double buffer.
// 256 threads = 8 warps (4 m x 2 n), warp tile 32 x WN.
template<int WN, int OMODE, bool GELU>
__global__ void __launch_bounds__(256) gemm_mma(
    const __nv_bfloat16* __restrict__ Ah, const __nv_bfloat16* __restrict__ Al,
    const __nv_bfloat16* __restrict__ Bh, const __nv_bfloat16* __restrict__ Bl,
    const float* __restrict__ bias, float* __restrict__ C,
    __nv_bfloat16* __restrict__ Ch, __nv_bfloat16* __restrict__ Cl,
    int K, int lda, int ldb, int ldc,
    long aB, long aH, long bB, long bH, long cB, long cH, int nh,
    float alpha, const unsigned* __restrict__ tptr)
{
    constexpr int BN = 2 * WN;
    constexpr int STR = 40;                    // padded stride (elems), 80B (16B mult.)
    constexpr int ASZ = 128 * STR;             // elems per A tile
    constexpr int BSZ = BN * STR;
    constexpr int STAGE = 2 * ASZ + 2 * BSZ;   // elems per stage

    extern __shared__ __align__(16) __nv_bfloat16 sm[];

    int z = blockIdx.z;
    int bb = z / nh, hh = z - bb * nh;
    Ah += bb * aB + hh * aH;  Al += bb * aB + hh * aH;
    Bh += bb * bB + hh * bH;  Bl += bb * bB + hh * bH;
    long coff = bb * cB + hh * cH;

    int i0 = blockIdx.y * 128;
    int j0 = blockIdx.x * BN;
    int tid = threadIdx.x;
    int lane = tid & 31, wid = tid >> 5;
    int wm = wid & 3, wn = wid >> 2;

    float acc[2][WN / 8][4] = {};

    const int nch = K / 32;

    // ---- stage loader ----
    auto load_stage = [&](int c, int s) {
        long kc = (long)c * 32;
        u32 base = s2u(sm + s * STAGE);
        #pragma unroll
        for (int t = 0; t < 2; t++) {
            int idx = tid + t * 256;
            int r = idx >> 2, sg = idx & 3;
            long go = (long)(i0 + r) * lda + kc + sg * 8;
            u32 so = (u32)(r * STR + sg * 8) * 2;
            cpa16(base + so, Ah + go);
            cpa16(base + ASZ * 2 + so, Al + go);
        }
        #pragma unroll
        for (int t = 0; t < BN / 64; t++) {
            int idx = tid + t * 256;
            int r = idx >> 2, sg = idx & 3;
            long go = (long)(j0 + r) * ldb + kc + sg * 8;
            u32 so = (u32)(r * STR + sg * 8) * 2;
            cpa16(base + 4 * ASZ + so, Bh + go);
            cpa16(base + 4 * ASZ + 2 * BSZ + so, Bl + go);
        }
    };

    load_stage(0, 0);
    cpcommit();

    for (int c = 0; c < nch; c++) {
        if (c + 1 < nch) {
            load_stage(c + 1, (c + 1) & 1);
            cpcommit();
            cpwait1();
        } else {
            cpwait0();
        }
        __syncthreads();

        const __nv_bfloat16* sAh = sm + (c & 1) * STAGE;
        const __nv_bfloat16* sAl = sAh + ASZ;
        const __nv_bfloat16* sBh = sAl + ASZ;
        const __nv_bfloat16* sBl = sBh + BSZ;

        #pragma unroll
        for (int ks = 0; ks < 2; ks++) {
            u32 afh[2][4], afl[2][4];
            #pragma unroll
            for (int mt = 0; mt < 2; mt++) {
                int row = wm * 32 + mt * 16 + (lane & 15);
                int col = ks * 16 + (lane >> 4) * 8;
                ldsm_x4(afh[mt], s2u(&sAh[row * STR + col]));
                ldsm_x4(afl[mt], s2u(&sAl[row * STR + col]));
            }
            #pragma unroll
            for (int nt = 0; nt < WN / 8; nt++) {
                int brow = wn * WN + nt * 8 + (lane & 7);
                int bcol = ks * 16 + ((lane >> 3) & 1) * 8;
                u32 bh[2], bl[2];
                ldsm_x2(bh, s2u(&sBh[brow * STR + bcol]));
                ldsm_x2(bl, s2u(&sBl[brow * STR + bcol]));
                #pragma unroll
                for (int mt = 0; mt < 2; mt++) {
                    mma16816(acc[mt][nt], afh[mt], bh);
                    mma16816(acc[mt][nt], afh[mt], bl);
                    mma16816(acc[mt][nt], afl[mt], bh);
                }
            }
        }
        __syncthreads();
    }

    float scl = alpha;
    if (tptr) {
        unsigned u = *tptr;
        float f = __uint_as_float(u);
        float temp = (f > 1e-6f && f < 1e6f) ? f : (float)(int)u;
        scl /= temp;
    }

    // ---- epilogue ----
    int grp = lane >> 2, qd = lane & 3;
    #pragma unroll
    for (int mt = 0; mt < 2; mt++) {
        #pragma unroll
        for (int nt = 0; nt < WN / 8; nt++) {
            int n = j0 + wn * WN + nt * 8 + qd * 2;
            float b0 = 0.f, b1 = 0.f;
            if (bias) { b0 = bias[n]; b1 = bias[n + 1]; }
            #pragma unroll
            for (int rh = 0; rh < 2; rh++) {
                int m = i0 + wm * 32 + mt * 16 + grp + rh * 8;
                float x = acc[mt][nt][rh * 2 + 0] * scl + b0;
                float y = acc[mt][nt][rh * 2 + 1] * scl + b1;
                if (GELU) {
                    x = 0.5f * x * (1.f + erff(x * 0.70710678118654752f));
                    y = 0.5f * y * (1.f + erff(y * 0.70710678118654752f));
                }
                long off = coff + (long)m * ldc + n;
                if (OMODE == 0) {
                    *(float2*)&C[off] = make_float2(x, y);
                } else {
                    __nv_bfloat16 hx = __float2bfloat16(x);
                    __nv_bfloat16 hy = __float2bfloat16(y);
                    __nv_bfloat16 lx = __float2bfloat16(x - __bfloat162float(hx));
                    __nv_bfloat16 ly = __float2bfloat16(y - __bfloat162float(hy));
                    *(ushort2*)&Ch[off] = make_ushort2(__bfloat16_as_ushort(hx), __bfloat16_as_ushort(hy));
                    *(ushort2*)&Cl[off] = make_ushort2(__bfloat16_as_ushort(lx), __bfloat16_as_ushort(ly));
                }
            }
        }
    }
}

// ------------------------- elementwise hi/lo split -------------------------
__global__ void split_k(const float* __restrict__ x, __nv_bfloat16* __restrict__ h,
                        __nv_bfloat16* __restrict__ l, long n)
{
    long i = ((long)blockIdx.x * blockDim.x + threadIdx.x) * 4;
    if (i >= n) return;
    float4 v = *(const float4*)(x + i);
    float vv[4] = {v.x, v.y, v.z, v.w};
    u32 hp[2] = {0, 0}, lp[2] = {0, 0};
    #pragma unroll
    for (int e = 0; e < 4; e++) {
        __nv_bfloat16 hb = __float2bfloat16(vv[e]);
        __nv_bfloat16 lb = __float2bfloat16(vv[e] - __bfloat162float(hb));
        hp[e >> 1] |= (u32)__bfloat16_as_ushort(hb) << ((e & 1) * 16);
        lp[e >> 1] |= (u32)__bfloat16_as_ushort(lb) << ((e & 1) * 16);
    }
    *(uint2*)(h + i) = make_uint2(hp[0], hp[1]);
    *(uint2*)(l + i) = make_uint2(lp[0], lp[1]);
}

// ------------------------- transpose + split -------------------------
__global__ void tsplit_k(const float* __restrict__ src, __nv_bfloat16* __restrict__ h,
                         __nv_bfloat16* __restrict__ l,
                         int lds, int ldd, long sB, long sH, long dB, long dH, int nh)
{
    __shared__ float sm[32][33];
    int z = blockIdx.z;
    int bb = z / nh, hh = z - bb * nh;
    src += bb * sB + hh * sH;
    h   += bb * dB + hh * dH;
    l   += bb * dB + hh * dH;
    int r0 = blockIdx.y * 32, c0 = blockIdx.x * 32;
    int tx = threadIdx.x, ty = threadIdx.y;
    #pragma unroll
    for (int i = 0; i < 4; i++)
        sm[ty + 8 * i][tx] = src[(long)(r0 + ty + 8 * i) * lds + c0 + tx];
    __syncthreads();
    #pragma unroll
    for (int i = 0; i < 4; i++) {
        int n = c0 + ty + 8 * i, k = r0 + tx;
        float v = sm[tx][ty + 8 * i];
        __nv_bfloat16 hv = __float2bfloat16(v);
        __nv_bfloat16 lv = __float2bfloat16(v - __bfloat162float(hv));
        h[(long)n * ldd + k] = hv;
        l[(long)n * ldd + k] = lv;
    }
}

// ------------------------- softmax (rows of 1024) -> bf16 hi/lo -------------------------
__global__ void softmax_split_k(const float* __restrict__ sc,
                                __nv_bfloat16* __restrict__ ph, __nv_bfloat16* __restrict__ pl)
{
    long gwarp = ((long)blockIdx.x * blockDim.x + threadIdx.x) >> 5;
    int lane = threadIdx.x & 31;
    const float* row = sc + gwarp * SS;
    long ob = gwarp * SS;

    float4 v[8];
    float m = -1e30f;
    #pragma unroll
    for (int i = 0; i < 8; i++) {
        v[i] = ((const float4*)row)[lane + i * 32];
        m = fmaxf(m, fmaxf(fmaxf(v[i].x, v[i].y), fmaxf(v[i].z, v[i].w)));
    }
    #pragma unroll
    for (int o = 16; o; o >>= 1) m = fmaxf(m, __shfl_xor_sync(0xffffffffu, m, o));
    float s = 0.f;
    #pragma unroll
    for (int i = 0; i < 8; i++) {
        v[i].x = __expf(v[i].x - m); v[i].y = __expf(v[i].y - m);
        v[i].z = __expf(v[i].z - m); v[i].w = __expf(v[i].w - m);
        s += v[i].x + v[i].y + v[i].z + v[i].w;
    }
    #pragma unroll
    for (int o = 16; o; o >>= 1) s += __shfl_xor_sync(0xffffffffu, s, o);
    float inv = 1.f / s;
    #pragma unroll
    for (int i = 0; i < 8; i++) {
        float vv[4] = {v[i].x * inv, v[i].y * inv, v[i].z * inv, v[i].w * inv};
        u32 hp[2] = {0, 0}, lp[2] = {0, 0};
        #pragma unroll
        for (int e = 0; e < 4; e++) {
            __nv_bfloat16 hb = __float2bfloat16(vv[e]);
            __nv_bfloat16 lb = __float2bfloat16(vv[e] - __bfloat162float(hb));
            hp[e >> 1] |= (u32)__bfloat16_as_ushort(hb) << ((e & 1) * 16);
            lp[e >> 1] |= (u32)__bfloat16_as_ushort(lb) << ((e & 1) * 16);
        }
        long off = ob + (long)(lane + i * 32) * 4;
        *(uint2*)(ph + off) = make_uint2(hp[0], hp[1]);
        *(uint2*)(pl + off) = make_uint2(lp[0], lp[1]);
    }
}

// ------------------------- residual + layernorm (+ optional split out) -------------------------
__global__ void ln_k(const float* __restrict__ x, const float* __restrict__ res,
                     const float* __restrict__ gamma, const float* __restrict__ beta,
                     float* __restrict__ out,
                     __nv_bfloat16* __restrict__ oh = nullptr,
                     __nv_bfloat16* __restrict__ ol = nullptr)
{
    long row = blockIdx.x;
    int t = threadIdx.x;
    float4 v = ((const float4*)(x + row * EE))[t];
    if (res) {
        float4 r = ((const float4*)(res + row * EE))[t];
        v.x += r.x; v.y += r.y; v.z += r.z; v.w += r.w;
    }
    float s = v.x + v.y + v.z + v.w;
    float q = v.x * v.x + v.y * v.y + v.z * v.z + v.w * v.w;
    #pragma unroll
    for (int o = 16; o; o >>= 1) {
        s += __shfl_xor_sync(0xffffffffu, s, o);
        q += __shfl_xor_sync(0xffffffffu, q, o);
    }
    __shared__ float shS[4], shQ[4];
    int w = t >> 5;
    if ((t & 31) == 0) { shS[w] = s; shQ[w] = q; }
    __syncthreads();
    s = shS[0] + shS[1] + shS[2] + shS[3];
    q = shQ[0] + shQ[1] + shQ[2] + shQ[3];
    float mean = s * (1.f / EE);
    float var = q * (1.f / EE) - mean * mean;
    float rstd = rsqrtf(var + 1e-5f);
    float4 g = ((const float4*)gamma)[t];
    float4 b = ((const float4*)beta)[t];
    float4 o;
    o.x = (v.x - mean) * rstd * g.x + b.x;
    o.y = (v.y - mean) * rstd * g.y + b.y;
    o.z = (v.z - mean) * rstd * g.z + b.z;
    o.w = (v.w - mean) * rstd * g.w + b.w;
    ((float4*)(out + row * EE))[t] = o;
    if (oh) {
        float vv[4] = {o.x, o.y, o.z, o.w};
        u32 hp[2] = {0, 0}, lp[2] = {0, 0};
        #pragma unroll
        for (int e = 0; e < 4; e++) {
            __nv_bfloat16 hb = __float2bfloat16(vv[e]);
            __nv_bfloat16 lb = __float2bfloat16(vv[e] - __bfloat162float(hb));
            hp[e >> 1] |= (u32)__bfloat16_as_ushort(hb) << ((e & 1) * 16);
            lp[e >> 1] |= (u32)__bfloat16_as_ushort(lb) << ((e & 1) * 16);
        }
        *(uint2*)(oh + row * EE + t * 4) = make_uint2(hp[0], hp[1]);
        *(uint2*)(ol + row * EE + t * 4) = make_uint2(lp[0], lp[1]);
    }
}

// ------------------------- gate + mix -------------------------
__global__ void gate_mix_k(const float* __restrict__ x, const float* __restrict__ cr,
                           const float* __restrict__ gw, const float* __restrict__ gb,
                           float* __restrict__ out)
{
    long row = blockIdx.x;
    int t = threadIdx.x;
    float4 xv = ((const float4*)(x + row * EE))[t];
    float4 cv = ((const float4*)(cr + row * EE))[t];
    int k0 = t * 4;
    float l0 = 0.f, l1 = 0.f;
    float xs[4] = {xv.x, xv.y, xv.z, xv.w};
    float cs[4] = {cv.x, cv.y, cv.z, cv.w};
    #pragma unroll
    for (int e = 0; e < 4; e++) {
        int k = k0 + e;
        l0 += xs[e] * gw[k * 2 + 0] + cs[e] * gw[(EE + k) * 2 + 0];
        l1 += xs[e] * gw[k * 2 + 1] + cs[e] * gw[(EE + k) * 2 + 1];
    }
    #pragma unroll
    for (int o = 16; o; o >>= 1) {
        l0 += __shfl_xor_sync(0xffffffffu, l0, o);
        l1 += __shfl_xor_sync(0xffffffffu, l1, o);
    }
    __shared__ float sh0[4], sh1[4];
    int w = t >> 5;
    if ((t & 31) == 0) { sh0[w] = l0; sh1[w] = l1; }
    __syncthreads();
    l0 = sh0[0] + sh0[1] + sh0[2] + sh0[3] + gb[0];
    l1 = sh1[0] + sh1[1] + sh1[2] + sh1[3] + gb[1];
    float m = fmaxf(l0, l1);
    float e0 = __expf(l0 - m), e1 = __expf(l1 - m);
    float g0 = e0 / (e0 + e1), g1 = e1 / (e0 + e1);
    float4 o;
    o.x = xv.x * g0 + cv.x * g1;
    o.y = xv.y * g0 + cv.y * g1;
    o.z = xv.z * g0 + cv.z * g1;
    o.w = xv.w * g0 + cv.w * g1;
    ((float4*)(out + row * EE))[t] = o;
}

// ------------------------- host orchestration -------------------------
typedef __nv_bfloat16 bf;
static float* sym(const void* s) { void* p = nullptr; cudaGetSymbolAddress(&p, s); return (float*)p; }
static bf* symb(const void* s)   { void* p = nullptr; cudaGetSymbolAddress(&p, s); return (bf*)p; }

#define SMEM64 ((2 * 128 * 40 + 2 * 128 * 40) * 2 * 2)   // 81920 B
#define SMEM32 ((2 * 128 * 40 + 2 * 64 * 40) * 2 * 2)    // 61440 B

struct Weights {
    const float *qb, *kb, *vb, *ob;
    const unsigned* temp;
};

// C fp32 = A @ B^T + bias
static void gemm_f32(const bf* ah, const bf* al, const bf* bh, const bf* bl,
                     const float* bias, float* C, int M, int N, int K) {
    dim3 grid(N / 128, M / 128, 1);
    gemm_mma<64, 0, false><<<grid, 256, SMEM64>>>(ah, al, bh, bl, bias, C, nullptr, nullptr,
        K, K, K, N, 0, 0, 0, 0, 0, 0, 1, 1.f, nullptr);
}
// C hi/lo = A @ B^T + bias
static void gemm_sp(const bf* ah, const bf* al, const bf* bh, const bf* bl,
                    const float* bias, bf* Ch, bf* Cl, int M, int N, int K, bool gelu) {
    dim3 grid(N / 128, M / 128, 1);
    if (gelu)
        gemm_mma<64, 2, true><<<grid, 256, SMEM64>>>(ah, al, bh, bl, bias, nullptr, Ch, Cl,
            K, K, K, N, 0, 0, 0, 0, 0, 0, 1, 1.f, nullptr);
    else
        gemm_mma<64, 2, false><<<grid, 256, SMEM64>>>(ah, al, bh, bl, bias, nullptr, Ch, Cl,
            K, K, K, N, 0, 0, 0, 0, 0, 0, 1, 1.f, nullptr);
}

static void run_attn(int i, const bf* qih, const bf* qil, const bf* kih, const bf* kil,
                     const Weights& W, float* out)
{
    bf *qh = symb(g_qh), *ql = symb(g_ql);
    bf *kh = symb(g_kh), *kl = symb(g_kl);
    bf *vth = symb(g_vth), *vtl = symb(g_vtl);
    bf *atth = symb(g_atth), *attl = symb(g_attl);
    bf *ph = symb(g_ph), *pl = symb(g_pl);
    float *v = sym(g_v), *sc = sym(g_scores);
    long wo = (long)i * EE * EE;
    long bo = (long)i * EE;

    // projections: Q,K -> split out; V -> fp32 (for transpose)
    gemm_sp(qih, qil, symb(g_qwth) + wo, symb(g_qwtl) + wo, W.qb + bo, qh, ql, NTOK, EE, EE, false);
    gemm_sp(kih, kil, symb(g_kwth) + wo, symb(g_kwtl) + wo, W.kb + bo, kh, kl, NTOK, EE, EE, false);
    gemm_f32(kih, kil, symb(g_vwth) + wo, symb(g_vwtl) + wo, W.vb + bo, v, NTOK, EE, EE);

    {   // V^T per head: [b,h,d,s]
        dim3 grid(DD / 32, SS / 32, NB);
        tsplit_k<<<grid, dim3(32, 8)>>>(v, vth, vtl, EE, SS,
            (long)SS * EE, DD, (long)NHH * DD * SS, (long)DD * SS, NHH);
    }

    // scores = alpha/temp * Q K^T (K=64)
    {
        dim3 grid(SS / 128, SS / 128, NB);
        gemm_mma<64, 0, false><<<grid, 256, SMEM64>>>(qh, ql, kh, kl, nullptr, sc, nullptr, nullptr,
            DD, EE, EE, SS,
            (long)SS * EE, DD, (long)SS * EE, DD,
            (long)NHH * SS * SS, (long)SS * SS, NHH, 0.125f, W.temp);
    }
    softmax_split_k<<<NB * SS / 8, 256>>>(sc, ph, pl);

    // att = P @ V  (N=64, K=1024) -> split out
    {
        dim3 grid(1, SS / 128, NB);
        gemm_mma<32, 2, false><<<grid, 256, SMEM32>>>(ph, pl, vth, vtl, nullptr, nullptr, atth, attl,
            SS, SS, SS, EE,
            (long)NHH * SS * SS, (long)SS * SS,
            (long)NHH * DD * SS, (long)DD * SS,
            (long)SS * EE, DD, NHH, 1.f, nullptr);
    }
    gemm_f32(atth, attl, symb(g_owth) + wo, symb(g_owtl) + wo, W.ob + bo, out, NTOK, EE, EE);
}

extern "C" void kernel_launch(void* const* d_in, const int* in_sizes, int n_in,
                              void* d_out, int out_size)
{
    const float* body_feats = (const float*)d_in[0];
    const float* limb_feats = (const float*)d_in[1];
    const float* attn_qw = (const float*)d_in[2];
    const float* attn_qb = (const float*)d_in[3];
    const float* attn_kw = (const float*)d_in[4];
    const float* attn_kb = (const float*)d_in[5];
    const float* attn_vw = (const float*)d_in[6];
    const float* attn_vb = (const float*)d_in[7];
    const float* attn_ow = (const float*)d_in[8];
    const float* attn_ob = (const float*)d_in[9];
    const float* ffn_w1 = (const float*)d_in[10];
    const float* ffn_b1 = (const float*)d_in[11];
    const float* ffn_w2 = (const float*)d_in[12];
    const float* ffn_b2 = (const float*)d_in[13];
    const float* nsc = (const float*)d_in[14];
    const float* nbi = (const float*)d_in[15];
    const float* gw = (const float*)d_in[16];
    const float* gb = (const float*)d_in[17];

    Weights W;
    W.qb = attn_qb; W.kb = attn_kb; W.vb = attn_vb; W.ob = attn_ob;
    W.temp = (const unsigned*)d_in[18];

    // raise dynamic smem limits (idempotent)
    cudaFuncSetAttribute(gemm_mma<64, 0, false>, cudaFuncAttributeMaxDynamicSharedMemorySize, SMEM64);
    cudaFuncSetAttribute(gemm_mma<64, 2, false>, cudaFuncAttributeMaxDynamicSharedMemorySize, SMEM64);
    cudaFuncSetAttribute(gemm_mma<64, 2, true>,  cudaFuncAttributeMaxDynamicSharedMemorySize, SMEM64);
    cudaFuncSetAttribute(gemm_mma<32, 2, false>, cudaFuncAttributeMaxDynamicSharedMemorySize, SMEM32);

    float* out = (float*)d_out;
    float* out_body = out;
    float* out_limb = out + TOKE;

    float* tmp  = sym(g_tmp);
    float* body = sym(g_body);
    float* limb = sym(g_limb);
    float* crB  = sym(g_crossB);
    float* crL  = sym(g_crossL);
    float* mixB = sym(g_mixB);
    float* mixL = sym(g_mixL);
    float* ffn  = sym(g_ffn);
    bf *bfh = symb(g_bfh), *bfl = symb(g_bfl);
    bf *lfh = symb(g_lfh), *lfl = symb(g_lfl);
    bf *bodyh = symb(g_bodyh), *bodyl = symb(g_bodyl);
    bf *limbh = symb(g_limbh), *limbl = symb(g_limbl);
    bf *hidh = symb(g_hidh), *hidl = symb(g_hidl);

    // ---- weight transposes + splits ----
    {
        dim3 blk(32, 8);
        dim3 gE(EE / 32, EE / 32, 4);
        tsplit_k<<<gE, blk>>>(attn_qw, symb(g_qwth), symb(g_qwtl), EE, EE,
                              (long)EE * EE, 0, (long)EE * EE, 0, 1);
        tsplit_k<<<gE, blk>>>(attn_kw, symb(g_kwth), symb(g_kwtl), EE, EE,
                              (long)EE * EE, 0, (long)EE * EE, 0, 1);
        tsplit_k<<<gE, blk>>>(attn_vw, symb(g_vwth), symb(g_vwtl), EE, EE,
                              (long)EE * EE, 0, (long)EE * EE, 0, 1);
        tsplit_k<<<gE, blk>>>(attn_ow, symb(g_owth), symb(g_owtl), EE, EE,
                              (long)EE * EE, 0, (long)EE * EE, 0, 1);
        dim3 g1(4 * EE / 32, EE / 32, 2);
        tsplit_k<<<g1, blk>>>(ffn_w1, symb(g_w1th), symb(g_w1tl), 4 * EE, EE,
                              (long)EE * 4 * EE, 0, (long)EE * 4 * EE, 0, 1);
        dim3 g2(EE / 32, 4 * EE / 32, 2);
        tsplit_k<<<g2, blk>>>(ffn_w2, symb(g_w2th), symb(g_w2tl), EE, 4 * EE,
                              (long)EE * 4 * EE, 0, (long)EE * 4 * EE, 0, 1);
    }

    // ---- input splits (once) ----
    split_k<<<(unsigned)(TOKE / 1024), 256>>>(body_feats, bfh, bfl, TOKE);
    split_k<<<(unsigned)(TOKE / 1024), 256>>>(limb_feats, lfh, lfl, TOKE);

    // ---- self attentions + norm1 (split out for cross attn) ----
    run_attn(0, bfh, bfl, bfh, bfl, W, tmp);
    ln_k<<<NTOK, 128>>>(body_feats, tmp, nsc + 0 * EE, nbi + 0 * EE, body, bodyh, bodyl);

    run_attn(1, lfh, lfl, lfh, lfl, W, tmp);
    ln_k<<<NTOK, 128>>>(limb_feats, tmp, nsc + 3 * EE, nbi + 3 * EE, limb, limbh, limbl);

    // ---- cross attentions ----
    run_attn(2, bodyh, bodyl, limbh, limbl, W, crB);
    run_attn(3, limbh, limbl, bodyh, bodyl, W, crL);

    // ---- gates + norm2(body) on both streams (faithful to reference) ----
    gate_mix_k<<<NTOK, 128>>>(body, crB, gw, gb, mixB);
    gate_mix_k<<<NTOK, 128>>>(limb, crL, gw, gb, mixL);
    ln_k<<<NTOK, 128>>>(mixB, nullptr, nsc + 1 * EE, nbi + 1 * EE, body, bodyh, bodyl);
    ln_k<<<NTOK, 128>>>(mixL, nullptr, nsc + 1 * EE, nbi + 1 * EE, limb, limbh, limbl);

    // ---- FFN body ----
    gemm_sp(bodyh, bodyl, symb(g_w1th), symb(g_w1tl), ffn_b1, hidh, hidl, NTOK, 4 * EE, EE, true);
    gemm_f32(hidh, hidl, symb(g_w2th), symb(g_w2tl), ffn_b2, ffn, NTOK, EE, 4 * EE);
    ln_k<<<NTOK, 128>>>(body, ffn, nsc + 2 * EE, nbi + 2 * EE, out_body, nullptr, nullptr);

    // ---- FFN limb ----
    gemm_sp(limbh, limbl, symb(g_w1th) + (long)4 * EE * EE, symb(g_w1tl) + (long)4 * EE * EE,
            ffn_b1 + 4 * EE, hidh, hidl, NTOK, 4 * EE, EE, true);
    gemm_f32(hidh, hidl, symb(g_w2th) + (long)4 * EE * EE, symb(g_w2tl) + (long)4 * EE * EE,
             ffn_b2 + EE, ffn, NTOK, EE, 4 * EE);
    ln_k<<<NTOK, 128>>>(limb, ffn, nsc + 5 * EE, nbi + 5 * EE, out_limb, nullptr, nullptr);
}

// round 9
// speedup vs baseline: 2.8951x; 1.0225x over previous
#include <cuda_runtime.h>
#include <cuda_bf16.h>
#include <math.h>

typedef unsigned int u32;
typedef unsigned long long u64;
typedef __nv_bfloat16 bf;

#define BB 4
#define SS 1024
#define EE 512
#define NHH 8
#define DD 64
#define NTOK (BB*SS)          // 4096
#define TOKE ((long)NTOK*EE)  // 2,097,152
#define NB (BB*NHH)           // 32

// ------------------------- fp32 scratch -------------------------
__device__ float g_v[NTOK*EE];
__device__ float g_tmp[NTOK*EE];
__device__ float g_body[NTOK*EE];
__device__ float g_limb[NTOK*EE];
__device__ float g_crossB[NTOK*EE];
__device__ float g_crossL[NTOK*EE];
__device__ float g_mixB[NTOK*EE];
__device__ float g_mixL[NTOK*EE];
__device__ float g_ffn[NTOK*EE];

// ------------------------- bf16 split scratch (16B aligned) -------------------------
__device__ __align__(16) bf g_bfh[NTOK*EE], g_bfl[NTOK*EE];
__device__ __align__(16) bf g_lfh[NTOK*EE], g_lfl[NTOK*EE];
__device__ __align__(16) bf g_bodyh[NTOK*EE], g_bodyl[NTOK*EE];
__device__ __align__(16) bf g_limbh[NTOK*EE], g_limbl[NTOK*EE];
__device__ __align__(16) bf g_qh[NTOK*EE],  g_ql[NTOK*EE];
__device__ __align__(16) bf g_kh[NTOK*EE],  g_kl[NTOK*EE];
__device__ __align__(16) bf g_vth[NTOK*EE], g_vtl[NTOK*EE];   // V^T per head [32][64][1024]
__device__ __align__(16) bf g_atth[NTOK*EE], g_attl[NTOK*EE];
__device__ __align__(16) bf g_hidh[(long)NTOK*4*EE], g_hidl[(long)NTOK*4*EE];
__device__ __align__(16) bf g_qwth[4*EE*EE], g_qwtl[4*EE*EE];
__device__ __align__(16) bf g_kwth[4*EE*EE], g_kwtl[4*EE*EE];
__device__ __align__(16) bf g_vwth[4*EE*EE], g_vwtl[4*EE*EE];
__device__ __align__(16) bf g_owth[4*EE*EE], g_owtl[4*EE*EE];
__device__ __align__(16) bf g_w1th[(long)2*EE*4*EE], g_w1tl[(long)2*EE*4*EE];
__device__ __align__(16) bf g_w2th[(long)2*EE*4*EE], g_w2tl[(long)2*EE*4*EE];

// ------------------------- asm helpers -------------------------
__device__ __forceinline__ u32 s2u(const void* p) {
    u32 a;
    asm("{ .reg .u64 t; cvta.to.shared.u64 t, %1; cvt.u32.u64 %0, t; }" : "=r"(a) : "l"(p));
    return a;
}
__device__ __forceinline__ void cpa16(u32 saddr, const void* g) {
    asm volatile("cp.async.cg.shared.global [%0], [%1], 16;" :: "r"(saddr), "l"(g));
}
__device__ __forceinline__ void cpcommit() { asm volatile("cp.async.commit_group;"); }
__device__ __forceinline__ void cpwait1()  { asm volatile("cp.async.wait_group 1;"); }
__device__ __forceinline__ void cpwait0()  { asm volatile("cp.async.wait_group 0;"); }

__device__ __forceinline__ void ldsm_x4(u32 r[4], u32 addr) {
    asm volatile("ldmatrix.sync.aligned.m8n8.x4.shared.b16 {%0,%1,%2,%3}, [%4];"
                 : "=r"(r[0]), "=r"(r[1]), "=r"(r[2]), "=r"(r[3]) : "r"(addr));
}
__device__ __forceinline__ void ldsm_x2(u32 r[2], u32 addr) {
    asm volatile("ldmatrix.sync.aligned.m8n8.x2.shared.b16 {%0,%1}, [%2];"
                 : "=r"(r[0]), "=r"(r[1]) : "r"(addr));
}
__device__ __forceinline__ void mma16816(float c[4], const u32 a[4], const u32 b[2]) {
    asm volatile(
        "mma.sync.aligned.m16n8k16.row.col.f32.bf16.bf16.f32 "
        "{%0,%1,%2,%3}, {%4,%5,%6,%7}, {%8,%9}, {%0,%1,%2,%3};"
        : "+f"(c[0]), "+f"(c[1]), "+f"(c[2]), "+f"(c[3])
        : "r"(a[0]), "r"(a[1]), "r"(a[2]), "r"(a[3]), "r"(b[0]), "r"(b[1]));
}
// split (x,y) into packed hi / lo bf16x2
__device__ __forceinline__ void split2(float x, float y, u32& hp, u32& lp) {
    bf hx = __float2bfloat16(x), hy = __float2bfloat16(y);
    bf lx = __float2bfloat16(x - __bfloat162float(hx));
    bf ly = __float2bfloat16(y - __bfloat162float(hy));
    hp = (u32)__bfloat16_as_ushort(hx) | ((u32)__bfloat16_as_ushort(hy) << 16);
    lp = (u32)__bfloat16_as_ushort(lx) | ((u32)__bfloat16_as_ushort(ly) << 16);
}

// ------------------------- bf16-split tensor-core GEMM, cp.async pipelined -----
// C[i,j] = act(alpha * sum_l A[i,l]*B[j,l] + bias[j])   i.e. D = A @ B^T
// OMODE: 0 = write fp32 C; 2 = write bf16 hi/lo (Ch, Cl) only.
template<int WN, int OMODE, bool GELU>
__global__ void __launch_bounds__(256) gemm_mma(
    const bf* __restrict__ Ah, const bf* __restrict__ Al,
    const bf* __restrict__ Bh, const bf* __restrict__ Bl,
    const float* __restrict__ bias, float* __restrict__ C,
    bf* __restrict__ Ch, bf* __restrict__ Cl,
    int K, int lda, int ldb, int ldc,
    long aB, long aH, long bB, long bH, long cB, long cH, int nh,
    float alpha, const unsigned* __restrict__ tptr)
{
    constexpr int BN = 2 * WN;
    constexpr int STR = 40;
    constexpr int ASZ = 128 * STR;
    constexpr int BSZ = BN * STR;
    constexpr int STAGE = 2 * ASZ + 2 * BSZ;

    extern __shared__ __align__(16) bf sm[];

    int z = blockIdx.z;
    int bb = z / nh, hh = z - bb * nh;
    Ah += bb * aB + hh * aH;  Al += bb * aB + hh * aH;
    Bh += bb * bB + hh * bH;  Bl += bb * bB + hh * bH;
    long coff = bb * cB + hh * cH;

    int i0 = blockIdx.y * 128;
    int j0 = blockIdx.x * BN;
    int tid = threadIdx.x;
    int lane = tid & 31, wid = tid >> 5;
    int wm = wid & 3, wn = wid >> 2;

    float acc[2][WN / 8][4] = {};
    const int nch = K / 32;

    auto load_stage = [&](int c, int s) {
        long kc = (long)c * 32;
        u32 base = s2u(sm + s * STAGE);
        #pragma unroll
        for (int t = 0; t < 2; t++) {
            int idx = tid + t * 256;
            int r = idx >> 2, sg = idx & 3;
            long go = (long)(i0 + r) * lda + kc + sg * 8;
            u32 so = (u32)(r * STR + sg * 8) * 2;
            cpa16(base + so, Ah + go);
            cpa16(base + ASZ * 2 + so, Al + go);
        }
        #pragma unroll
        for (int t = 0; t < BN / 64; t++) {
            int idx = tid + t * 256;
            int r = idx >> 2, sg = idx & 3;
            long go = (long)(j0 + r) * ldb + kc + sg * 8;
            u32 so = (u32)(r * STR + sg * 8) * 2;
            cpa16(base + 4 * ASZ + so, Bh + go);
            cpa16(base + 4 * ASZ + 2 * BSZ + so, Bl + go);
        }
    };

    load_stage(0, 0);
    cpcommit();

    for (int c = 0; c < nch; c++) {
        if (c + 1 < nch) {
            load_stage(c + 1, (c + 1) & 1);
            cpcommit();
            cpwait1();
        } else {
            cpwait0();
        }
        __syncthreads();

        const bf* sAh = sm + (c & 1) * STAGE;
        const bf* sAl = sAh + ASZ;
        const bf* sBh = sAl + ASZ;
        const bf* sBl = sBh + BSZ;

        #pragma unroll
        for (int ks = 0; ks < 2; ks++) {
            u32 afh[2][4], afl[2][4];
            #pragma unroll
            for (int mt = 0; mt < 2; mt++) {
                int row = wm * 32 + mt * 16 + (lane & 15);
                int col = ks * 16 + (lane >> 4) * 8;
                ldsm_x4(afh[mt], s2u(&sAh[row * STR + col]));
                ldsm_x4(afl[mt], s2u(&sAl[row * STR + col]));
            }
            #pragma unroll
            for (int nt = 0; nt < WN / 8; nt++) {
                int brow = wn * WN + nt * 8 + (lane & 7);
                int bcol = ks * 16 + ((lane >> 3) & 1) * 8;
                u32 bh[2], bl[2];
                ldsm_x2(bh, s2u(&sBh[brow * STR + bcol]));
                ldsm_x2(bl, s2u(&sBl[brow * STR + bcol]));
                #pragma unroll
                for (int mt = 0; mt < 2; mt++) {
                    mma16816(acc[mt][nt], afh[mt], bh);
                    mma16816(acc[mt][nt], afh[mt], bl);
                    mma16816(acc[mt][nt], afl[mt], bh);
                }
            }
        }
        __syncthreads();
    }

    float scl = alpha;
    if (tptr) {
        unsigned u = *tptr;
        float f = __uint_as_float(u);
        float temp = (f > 1e-6f && f < 1e6f) ? f : (float)(int)u;
        scl /= temp;
    }

    int grp = lane >> 2, qd = lane & 3;
    #pragma unroll
    for (int mt = 0; mt < 2; mt++) {
        #pragma unroll
        for (int nt = 0; nt < WN / 8; nt++) {
            int n = j0 + wn * WN + nt * 8 + qd * 2;
            float b0 = 0.f, b1 = 0.f;
            if (bias) { b0 = bias[n]; b1 = bias[n + 1]; }
            #pragma unroll
            for (int rh = 0; rh < 2; rh++) {
                int m = i0 + wm * 32 + mt * 16 + grp + rh * 8;
                float x = acc[mt][nt][rh * 2 + 0] * scl + b0;
                float y = acc[mt][nt][rh * 2 + 1] * scl + b1;
                if (GELU) {
                    x = 0.5f * x * (1.f + erff(x * 0.70710678118654752f));
                    y = 0.5f * y * (1.f + erff(y * 0.70710678118654752f));
                }
                long off = coff + (long)m * ldc + n;
                if (OMODE == 0) {
                    *(float2*)&C[off] = make_float2(x, y);
                } else {
                    u32 hp, lp;
                    split2(x, y, hp, lp);
                    *(u32*)&Ch[off] = hp;
                    *(u32*)&Cl[off] = lp;
                }
            }
        }
    }
}

// ------------------------- flash attention -------------------------
// One CTA = 128 q-rows of one (b,h). 8 warps x 16 rows each (warp-local softmax).
// kv tiled by 64, 2-stage cp.async pipeline. O written as bf16 hi/lo.
#define KVT 64
#define FSTR 72
#define FQSZ (128 * FSTR)
#define FKSZ (KVT * FSTR)
#define FSTG (4 * FKSZ)
#define FSMEM ((2 * FQSZ + 2 * FSTG) * 2)   // bytes = 110,592

__global__ void __launch_bounds__(256) flash_k(
    const bf* __restrict__ Qh, const bf* __restrict__ Ql,
    const bf* __restrict__ Kh, const bf* __restrict__ Kl,
    const bf* __restrict__ Vth, const bf* __restrict__ Vtl,
    bf* __restrict__ Oh, bf* __restrict__ Ol,
    const unsigned* __restrict__ tptr)
{
    extern __shared__ __align__(16) bf fsm[];
    bf* sQh = fsm;
    bf* sQl = fsm + FQSZ;
    bf* stg = fsm + 2 * FQSZ;

    int q0 = blockIdx.x * 128;
    int z = blockIdx.y;
    int b = z / NHH, h = z - b * NHH;
    long qoff = (long)b * SS * EE + h * DD;
    long voff = (long)z * DD * SS;

    int tid = threadIdx.x, lane = tid & 31, w = tid >> 5;
    int grp = lane >> 2, qd = lane & 3;

    // Q load (once): 128 rows x 64 cols = 128 x 8 segs of 8 bf16
    #pragma unroll
    for (int t = 0; t < 4; t++) {
        int idx = tid + t * 256;
        int r = idx >> 3, sg = idx & 7;
        long go = qoff + (long)(q0 + r) * EE + sg * 8;
        u32 so = (u32)(r * FSTR + sg * 8) * 2;
        cpa16(s2u(sQh) + so, Qh + go);
        cpa16(s2u(sQl) + so, Ql + go);
    }
    // KV stage: K 64 rows x 64 cols; V^T 64 d-rows x 64 kv-cols
    auto load_kv = [&](int c, int s) {
        bf* st = stg + s * FSTG;
        int kv0 = c * KVT;
        #pragma unroll
        for (int t = 0; t < 2; t++) {
            int idx = tid + t * 256;
            int r = idx >> 3, sg = idx & 7;
            u32 so = (u32)(r * FSTR + sg * 8) * 2;
            long gk = qoff + (long)(kv0 + r) * EE + sg * 8;
            cpa16(s2u(st) + so, Kh + gk);
            cpa16(s2u(st + FKSZ) + so, Kl + gk);
            long gv = voff + (long)r * SS + kv0 + sg * 8;
            cpa16(s2u(st + 2 * FKSZ) + so, Vth + gv);
            cpa16(s2u(st + 3 * FKSZ) + so, Vtl + gv);
        }
    };
    load_kv(0, 0);
    cpcommit();

    float scl;
    {
        unsigned u = *tptr;
        float f = __uint_as_float(u);
        float temp = (f > 1e-6f && f < 1e6f) ? f : (float)(int)u;
        scl = 0.125f / temp;
    }

    float m0 = -1e30f, m1 = -1e30f, l0 = 0.f, l1 = 0.f;
    float acc_o[8][4] = {};

    const int NT = SS / KVT;   // 16
    for (int c = 0; c < NT; c++) {
        if (c + 1 < NT) { load_kv(c + 1, (c + 1) & 1); cpcommit(); cpwait1(); }
        else cpwait0();
        __syncthreads();
        bf* st = stg + (c & 1) * FSTG;
        bf* sKh = st;
        bf* sKl = st + FKSZ;
        bf* sVh = st + 2 * FKSZ;
        bf* sVl = st + 3 * FKSZ;

        // ---- S = Q K^T (warp rows w*16..w*16+15, 64 kv cols) ----
        float s_[8][4] = {};
        #pragma unroll
        for (int t = 0; t < 4; t++) {
            u32 ah4[4], al4[4];
            int arow = w * 16 + (lane & 15);
            int acol = t * 16 + (lane >> 4) * 8;
            ldsm_x4(ah4, s2u(&sQh[arow * FSTR + acol]));
            ldsm_x4(al4, s2u(&sQl[arow * FSTR + acol]));
            #pragma unroll
            for (int j = 0; j < 8; j++) {
                int brow = j * 8 + (lane & 7);
                int bcol = t * 16 + ((lane >> 3) & 1) * 8;
                u32 bh2[2], bl2[2];
                ldsm_x2(bh2, s2u(&sKh[brow * FSTR + bcol]));
                ldsm_x2(bl2, s2u(&sKl[brow * FSTR + bcol]));
                mma16816(s_[j], ah4, bh2);
                mma16816(s_[j], ah4, bl2);
                mma16816(s_[j], al4, bh2);
            }
        }
        // ---- online softmax (rows grp, grp+8; warp-local) ----
        float t0 = -1e30f, t1 = -1e30f;
        #pragma unroll
        for (int j = 0; j < 8; j++) {
            s_[j][0] *= scl; s_[j][1] *= scl; s_[j][2] *= scl; s_[j][3] *= scl;
            t0 = fmaxf(t0, fmaxf(s_[j][0], s_[j][1]));
            t1 = fmaxf(t1, fmaxf(s_[j][2], s_[j][3]));
        }
        t0 = fmaxf(t0, __shfl_xor_sync(0xffffffffu, t0, 1));
        t0 = fmaxf(t0, __shfl_xor_sync(0xffffffffu, t0, 2));
        t1 = fmaxf(t1, __shfl_xor_sync(0xffffffffu, t1, 1));
        t1 = fmaxf(t1, __shfl_xor_sync(0xffffffffu, t1, 2));
        float nm0 = fmaxf(m0, t0), nm1 = fmaxf(m1, t1);
        float corr0 = __expf(m0 - nm0), corr1 = __expf(m1 - nm1);
        m0 = nm0; m1 = nm1;
        float sum0 = 0.f, sum1 = 0.f;
        #pragma unroll
        for (int j = 0; j < 8; j++) {
            s_[j][0] = __expf(s_[j][0] - m0);
            s_[j][1] = __expf(s_[j][1] - m0);
            s_[j][2] = __expf(s_[j][2] - m1);
            s_[j][3] = __expf(s_[j][3] - m1);
            sum0 += s_[j][0] + s_[j][1];
            sum1 += s_[j][2] + s_[j][3];
        }
        sum0 += __shfl_xor_sync(0xffffffffu, sum0, 1);
        sum0 += __shfl_xor_sync(0xffffffffu, sum0, 2);
        sum1 += __shfl_xor_sync(0xffffffffu, sum1, 1);
        sum1 += __shfl_xor_sync(0xffffffffu, sum1, 2);
        l0 = l0 * corr0 + sum0;
        l1 = l1 * corr1 + sum1;
        #pragma unroll
        for (int n = 0; n < 8; n++) {
            acc_o[n][0] *= corr0; acc_o[n][1] *= corr0;
            acc_o[n][2] *= corr1; acc_o[n][3] *= corr1;
        }
        // ---- O += P @ V (P C-frags -> A-frags in registers) ----
        #pragma unroll
        for (int t = 0; t < 4; t++) {
            u32 pah[4], pal[4];
            split2(s_[2 * t][0],     s_[2 * t][1],     pah[0], pal[0]);
            split2(s_[2 * t][2],     s_[2 * t][3],     pah[1], pal[1]);
            split2(s_[2 * t + 1][0], s_[2 * t + 1][1], pah[2], pal[2]);
            split2(s_[2 * t + 1][2], s_[2 * t + 1][3], pah[3], pal[3]);
            #pragma unroll
            for (int n = 0; n < 8; n++) {
                int brow = n * 8 + (lane & 7);
                int bcol = t * 16 + ((lane >> 3) & 1) * 8;
                u32 bh2[2], bl2[2];
                ldsm_x2(bh2, s2u(&sVh[brow * FSTR + bcol]));
                ldsm_x2(bl2, s2u(&sVl[brow * FSTR + bcol]));
                mma16816(acc_o[n], pah, bh2);
                mma16816(acc_o[n], pah, bl2);
                mma16816(acc_o[n], pal, bh2);
            }
        }
        __syncthreads();
    }

    // ---- epilogue: normalize + hi/lo write ----
    float inv0 = 1.f / l0, inv1 = 1.f / l1;
    int r0 = q0 + w * 16 + grp;
    #pragma unroll
    for (int n = 0; n < 8; n++) {
        int col = h * DD + n * 8 + qd * 2;
        {
            long off = (long)b * SS * EE + (long)r0 * EE + col;
            u32 hp, lp;
            split2(acc_o[n][0] * inv0, acc_o[n][1] * inv0, hp, lp);
            *(u32*)&Oh[off] = hp;
            *(u32*)&Ol[off] = lp;
        }
        {
            long off = (long)b * SS * EE + (long)(r0 + 8) * EE + col;
            u32 hp, lp;
            split2(acc_o[n][2] * inv1, acc_o[n][3] * inv1, hp, lp);
            *(u32*)&Oh[off] = hp;
            *(u32*)&Ol[off] = lp;
        }
    }
}

// ------------------------- elementwise hi/lo split -------------------------
__global__ void split_k(const float* __restrict__ x, bf* __restrict__ h,
                        bf* __restrict__ l, long n)
{
    long i = ((long)blockIdx.x * blockDim.x + threadIdx.x) * 4;
    if (i >= n) return;
    float4 v = *(const float4*)(x + i);
    float vv[4] = {v.x, v.y, v.z, v.w};
    u32 hp[2], lp[2];
    split2(vv[0], vv[1], hp[0], lp[0]);
    split2(vv[2], vv[3], hp[1], lp[1]);
    *(uint2*)(h + i) = make_uint2(hp[0], hp[1]);
    *(uint2*)(l + i) = make_uint2(lp[0], lp[1]);
}

// ------------------------- transpose + split -------------------------
__global__ void tsplit_k(const float* __restrict__ src, bf* __restrict__ h,
                         bf* __restrict__ l,
                         int lds, int ldd, long sB, long sH, long dB, long dH, int nh)
{
    __shared__ float sm[32][33];
    int z = blockIdx.z;
    int bb = z / nh, hh = z - bb * nh;
    src += bb * sB + hh * sH;
    h   += bb * dB + hh * dH;
    l   += bb * dB + hh * dH;
    int r0 = blockIdx.y * 32, c0 = blockIdx.x * 32;
    int tx = threadIdx.x, ty = threadIdx.y;
    #pragma unroll
    for (int i = 0; i < 4; i++)
        sm[ty + 8 * i][tx] = src[(long)(r0 + ty + 8 * i) * lds + c0 + tx];
    __syncthreads();
    #pragma unroll
    for (int i = 0; i < 4; i++) {
        int n = c0 + ty + 8 * i, k = r0 + tx;
        float v = sm[tx][ty + 8 * i];
        bf hv = __float2bfloat16(v);
        bf lv = __float2bfloat16(v - __bfloat162float(hv));
        h[(long)n * ldd + k] = hv;
        l[(long)n * ldd + k] = lv;
    }
}

// ------------------------- residual + layernorm (+ optional split out) -------------------------
__global__ void ln_k(const float* __restrict__ x, const float* __restrict__ res,
                     const float* __restrict__ gamma, const float* __restrict__ beta,
                     float* __restrict__ out,
                     bf* __restrict__ oh = nullptr,
                     bf* __restrict__ ol = nullptr)
{
    long row = blockIdx.x;
    int t = threadIdx.x;
    float4 v = ((const float4*)(x + row * EE))[t];
    if (res) {
        float4 r = ((const float4*)(res + row * EE))[t];
        v.x += r.x; v.y += r.y; v.z += r.z; v.w += r.w;
    }
    float s = v.x + v.y + v.z + v.w;
    float q = v.x * v.x + v.y * v.y + v.z * v.z + v.w * v.w;
    #pragma unroll
    for (int o = 16; o; o >>= 1) {
        s += __shfl_xor_sync(0xffffffffu, s, o);
        q += __shfl_xor_sync(0xffffffffu, q, o);
    }
    __shared__ float shS[4], shQ[4];
    int w = t >> 5;
    if ((t & 31) == 0) { shS[w] = s; shQ[w] = q; }
    __syncthreads();
    s = shS[0] + shS[1] + shS[2] + shS[3];
    q = shQ[0] + shQ[1] + shQ[2] + shQ[3];
    float mean = s * (1.f / EE);
    float var = q * (1.f / EE) - mean * mean;
    float rstd = rsqrtf(var + 1e-5f);
    float4 g = ((const float4*)gamma)[t];
    float4 b = ((const float4*)beta)[t];
    float4 o;
    o.x = (v.x - mean) * rstd * g.x + b.x;
    o.y = (v.y - mean) * rstd * g.y + b.y;
    o.z = (v.z - mean) * rstd * g.z + b.z;
    o.w = (v.w - mean) * rstd * g.w + b.w;
    ((float4*)(out + row * EE))[t] = o;
    if (oh) {
        u32 hp[2], lp[2];
        split2(o.x, o.y, hp[0], lp[0]);
        split2(o.z, o.w, hp[1], lp[1]);
        *(uint2*)(oh + row * EE + t * 4) = make_uint2(hp[0], hp[1]);
        *(uint2*)(ol + row * EE + t * 4) = make_uint2(lp[0], lp[1]);
    }
}

// ------------------------- gate + mix -------------------------
__global__ void gate_mix_k(const float* __restrict__ x, const float* __restrict__ cr,
                           const float* __restrict__ gw, const float* __restrict__ gb,
                           float* __restrict__ out)
{
    long row = blockIdx.x;
    int t = threadIdx.x;
    float4 xv = ((const float4*)(x + row * EE))[t];
    float4 cv = ((const float4*)(cr + row * EE))[t];
    int k0 = t * 4;
    float l0 = 0.f, l1 = 0.f;
    float xs[4] = {xv.x, xv.y, xv.z, xv.w};
    float cs[4] = {cv.x, cv.y, cv.z, cv.w};
    #pragma unroll
    for (int e = 0; e < 4; e++) {
        int k = k0 + e;
        l0 += xs[e] * gw[k * 2 + 0] + cs[e] * gw[(EE + k) * 2 + 0];
        l1 += xs[e] * gw[k * 2 + 1] + cs[e] * gw[(EE + k) * 2 + 1];
    }
    #pragma unroll
    for (int o = 16; o; o >>= 1) {
        l0 += __shfl_xor_sync(0xffffffffu, l0, o);
        l1 += __shfl_xor_sync(0xffffffffu, l1, o);
    }
    __shared__ float sh0[4], sh1[4];
    int w = t >> 5;
    if ((t & 31) == 0) { sh0[w] = l0; sh1[w] = l1; }
    __syncthreads();
    l0 = sh0[0] + sh0[1] + sh0[2] + sh0[3] + gb[0];
    l1 = sh1[0] + sh1[1] + sh1[2] + sh1[3] + gb[1];
    float m = fmaxf(l0, l1);
    float e0 = __expf(l0 - m), e1 = __expf(l1 - m);
    float g0 = e0 / (e0 + e1), g1 = e1 / (e0 + e1);
    float4 o;
    o.x = xv.x * g0 + cv.x * g1;
    o.y = xv.y * g0 + cv.y * g1;
    o.z = xv.z * g0 + cv.z * g1;
    o.w = xv.w * g0 + cv.w * g1;
    ((float4*)(out + row * EE))[t] = o;
}

// ------------------------- host orchestration -------------------------
static float* sym(const void* s) { void* p = nullptr; cudaGetSymbolAddress(&p, s); return (float*)p; }
static bf* symb(const void* s)   { void* p = nullptr; cudaGetSymbolAddress(&p, s); return (bf*)p; }

#define SMEM64 ((2 * 128 * 40 + 2 * 128 * 40) * 2 * 2)   // 81920 B
#define SMEM32 ((2 * 128 * 40 + 2 * 64 * 40) * 2 * 2)    // 61440 B

struct Weights {
    const float *qb, *kb, *vb, *ob;
    const unsigned* temp;
};

static void gemm_f32(const bf* ah, const bf* al, const bf* bh, const bf* bl,
                     const float* bias, float* C, int M, int N, int K) {
    dim3 grid(N / 128, M / 128, 1);
    gemm_mma<64, 0, false><<<grid, 256, SMEM64>>>(ah, al, bh, bl, bias, C, nullptr, nullptr,
        K, K, K, N, 0, 0, 0, 0, 0, 0, 1, 1.f, nullptr);
}
static void gemm_sp(const bf* ah, const bf* al, const bf* bh, const bf* bl,
                    const float* bias, bf* Ch, bf* Cl, int M, int N, int K, bool gelu) {
    dim3 grid(N / 128, M / 128, 1);
    if (gelu)
        gemm_mma<64, 2, true><<<grid, 256, SMEM64>>>(ah, al, bh, bl, bias, nullptr, Ch, Cl,
            K, K, K, N, 0, 0, 0, 0, 0, 0, 1, 1.f, nullptr);
    else
        gemm_mma<64, 2, false><<<grid, 256, SMEM64>>>(ah, al, bh, bl, bias, nullptr, Ch, Cl,
            K, K, K, N, 0, 0, 0, 0, 0, 0, 1, 1.f, nullptr);
}

static void run_attn(int i, const bf* qih, const bf* qil, const bf* kih, const bf* kil,
                     const Weights& W, float* out)
{
    bf *qh = symb(g_qh), *ql = symb(g_ql);
    bf *kh = symb(g_kh), *kl = symb(g_kl);
    bf *vth = symb(g_vth), *vtl = symb(g_vtl);
    bf *atth = symb(g_atth), *attl = symb(g_attl);
    float *v = sym(g_v);
    long wo = (long)i * EE * EE;
    long bo = (long)i * EE;

    gemm_sp(qih, qil, symb(g_qwth) + wo, symb(g_qwtl) + wo, W.qb + bo, qh, ql, NTOK, EE, EE, false);
    gemm_sp(kih, kil, symb(g_kwth) + wo, symb(g_kwtl) + wo, W.kb + bo, kh, kl, NTOK, EE, EE, false);
    gemm_f32(kih, kil, symb(g_vwth) + wo, symb(g_vwtl) + wo, W.vb + bo, v, NTOK, EE, EE);

    {   // V^T per head: [b,h,d,s]
        dim3 grid(DD / 32, SS / 32, NB);
        tsplit_k<<<grid, dim3(32, 8)>>>(v, vth, vtl, EE, SS,
            (long)SS * EE, DD, (long)NHH * DD * SS, (long)DD * SS, NHH);
    }

    // fused flash attention -> att hi/lo
    flash_k<<<dim3(SS / 128, NB), 256, FSMEM>>>(qh, ql, kh, kl, vth, vtl, atth, attl, W.temp);

    gemm_f32(atth, attl, symb(g_owth) + wo, symb(g_owtl) + wo, W.ob + bo, out, NTOK, EE, EE);
}

extern "C" void kernel_launch(void* const* d_in, const int* in_sizes, int n_in,
                              void* d_out, int out_size)
{
    const float* body_feats = (const float*)d_in[0];
    const float* limb_feats = (const float*)d_in[1];
    const float* attn_qw = (const float*)d_in[2];
    const float* attn_qb = (const float*)d_in[3];
    const float* attn_kw = (const float*)d_in[4];
    const float* attn_kb = (const float*)d_in[5];
    const float* attn_vw = (const float*)d_in[6];
    const float* attn_vb = (const float*)d_in[7];
    const float* attn_ow = (const float*)d_in[8];
    const float* attn_ob = (const float*)d_in[9];
    const float* ffn_w1 = (const float*)d_in[10];
    const float* ffn_b1 = (const float*)d_in[11];
    const float* ffn_w2 = (const float*)d_in[12];
    const float* ffn_b2 = (const float*)d_in[13];
    const float* nsc = (const float*)d_in[14];
    const float* nbi = (const float*)d_in[15];
    const float* gw = (const float*)d_in[16];
    const float* gb = (const float*)d_in[17];

    Weights W;
    W.qb = attn_qb; W.kb = attn_kb; W.vb = attn_vb; W.ob = attn_ob;
    W.temp = (const unsigned*)d_in[18];

    cudaFuncSetAttribute(gemm_mma<64, 0, false>, cudaFuncAttributeMaxDynamicSharedMemorySize, SMEM64);
    cudaFuncSetAttribute(gemm_mma<64, 2, false>, cudaFuncAttributeMaxDynamicSharedMemorySize, SMEM64);
    cudaFuncSetAttribute(gemm_mma<64, 2, true>,  cudaFuncAttributeMaxDynamicSharedMemorySize, SMEM64);
    cudaFuncSetAttribute(flash_k, cudaFuncAttributeMaxDynamicSharedMemorySize, FSMEM);

    float* out = (float*)d_out;
    float* out_body = out;
    float* out_limb = out + TOKE;

    float* tmp  = sym(g_tmp);
    float* body = sym(g_body);
    float* limb = sym(g_limb);
    float* crB  = sym(g_crossB);
    float* crL  = sym(g_crossL);
    float* mixB = sym(g_mixB);
    float* mixL = sym(g_mixL);
    float* ffn  = sym(g_ffn);
    bf *bfh = symb(g_bfh), *bfl = symb(g_bfl);
    bf *lfh = symb(g_lfh), *lfl = symb(g_lfl);
    bf *bodyh = symb(g_bodyh), *bodyl = symb(g_bodyl);
    bf *limbh = symb(g_limbh), *limbl = symb(g_limbl);
    bf *hidh = symb(g_hidh), *hidl = symb(g_hidl);

    // ---- weight transposes + splits ----
    {
        dim3 blk(32, 8);
        dim3 gE(EE / 32, EE / 32, 4);
        tsplit_k<<<gE, blk>>>(attn_qw, symb(g_qwth), symb(g_qwtl), EE, EE,
                              (long)EE * EE, 0, (long)EE * EE, 0, 1);
        tsplit_k<<<gE, blk>>>(attn_kw, symb(g_kwth), symb(g_kwtl), EE, EE,
                              (long)EE * EE, 0, (long)EE * EE, 0, 1);
        tsplit_k<<<gE, blk>>>(attn_vw, symb(g_vwth), symb(g_vwtl), EE, EE,
                              (long)EE * EE, 0, (long)EE * EE, 0, 1);
        tsplit_k<<<gE, blk>>>(attn_ow, symb(g_owth), symb(g_owtl), EE, EE,
                              (long)EE * EE, 0, (long)EE * EE, 0, 1);
        dim3 g1(4 * EE / 32, EE / 32, 2);
        tsplit_k<<<g1, blk>>>(ffn_w1, symb(g_w1th), symb(g_w1tl), 4 * EE, EE,
                              (long)EE * 4 * EE, 0, (long)EE * 4 * EE, 0, 1);
        dim3 g2(EE / 32, 4 * EE / 32, 2);
        tsplit_k<<<g2, blk>>>(ffn_w2, symb(g_w2th), symb(g_w2tl), EE, 4 * EE,
                              (long)EE * 4 * EE, 0, (long)EE * 4 * EE, 0, 1);
    }

    // ---- input splits (once) ----
    split_k<<<(unsigned)(TOKE / 1024), 256>>>(body_feats, bfh, bfl, TOKE);
    split_k<<<(unsigned)(TOKE / 1024), 256>>>(limb_feats, lfh, lfl, TOKE);

    // ---- self attentions + norm1 (split out for cross attn) ----
    run_attn(0, bfh, bfl, bfh, bfl, W, tmp);
    ln_k<<<NTOK, 128>>>(body_feats, tmp, nsc + 0 * EE, nbi + 0 * EE, body, bodyh, bodyl);

    run_attn(1, lfh, lfl, lfh, lfl, W, tmp);
    ln_k<<<NTOK, 128>>>(limb_feats, tmp, nsc + 3 * EE, nbi + 3 * EE, limb, limbh, limbl);

    // ---- cross attentions ----
    run_attn(2, bodyh, bodyl, limbh, limbl, W, crB);
    run_attn(3, limbh, limbl, bodyh, bodyl, W, crL);

    // ---- gates + norm2(body) on both streams (faithful to reference) ----
    gate_mix_k<<<NTOK, 128>>>(body, crB, gw, gb, mixB);
    gate_mix_k<<<NTOK, 128>>>(limb, crL, gw, gb, mixL);
    ln_k<<<NTOK, 128>>>(mixB, nullptr, nsc + 1 * EE, nbi + 1 * EE, body, bodyh, bodyl);
    ln_k<<<NTOK, 128>>>(mixL, nullptr, nsc + 1 * EE, nbi + 1 * EE, limb, limbh, limbl);

    // ---- FFN body ----
    gemm_sp(bodyh, bodyl, symb(g_w1th), symb(g_w1tl), ffn_b1, hidh, hidl, NTOK, 4 * EE, EE, true);
    gemm_f32(hidh, hidl, symb(g_w2th), symb(g_w2tl), ffn_b2, ffn, NTOK, EE, 4 * EE);
    ln_k<<<NTOK, 128>>>(body, ffn, nsc + 2 * EE, nbi + 2 * EE, out_body);

    // ---- FFN limb ----
    gemm_sp(limbh, limbl, symb(g_w1th) + (long)4 * EE * EE, symb(g_w1tl) + (long)4 * EE * EE,
            ffn_b1 + 4 * EE, hidh, hidl, NTOK, 4 * EE, EE, true);
    gemm_f32(hidh, hidl, symb(g_w2th) + (long)4 * EE * EE, symb(g_w2tl) + (long)4 * EE * EE,
             ffn_b2 + EE, ffn, NTOK, EE, 4 * EE);
    ln_k<<<NTOK, 128>>>(limb, ffn, nsc + 5 * EE, nbi + 5 * EE, out_limb);
}

// round 10
// speedup vs baseline: 3.2650x; 1.1278x over previous
#include <cuda_runtime.h>
#include <cuda_bf16.h>
#include <math.h>

typedef unsigned int u32;
typedef unsigned long long u64;
typedef __nv_bfloat16 bf;

#define BB 4
#define SS 1024
#define EE 512
#define NHH 8
#define DD 64
#define NTOK (BB*SS)          // 4096
#define TOKE ((long)NTOK*EE)  // 2,097,152
#define NB (BB*NHH)           // 32
#define NQKV 1536

// ------------------------- fp32 scratch -------------------------
__device__ float g_tmp[NTOK*EE];
__device__ float g_body[NTOK*EE];
__device__ float g_limb[NTOK*EE];
__device__ float g_crossB[NTOK*EE];
__device__ float g_crossL[NTOK*EE];
__device__ float g_mixB[NTOK*EE];
__device__ float g_mixL[NTOK*EE];
__device__ float g_ffn[NTOK*EE];
__device__ float g_qkvb[4*NQKV];          // packed q/k/v bias

// ------------------------- bf16 split scratch (16B aligned) -------------------------
__device__ __align__(16) bf g_bfh[NTOK*EE], g_bfl[NTOK*EE];
__device__ __align__(16) bf g_lfh[NTOK*EE], g_lfl[NTOK*EE];
__device__ __align__(16) bf g_bodyh[NTOK*EE], g_bodyl[NTOK*EE];
__device__ __align__(16) bf g_limbh[NTOK*EE], g_limbl[NTOK*EE];
__device__ __align__(16) bf g_qkvh[(long)NTOK*NQKV], g_qkvl[(long)NTOK*NQKV];
__device__ __align__(16) bf g_atth[NTOK*EE], g_attl[NTOK*EE];
__device__ __align__(16) bf g_hidh[(long)NTOK*4*EE], g_hidl[(long)NTOK*4*EE];
__device__ __align__(16) bf g_wqkvh[(long)4*NQKV*EE], g_wqkvl[(long)4*NQKV*EE];
__device__ __align__(16) bf g_owth[4*EE*EE], g_owtl[4*EE*EE];
__device__ __align__(16) bf g_w1th[(long)2*EE*4*EE], g_w1tl[(long)2*EE*4*EE];
__device__ __align__(16) bf g_w2th[(long)2*EE*4*EE], g_w2tl[(long)2*EE*4*EE];

// ------------------------- asm helpers -------------------------
__device__ __forceinline__ u32 s2u(const void* p) {
    u32 a;
    asm("{ .reg .u64 t; cvta.to.shared.u64 t, %1; cvt.u32.u64 %0, t; }" : "=r"(a) : "l"(p));
    return a;
}
__device__ __forceinline__ void cpa16(u32 saddr, const void* g) {
    asm volatile("cp.async.cg.shared.global [%0], [%1], 16;" :: "r"(saddr), "l"(g));
}
__device__ __forceinline__ void cpcommit() { asm volatile("cp.async.commit_group;"); }
__device__ __forceinline__ void cpwait1()  { asm volatile("cp.async.wait_group 1;"); }
__device__ __forceinline__ void cpwait0()  { asm volatile("cp.async.wait_group 0;"); }

__device__ __forceinline__ void ldsm_x4(u32 r[4], u32 addr) {
    asm volatile("ldmatrix.sync.aligned.m8n8.x4.shared.b16 {%0,%1,%2,%3}, [%4];"
                 : "=r"(r[0]), "=r"(r[1]), "=r"(r[2]), "=r"(r[3]) : "r"(addr));
}
__device__ __forceinline__ void ldsm_x2(u32 r[2], u32 addr) {
    asm volatile("ldmatrix.sync.aligned.m8n8.x2.shared.b16 {%0,%1}, [%2];"
                 : "=r"(r[0]), "=r"(r[1]) : "r"(addr));
}
__device__ __forceinline__ void ldsm_x2t(u32 r[2], u32 addr) {
    asm volatile("ldmatrix.sync.aligned.m8n8.x2.trans.shared.b16 {%0,%1}, [%2];"
                 : "=r"(r[0]), "=r"(r[1]) : "r"(addr));
}
__device__ __forceinline__ void mma16816(float c[4], const u32 a[4], const u32 b[2]) {
    asm volatile(
        "mma.sync.aligned.m16n8k16.row.col.f32.bf16.bf16.f32 "
        "{%0,%1,%2,%3}, {%4,%5,%6,%7}, {%8,%9}, {%0,%1,%2,%3};"
        : "+f"(c[0]), "+f"(c[1]), "+f"(c[2]), "+f"(c[3])
        : "r"(a[0]), "r"(a[1]), "r"(a[2]), "r"(a[3]), "r"(b[0]), "r"(b[1]));
}
__device__ __forceinline__ void split2(float x, float y, u32& hp, u32& lp) {
    bf hx = __float2bfloat16(x), hy = __float2bfloat16(y);
    bf lx = __float2bfloat16(x - __bfloat162float(hx));
    bf ly = __float2bfloat16(y - __bfloat162float(hy));
    hp = (u32)__bfloat16_as_ushort(hx) | ((u32)__bfloat16_as_ushort(hy) << 16);
    lp = (u32)__bfloat16_as_ushort(lx) | ((u32)__bfloat16_as_ushort(ly) << 16);
}

// ------------------------- bf16-split tensor-core GEMM, cp.async pipelined -----
// C[i,j] = act(alpha * sum_l A[i,l]*B[j,l] + bias[j])   i.e. D = A @ B^T
// OMODE: 0 = write fp32 C; 2 = write bf16 hi/lo (Ch, Cl) only.
template<int WN, int OMODE, bool GELU>
__global__ void __launch_bounds__(256) gemm_mma(
    const bf* __restrict__ Ah, const bf* __restrict__ Al,
    const bf* __restrict__ Bh, const bf* __restrict__ Bl,
    const float* __restrict__ bias, float* __restrict__ C,
    bf* __restrict__ Ch, bf* __restrict__ Cl,
    int K, int lda, int ldb, int ldc,
    long aB, long aH, long bB, long bH, long cB, long cH, int nh,
    float alpha, const unsigned* __restrict__ tptr)
{
    constexpr int BN = 2 * WN;
    constexpr int STR = 40;
    constexpr int ASZ = 128 * STR;
    constexpr int BSZ = BN * STR;
    constexpr int STAGE = 2 * ASZ + 2 * BSZ;

    extern __shared__ __align__(16) bf sm[];

    int z = blockIdx.z;
    int bb = z / nh, hh = z - bb * nh;
    Ah += bb * aB + hh * aH;  Al += bb * aB + hh * aH;
    Bh += bb * bB + hh * bH;  Bl += bb * bB + hh * bH;
    long coff = bb * cB + hh * cH;

    int i0 = blockIdx.y * 128;
    int j0 = blockIdx.x * BN;
    int tid = threadIdx.x;
    int lane = tid & 31, wid = tid >> 5;
    int wm = wid & 3, wn = wid >> 2;

    float acc[2][WN / 8][4] = {};
    const int nch = K / 32;

    auto load_stage = [&](int c, int s) {
        long kc = (long)c * 32;
        u32 base = s2u(sm + s * STAGE);
        #pragma unroll
        for (int t = 0; t < 2; t++) {
            int idx = tid + t * 256;
            int r = idx >> 2, sg = idx & 3;
            long go = (long)(i0 + r) * lda + kc + sg * 8;
            u32 so = (u32)(r * STR + sg * 8) * 2;
            cpa16(base + so, Ah + go);
            cpa16(base + ASZ * 2 + so, Al + go);
        }
        #pragma unroll
        for (int t = 0; t < BN / 64; t++) {
            int idx = tid + t * 256;
            int r = idx >> 2, sg = idx & 3;
            long go = (long)(j0 + r) * ldb + kc + sg * 8;
            u32 so = (u32)(r * STR + sg * 8) * 2;
            cpa16(base + 4 * ASZ + so, Bh + go);
            cpa16(base + 4 * ASZ + 2 * BSZ + so, Bl + go);
        }
    };

    load_stage(0, 0);
    cpcommit();

    for (int c = 0; c < nch; c++) {
        if (c + 1 < nch) {
            load_stage(c + 1, (c + 1) & 1);
            cpcommit();
            cpwait1();
        } else {
            cpwait0();
        }
        __syncthreads();

        const bf* sAh = sm + (c & 1) * STAGE;
        const bf* sAl = sAh + ASZ;
        const bf* sBh = sAl + ASZ;
        const bf* sBl = sBh + BSZ;

        #pragma unroll
        for (int ks = 0; ks < 2; ks++) {
            u32 afh[2][4], afl[2][4];
            #pragma unroll
            for (int mt = 0; mt < 2; mt++) {
                int row = wm * 32 + mt * 16 + (lane & 15);
                int col = ks * 16 + (lane >> 4) * 8;
                ldsm_x4(afh[mt], s2u(&sAh[row * STR + col]));
                ldsm_x4(afl[mt], s2u(&sAl[row * STR + col]));
            }
            #pragma unroll
            for (int nt = 0; nt < WN / 8; nt++) {
                int brow = wn * WN + nt * 8 + (lane & 7);
                int bcol = ks * 16 + ((lane >> 3) & 1) * 8;
                u32 bh[2], bl[2];
                ldsm_x2(bh, s2u(&sBh[brow * STR + bcol]));
                ldsm_x2(bl, s2u(&sBl[brow * STR + bcol]));
                #pragma unroll
                for (int mt = 0; mt < 2; mt++) {
                    mma16816(acc[mt][nt], afh[mt], bh);
                    mma16816(acc[mt][nt], afh[mt], bl);
                    mma16816(acc[mt][nt], afl[mt], bh);
                }
            }
        }
        __syncthreads();
    }

    float scl = alpha;
    if (tptr) {
        unsigned u = *tptr;
        float f = __uint_as_float(u);
        float temp = (f > 1e-6f && f < 1e6f) ? f : (float)(int)u;
        scl /= temp;
    }

    int grp = lane >> 2, qd = lane & 3;
    #pragma unroll
    for (int mt = 0; mt < 2; mt++) {
        #pragma unroll
        for (int nt = 0; nt < WN / 8; nt++) {
            int n = j0 + wn * WN + nt * 8 + qd * 2;
            float b0 = 0.f, b1 = 0.f;
            if (bias) { b0 = bias[n]; b1 = bias[n + 1]; }
            #pragma unroll
            for (int rh = 0; rh < 2; rh++) {
                int m = i0 + wm * 32 + mt * 16 + grp + rh * 8;
                float x = acc[mt][nt][rh * 2 + 0] * scl + b0;
                float y = acc[mt][nt][rh * 2 + 1] * scl + b1;
                if (GELU) {
                    x = 0.5f * x * (1.f + erff(x * 0.70710678118654752f));
                    y = 0.5f * y * (1.f + erff(y * 0.70710678118654752f));
                }
                long off = coff + (long)m * ldc + n;
                if (OMODE == 0) {
                    *(float2*)&C[off] = make_float2(x, y);
                } else {
                    u32 hp, lp;
                    split2(x, y, hp, lp);
                    *(u32*)&Ch[off] = hp;
                    *(u32*)&Cl[off] = lp;
                }
            }
        }
    }
}

// ------------------------- flash attention (packed QKV input) -------------------------
// QKV layout: [token 0..4095][1536] with cols 0-511 = Q, 512-1023 = K, 1024-1535 = V.
// One CTA = 128 q-rows of one (b,h). 8 warps x 16 rows each (warp-local softmax).
// kv tiled by 64, 2-stage cp.async pipeline. V kept [kv, d]; PV uses ldmatrix.trans.
#define KVT 64
#define FSTR 72
#define FQSZ (128 * FSTR)
#define FKSZ (KVT * FSTR)
#define FSTG (4 * FKSZ)
#define FSMEM ((2 * FQSZ + 2 * FSTG) * 2)   // 110,592 B

__global__ void __launch_bounds__(256) flash_k(
    const bf* __restrict__ QKVh, const bf* __restrict__ QKVl,
    bf* __restrict__ Oh, bf* __restrict__ Ol,
    const unsigned* __restrict__ tptr)
{
    extern __shared__ __align__(16) bf fsm[];
    bf* sQh = fsm;
    bf* sQl = fsm + FQSZ;
    bf* stg = fsm + 2 * FQSZ;

    int q0 = blockIdx.x * 128;
    int z = blockIdx.y;
    int b = z / NHH, h = z - b * NHH;
    long qbase = (long)b * SS * NQKV + h * DD;

    int tid = threadIdx.x, lane = tid & 31, w = tid >> 5;
    int grp = lane >> 2, qd = lane & 3;

    // Q load (once): 128 rows x 64 cols
    #pragma unroll
    for (int t = 0; t < 4; t++) {
        int idx = tid + t * 256;
        int r = idx >> 3, sg = idx & 7;
        long go = qbase + (long)(q0 + r) * NQKV + sg * 8;
        u32 so = (u32)(r * FSTR + sg * 8) * 2;
        cpa16(s2u(sQh) + so, QKVh + go);
        cpa16(s2u(sQl) + so, QKVl + go);
    }
    // KV stage: K rows kv x 64 d;  V rows kv x 64 d (row-major kv)
    auto load_kv = [&](int c, int s) {
        bf* st = stg + s * FSTG;
        int kv0 = c * KVT;
        #pragma unroll
        for (int t = 0; t < 2; t++) {
            int idx = tid + t * 256;
            int r = idx >> 3, sg = idx & 7;
            u32 so = (u32)(r * FSTR + sg * 8) * 2;
            long gk = qbase + 512 + (long)(kv0 + r) * NQKV + sg * 8;
            cpa16(s2u(st) + so, QKVh + gk);
            cpa16(s2u(st + FKSZ) + so, QKVl + gk);
            long gv = qbase + 1024 + (long)(kv0 + r) * NQKV + sg * 8;
            cpa16(s2u(st + 2 * FKSZ) + so, QKVh + gv);
            cpa16(s2u(st + 3 * FKSZ) + so, QKVl + gv);
        }
    };
    load_kv(0, 0);
    cpcommit();

    float scl;
    {
        unsigned u = *tptr;
        float f = __uint_as_float(u);
        float temp = (f > 1e-6f && f < 1e6f) ? f : (float)(int)u;
        scl = 0.125f / temp;
    }

    float m0 = -1e30f, m1 = -1e30f, l0 = 0.f, l1 = 0.f;
    float acc_o[8][4] = {};

    const int NT = SS / KVT;   // 16
    for (int c = 0; c < NT; c++) {
        if (c + 1 < NT) { load_kv(c + 1, (c + 1) & 1); cpcommit(); cpwait1(); }
        else cpwait0();
        __syncthreads();
        bf* st = stg + (c & 1) * FSTG;
        bf* sKh = st;
        bf* sKl = st + FKSZ;
        bf* sVh = st + 2 * FKSZ;
        bf* sVl = st + 3 * FKSZ;

        // ---- S = Q K^T ----
        float s_[8][4] = {};
        #pragma unroll
        for (int t = 0; t < 4; t++) {
            u32 ah4[4], al4[4];
            int arow = w * 16 + (lane & 15);
            int acol = t * 16 + (lane >> 4) * 8;
            ldsm_x4(ah4, s2u(&sQh[arow * FSTR + acol]));
            ldsm_x4(al4, s2u(&sQl[arow * FSTR + acol]));
            #pragma unroll
            for (int j = 0; j < 8; j++) {
                int brow = j * 8 + (lane & 7);
                int bcol = t * 16 + ((lane >> 3) & 1) * 8;
                u32 bh2[2], bl2[2];
                ldsm_x2(bh2, s2u(&sKh[brow * FSTR + bcol]));
                ldsm_x2(bl2, s2u(&sKl[brow * FSTR + bcol]));
                mma16816(s_[j], ah4, bh2);
                mma16816(s_[j], ah4, bl2);
                mma16816(s_[j], al4, bh2);
            }
        }
        // ---- online softmax (rows grp, grp+8; warp-local) ----
        float t0 = -1e30f, t1 = -1e30f;
        #pragma unroll
        for (int j = 0; j < 8; j++) {
            s_[j][0] *= scl; s_[j][1] *= scl; s_[j][2] *= scl; s_[j][3] *= scl;
            t0 = fmaxf(t0, fmaxf(s_[j][0], s_[j][1]));
            t1 = fmaxf(t1, fmaxf(s_[j][2], s_[j][3]));
        }
        t0 = fmaxf(t0, __shfl_xor_sync(0xffffffffu, t0, 1));
        t0 = fmaxf(t0, __shfl_xor_sync(0xffffffffu, t0, 2));
        t1 = fmaxf(t1, __shfl_xor_sync(0xffffffffu, t1, 1));
        t1 = fmaxf(t1, __shfl_xor_sync(0xffffffffu, t1, 2));
        float nm0 = fmaxf(m0, t0), nm1 = fmaxf(m1, t1);
        float corr0 = __expf(m0 - nm0), corr1 = __expf(m1 - nm1);
        m0 = nm0; m1 = nm1;
        float sum0 = 0.f, sum1 = 0.f;
        #pragma unroll
        for (int j = 0; j < 8; j++) {
            s_[j][0] = __expf(s_[j][0] - m0);
            s_[j][1] = __expf(s_[j][1] - m0);
            s_[j][2] = __expf(s_[j][2] - m1);
            s_[j][3] = __expf(s_[j][3] - m1);
            sum0 += s_[j][0] + s_[j][1];
            sum1 += s_[j][2] + s_[j][3];
        }
        sum0 += __shfl_xor_sync(0xffffffffu, sum0, 1);
        sum0 += __shfl_xor_sync(0xffffffffu, sum0, 2);
        sum1 += __shfl_xor_sync(0xffffffffu, sum1, 1);
        sum1 += __shfl_xor_sync(0xffffffffu, sum1, 2);
        l0 = l0 * corr0 + sum0;
        l1 = l1 * corr1 + sum1;
        #pragma unroll
        for (int n = 0; n < 8; n++) {
            acc_o[n][0] *= corr0; acc_o[n][1] *= corr0;
            acc_o[n][2] *= corr1; acc_o[n][3] *= corr1;
        }
        // ---- O += P @ V  (V [kv, d] via ldmatrix.trans) ----
        #pragma unroll
        for (int t = 0; t < 4; t++) {
            u32 pah[4], pal[4];
            split2(s_[2 * t][0],     s_[2 * t][1],     pah[0], pal[0]);
            split2(s_[2 * t][2],     s_[2 * t][3],     pah[1], pal[1]);
            split2(s_[2 * t + 1][0], s_[2 * t + 1][1], pah[2], pal[2]);
            split2(s_[2 * t + 1][2], s_[2 * t + 1][3], pah[3], pal[3]);
            int vrow = t * 16 + (lane & 15);
            #pragma unroll
            for (int n = 0; n < 8; n++) {
                u32 bh2[2], bl2[2];
                ldsm_x2t(bh2, s2u(&sVh[vrow * FSTR + n * 8]));
                ldsm_x2t(bl2, s2u(&sVl[vrow * FSTR + n * 8]));
                mma16816(acc_o[n], pah, bh2);
                mma16816(acc_o[n], pah, bl2);
                mma16816(acc_o[n], pal, bh2);
            }
        }
        __syncthreads();
    }

    // ---- epilogue: normalize + hi/lo write (O row stride EE) ----
    float inv0 = 1.f / l0, inv1 = 1.f / l1;
    int r0 = q0 + w * 16 + grp;
    #pragma unroll
    for (int n = 0; n < 8; n++) {
        int col = h * DD + n * 8 + qd * 2;
        {
            long off = (long)b * SS * EE + (long)r0 * EE + col;
            u32 hp, lp;
            split2(acc_o[n][0] * inv0, acc_o[n][1] * inv0, hp, lp);
            *(u32*)&Oh[off] = hp;
            *(u32*)&Ol[off] = lp;
        }
        {
            long off = (long)b * SS * EE + (long)(r0 + 8) * EE + col;
            u32 hp, lp;
            split2(acc_o[n][2] * inv1, acc_o[n][3] * inv1, hp, lp);
            *(u32*)&Oh[off] = hp;
            *(u32*)&Ol[off] = lp;
        }
    }
}

// ------------------------- elementwise hi/lo split -------------------------
__global__ void split_k(const float* __restrict__ x, bf* __restrict__ h,
                        bf* __restrict__ l, long n)
{
    long i = ((long)blockIdx.x * blockDim.x + threadIdx.x) * 4;
    if (i >= n) return;
    float4 v = *(const float4*)(x + i);
    u32 hp[2], lp[2];
    split2(v.x, v.y, hp[0], lp[0]);
    split2(v.z, v.w, hp[1], lp[1]);
    *(uint2*)(h + i) = make_uint2(hp[0], hp[1]);
    *(uint2*)(l + i) = make_uint2(lp[0], lp[1]);
}

// ------------------------- transpose + split (weights preprocessing) -------------------------
__global__ void tsplit_k(const float* __restrict__ src, bf* __restrict__ h,
                         bf* __restrict__ l,
                         int lds, int ldd, long sB, long sH, long dB, long dH, int nh)
{
    __shared__ float sm[32][33];
    int z = blockIdx.z;
    int bb = z / nh, hh = z - bb * nh;
    src += bb * sB + hh * sH;
    h   += bb * dB + hh * dH;
    l   += bb * dB + hh * dH;
    int r0 = blockIdx.y * 32, c0 = blockIdx.x * 32;
    int tx = threadIdx.x, ty = threadIdx.y;
    #pragma unroll
    for (int i = 0; i < 4; i++)
        sm[ty + 8 * i][tx] = src[(long)(r0 + ty + 8 * i) * lds + c0 + tx];
    __syncthreads();
    #pragma unroll
    for (int i = 0; i < 4; i++) {
        int n = c0 + ty + 8 * i, k = r0 + tx;
        float v = sm[tx][ty + 8 * i];
        bf hv = __float2bfloat16(v);
        bf lv = __float2bfloat16(v - __bfloat162float(hv));
        h[(long)n * ldd + k] = hv;
        l[(long)n * ldd + k] = lv;
    }
}

// ------------------------- bias packing -------------------------
__global__ void packb_k(const float* __restrict__ qb, const float* __restrict__ kb,
                        const float* __restrict__ vb, float* __restrict__ dst)
{
    int i = blockIdx.y;
    int t = blockIdx.x * 256 + threadIdx.x;   // 0..511
    dst[i * NQKV + t]        = qb[i * EE + t];
    dst[i * NQKV + 512 + t]  = kb[i * EE + t];
    dst[i * NQKV + 1024 + t] = vb[i * EE + t];
}

// ------------------------- residual + layernorm (+ optional split out) -------------------------
__global__ void ln_k(const float* __restrict__ x, const float* __restrict__ res,
                     const float* __restrict__ gamma, const float* __restrict__ beta,
                     float* __restrict__ out,
                     bf* __restrict__ oh = nullptr,
                     bf* __restrict__ ol = nullptr)
{
    long row = blockIdx.x;
    int t = threadIdx.x;
    float4 v = ((const float4*)(x + row * EE))[t];
    if (res) {
        float4 r = ((const float4*)(res + row * EE))[t];
        v.x += r.x; v.y += r.y; v.z += r.z; v.w += r.w;
    }
    float s = v.x + v.y + v.z + v.w;
    float q = v.x * v.x + v.y * v.y + v.z * v.z + v.w * v.w;
    #pragma unroll
    for (int o = 16; o; o >>= 1) {
        s += __shfl_xor_sync(0xffffffffu, s, o);
        q += __shfl_xor_sync(0xffffffffu, q, o);
    }
    __shared__ float shS[4], shQ[4];
    int w = t >> 5;
    if ((t & 31) == 0) { shS[w] = s; shQ[w] = q; }
    __syncthreads();
    s = shS[0] + shS[1] + shS[2] + shS[3];
    q = shQ[0] + shQ[1] + shQ[2] + shQ[3];
    float mean = s * (1.f / EE);
    float var = q * (1.f / EE) - mean * mean;
    float rstd = rsqrtf(var + 1e-5f);
    float4 g = ((const float4*)gamma)[t];
    float4 b = ((const float4*)beta)[t];
    float4 o;
    o.x = (v.x - mean) * rstd * g.x + b.x;
    o.y = (v.y - mean) * rstd * g.y + b.y;
    o.z = (v.z - mean) * rstd * g.z + b.z;
    o.w = (v.w - mean) * rstd * g.w + b.w;
    ((float4*)(out + row * EE))[t] = o;
    if (oh) {
        u32 hp[2], lp[2];
        split2(o.x, o.y, hp[0], lp[0]);
        split2(o.z, o.w, hp[1], lp[1]);
        *(uint2*)(oh + row * EE + t * 4) = make_uint2(hp[0], hp[1]);
        *(uint2*)(ol + row * EE + t * 4) = make_uint2(lp[0], lp[1]);
    }
}

// ------------------------- gate + mix -------------------------
__global__ void gate_mix_k(const float* __restrict__ x, const float* __restrict__ cr,
                           const float* __restrict__ gw, const float* __restrict__ gb,
                           float* __restrict__ out)
{
    long row = blockIdx.x;
    int t = threadIdx.x;
    float4 xv = ((const float4*)(x + row * EE))[t];
    float4 cv = ((const float4*)(cr + row * EE))[t];
    int k0 = t * 4;
    float l0 = 0.f, l1 = 0.f;
    float xs[4] = {xv.x, xv.y, xv.z, xv.w};
    float cs[4] = {cv.x, cv.y, cv.z, cv.w};
    #pragma unroll
    for (int e = 0; e < 4; e++) {
        int k = k0 + e;
        l0 += xs[e] * gw[k * 2 + 0] + cs[e] * gw[(EE + k) * 2 + 0];
        l1 += xs[e] * gw[k * 2 + 1] + cs[e] * gw[(EE + k) * 2 + 1];
    }
    #pragma unroll
    for (int o = 16; o; o >>= 1) {
        l0 += __shfl_xor_sync(0xffffffffu, l0, o);
        l1 += __shfl_xor_sync(0xffffffffu, l1, o);
    }
    __shared__ float sh0[4], sh1[4];
    int w = t >> 5;
    if ((t & 31) == 0) { sh0[w] = l0; sh1[w] = l1; }
    __syncthreads();
    l0 = sh0[0] + sh0[1] + sh0[2] + sh0[3] + gb[0];
    l1 = sh1[0] + sh1[1] + sh1[2] + sh1[3] + gb[1];
    float m = fmaxf(l0, l1);
    float e0 = __expf(l0 - m), e1 = __expf(l1 - m);
    float g0 = e0 / (e0 + e1), g1 = e1 / (e0 + e1);
    float4 o;
    o.x = xv.x * g0 + cv.x * g1;
    o.y = xv.y * g0 + cv.y * g1;
    o.z = xv.z * g0 + cv.z * g1;
    o.w = xv.w * g0 + cv.w * g1;
    ((float4*)(out + row * EE))[t] = o;
}

// ------------------------- host orchestration -------------------------
static float* sym(const void* s) { void* p = nullptr; cudaGetSymbolAddress(&p, s); return (float*)p; }
static bf* symb(const void* s)   { void* p = nullptr; cudaGetSymbolAddress(&p, s); return (bf*)p; }

#define SMEM64 ((2 * 128 * 40 + 2 * 128 * 40) * 2 * 2)   // 81920 B

struct Weights {
    const float* ob;
    const unsigned* temp;
};

// generic dense: C = A @ B^T + bias, explicit ldc (col-offset via pointer)
static void gemm_f32(const bf* ah, const bf* al, const bf* bh, const bf* bl,
                     const float* bias, float* C, int M, int N, int K) {
    dim3 grid(N / 128, M / 128, 1);
    gemm_mma<64, 0, false><<<grid, 256, SMEM64>>>(ah, al, bh, bl, bias, C, nullptr, nullptr,
        K, K, K, N, 0, 0, 0, 0, 0, 0, 1, 1.f, nullptr);
}
static void gemm_sp_ld(const bf* ah, const bf* al, const bf* bh, const bf* bl,
                       const float* bias, bf* Ch, bf* Cl, int M, int N, int K, int ldc, bool gelu) {
    dim3 grid(N / 128, M / 128, 1);
    if (gelu)
        gemm_mma<64, 2, true><<<grid, 256, SMEM64>>>(ah, al, bh, bl, bias, nullptr, Ch, Cl,
            K, K, K, ldc, 0, 0, 0, 0, 0, 0, 1, 1.f, nullptr);
    else
        gemm_mma<64, 2, false><<<grid, 256, SMEM64>>>(ah, al, bh, bl, bias, nullptr, Ch, Cl,
            K, K, K, ldc, 0, 0, 0, 0, 0, 0, 1, 1.f, nullptr);
}

static void run_attn(int i, const bf* qih, const bf* qil, const bf* kih, const bf* kil,
                     bool self, const Weights& W, float* out)
{
    bf *qkvh = symb(g_qkvh), *qkvl = symb(g_qkvl);
    bf *atth = symb(g_atth), *attl = symb(g_attl);
    const float* qkvb = sym(g_qkvb) + (long)i * NQKV;
    long wbase = (long)i * NQKV * EE;
    long wo = (long)i * EE * EE;
    long bo = (long)i * EE;

    if (self) {
        gemm_sp_ld(qih, qil, symb(g_wqkvh) + wbase, symb(g_wqkvl) + wbase,
                   qkvb, qkvh, qkvl, NTOK, NQKV, EE, NQKV, false);
    } else {
        gemm_sp_ld(qih, qil, symb(g_wqkvh) + wbase, symb(g_wqkvl) + wbase,
                   qkvb, qkvh, qkvl, NTOK, 512, EE, NQKV, false);
        gemm_sp_ld(kih, kil, symb(g_wqkvh) + wbase + (long)512 * EE,
                   symb(g_wqkvl) + wbase + (long)512 * EE,
                   qkvb + 512, qkvh + 512, qkvl + 512, NTOK, 1024, EE, NQKV, false);
    }

    flash_k<<<dim3(SS / 128, NB), 256, FSMEM>>>(qkvh, qkvl, atth, attl, W.temp);

    gemm_f32(atth, attl, symb(g_owth) + wo, symb(g_owtl) + wo, W.ob + bo, out, NTOK, EE, EE);
}

extern "C" void kernel_launch(void* const* d_in, const int* in_sizes, int n_in,
                              void* d_out, int out_size)
{
    const float* body_feats = (const float*)d_in[0];
    const float* limb_feats = (const float*)d_in[1];
    const float* attn_qw = (const float*)d_in[2];
    const float* attn_qb = (const float*)d_in[3];
    const float* attn_kw = (const float*)d_in[4];
    const float* attn_kb = (const float*)d_in[5];
    const float* attn_vw = (const float*)d_in[6];
    const float* attn_vb = (const float*)d_in[7];
    const float* attn_ow = (const float*)d_in[8];
    const float* attn_ob = (const float*)d_in[9];
    const float* ffn_w1 = (const float*)d_in[10];
    const float* ffn_b1 = (const float*)d_in[11];
    const float* ffn_w2 = (const float*)d_in[12];
    const float* ffn_b2 = (const float*)d_in[13];
    const float* nsc = (const float*)d_in[14];
    const float* nbi = (const float*)d_in[15];
    const float* gw = (const float*)d_in[16];
    const float* gb = (const float*)d_in[17];

    Weights W;
    W.ob = attn_ob;
    W.temp = (const unsigned*)d_in[18];

    cudaFuncSetAttribute(gemm_mma<64, 0, false>, cudaFuncAttributeMaxDynamicSharedMemorySize, SMEM64);
    cudaFuncSetAttribute(gemm_mma<64, 2, false>, cudaFuncAttributeMaxDynamicSharedMemorySize, SMEM64);
    cudaFuncSetAttribute(gemm_mma<64, 2, true>,  cudaFuncAttributeMaxDynamicSharedMemorySize, SMEM64);
    cudaFuncSetAttribute(flash_k, cudaFuncAttributeMaxDynamicSharedMemorySize, FSMEM);

    float* out = (float*)d_out;
    float* out_body = out;
    float* out_limb = out + TOKE;

    float* tmp  = sym(g_tmp);
    float* body = sym(g_body);
    float* limb = sym(g_limb);
    float* crB  = sym(g_crossB);
    float* crL  = sym(g_crossL);
    float* mixB = sym(g_mixB);
    float* mixL = sym(g_mixL);
    float* ffn  = sym(g_ffn);
    bf *bfh = symb(g_bfh), *bfl = symb(g_bfl);
    bf *lfh = symb(g_lfh), *lfl = symb(g_lfl);
    bf *bodyh = symb(g_bodyh), *bodyl = symb(g_bodyl);
    bf *limbh = symb(g_limbh), *limbl = symb(g_limbl);
    bf *hidh = symb(g_hidh), *hidl = symb(g_hidl);

    // ---- preprocessing: packed QKV weights + bias, O/FFN weights ----
    {
        dim3 blk(32, 8);
        dim3 gE(EE / 32, EE / 32, 4);
        bf *wqh = symb(g_wqkvh), *wql = symb(g_wqkvl);
        tsplit_k<<<gE, blk>>>(attn_qw, wqh, wql, EE, EE,
                              (long)EE * EE, 0, (long)NQKV * EE, 0, 1);
        tsplit_k<<<gE, blk>>>(attn_kw, wqh + (long)512 * EE, wql + (long)512 * EE, EE, EE,
                              (long)EE * EE, 0, (long)NQKV * EE, 0, 1);
        tsplit_k<<<gE, blk>>>(attn_vw, wqh + (long)1024 * EE, wql + (long)1024 * EE, EE, EE,
                              (long)EE * EE, 0, (long)NQKV * EE, 0, 1);
        tsplit_k<<<gE, blk>>>(attn_ow, symb(g_owth), symb(g_owtl), EE, EE,
                              (long)EE * EE, 0, (long)EE * EE, 0, 1);
        dim3 g1(4 * EE / 32, EE / 32, 2);
        tsplit_k<<<g1, blk>>>(ffn_w1, symb(g_w1th), symb(g_w1tl), 4 * EE, EE,
                              (long)EE * 4 * EE, 0, (long)EE * 4 * EE, 0, 1);
        dim3 g2(EE / 32, 4 * EE / 32, 2);
        tsplit_k<<<g2, blk>>>(ffn_w2, symb(g_w2th), symb(g_w2tl), EE, 4 * EE,
                              (long)EE * 4 * EE, 0, (long)EE * 4 * EE, 0, 1);
        packb_k<<<dim3(2, 4), 256>>>(attn_qb, attn_kb, attn_vb, sym(g_qkvb));
    }

    // ---- input splits (once) ----
    split_k<<<(unsigned)(TOKE / 1024), 256>>>(body_feats, bfh, bfl, TOKE);
    split_k<<<(unsigned)(TOKE / 1024), 256>>>(limb_feats, lfh, lfl, TOKE);

    // ---- self attentions + norm1 (split out for cross attn) ----
    run_attn(0, bfh, bfl, bfh, bfl, true, W, tmp);
    ln_k<<<NTOK, 128>>>(body_feats, tmp, nsc + 0 * EE, nbi + 0 * EE, body, bodyh, bodyl);

    run_attn(1, lfh, lfl, lfh, lfl, true, W, tmp);
    ln_k<<<NTOK, 128>>>(limb_feats, tmp, nsc + 3 * EE, nbi + 3 * EE, limb, limbh, limbl);

    // ---- cross attentions ----
    run_attn(2, bodyh, bodyl, limbh, limbl, false, W, crB);
    run_attn(3, limbh, limbl, bodyh, bodyl, false, W, crL);

    // ---- gates + norm2(body) on both streams (faithful to reference) ----
    gate_mix_k<<<NTOK, 128>>>(body, crB, gw, gb, mixB);
    gate_mix_k<<<NTOK, 128>>>(limb, crL, gw, gb, mixL);
    ln_k<<<NTOK, 128>>>(mixB, nullptr, nsc + 1 * EE, nbi + 1 * EE, body, bodyh, bodyl);
    ln_k<<<NTOK, 128>>>(mixL, nullptr, nsc + 1 * EE, nbi + 1 * EE, limb, limbh, limbl);

    // ---- FFN body ----
    gemm_sp_ld(bodyh, bodyl, symb(g_w1th), symb(g_w1tl), ffn_b1, hidh, hidl,
               NTOK, 4 * EE, EE, 4 * EE, true);
    gemm_f32(hidh, hidl, symb(g_w2th), symb(g_w2tl), ffn_b2, ffn, NTOK, EE, 4 * EE);
    ln_k<<<NTOK, 128>>>(body, ffn, nsc + 2 * EE, nbi + 2 * EE, out_body);

    // ---- FFN limb ----
    gemm_sp_ld(limbh, limbl, symb(g_w1th) + (long)4 * EE * EE, symb(g_w1tl) + (long)4 * EE * EE,
               ffn_b1 + 4 * EE, hidh, hidl, NTOK, 4 * EE, EE, 4 * EE, true);
    gemm_f32(hidh, hidl, symb(g_w2th) + (long)4 * EE * EE, symb(g_w2tl) + (long)4 * EE * EE,
             ffn_b2 + EE, ffn, NTOK, EE, 4 * EE);
    ln_k<<<NTOK, 128>>>(limb, ffn, nsc + 5 * EE, nbi + 5 * EE, out_limb);
}

// round 11
// speedup vs baseline: 3.4148x; 1.0459x over previous
#include <cuda_runtime.h>
#include <cuda_bf16.h>
#include <math.h>

typedef unsigned int u32;
typedef unsigned long long u64;
typedef __nv_bfloat16 bf;

#define BB 4
#define SS 1024
#define EE 512
#define NHH 8
#define DD 64
#define NTOK (BB*SS)          // 4096
#define TOKE ((long)NTOK*EE)  // 2,097,152
#define NB (BB*NHH)           // 32
#define NQKV 1536

// ------------------------- fp32 scratch ([2] = body, limb) -------------------------
__device__ float g_tmp[2*NTOK*EE];
__device__ float g_bl[2*NTOK*EE];
__device__ float g_cross[2*NTOK*EE];
__device__ float g_mix[2*NTOK*EE];
__device__ float g_ffn[2*NTOK*EE];
__device__ float g_qkvb[4*NQKV];

// ------------------------- bf16 split scratch (16B aligned) -------------------------
__device__ __align__(16) bf g_xh[2*NTOK*EE], g_xl[2*NTOK*EE];       // raw input splits
__device__ __align__(16) bf g_s1h[2*NTOK*EE], g_s1l[2*NTOK*EE];     // ln outputs
__device__ __align__(16) bf g_qkvh[(long)2*NTOK*NQKV], g_qkvl[(long)2*NTOK*NQKV];
__device__ __align__(16) bf g_atth[2*NTOK*EE], g_attl[2*NTOK*EE];
__device__ __align__(16) bf g_hidh[(long)2*NTOK*4*EE], g_hidl[(long)2*NTOK*4*EE];
__device__ __align__(16) bf g_wqkvh[(long)4*NQKV*EE], g_wqkvl[(long)4*NQKV*EE];
__device__ __align__(16) bf g_owth[4*EE*EE], g_owtl[4*EE*EE];
__device__ __align__(16) bf g_w1th[(long)2*EE*4*EE], g_w1tl[(long)2*EE*4*EE];
__device__ __align__(16) bf g_w2th[(long)2*EE*4*EE], g_w2tl[(long)2*EE*4*EE];

// ------------------------- asm helpers -------------------------
__device__ __forceinline__ u32 s2u(const void* p) {
    u32 a;
    asm("{ .reg .u64 t; cvta.to.shared.u64 t, %1; cvt.u32.u64 %0, t; }" : "=r"(a) : "l"(p));
    return a;
}
__device__ __forceinline__ void cpa16(u32 saddr, const void* g) {
    asm volatile("cp.async.cg.shared.global [%0], [%1], 16;" :: "r"(saddr), "l"(g));
}
__device__ __forceinline__ void cpcommit() { asm volatile("cp.async.commit_group;"); }
__device__ __forceinline__ void cpwait1()  { asm volatile("cp.async.wait_group 1;"); }
__device__ __forceinline__ void cpwait0()  { asm volatile("cp.async.wait_group 0;"); }

__device__ __forceinline__ void ldsm_x4(u32 r[4], u32 addr) {
    asm volatile("ldmatrix.sync.aligned.m8n8.x4.shared.b16 {%0,%1,%2,%3}, [%4];"
                 : "=r"(r[0]), "=r"(r[1]), "=r"(r[2]), "=r"(r[3]) : "r"(addr));
}
__device__ __forceinline__ void ldsm_x2(u32 r[2], u32 addr) {
    asm volatile("ldmatrix.sync.aligned.m8n8.x2.shared.b16 {%0,%1}, [%2];"
                 : "=r"(r[0]), "=r"(r[1]) : "r"(addr));
}
__device__ __forceinline__ void ldsm_x2t(u32 r[2], u32 addr) {
    asm volatile("ldmatrix.sync.aligned.m8n8.x2.trans.shared.b16 {%0,%1}, [%2];"
                 : "=r"(r[0]), "=r"(r[1]) : "r"(addr));
}
__device__ __forceinline__ void mma16816(float c[4], const u32 a[4], const u32 b[2]) {
    asm volatile(
        "mma.sync.aligned.m16n8k16.row.col.f32.bf16.bf16.f32 "
        "{%0,%1,%2,%3}, {%4,%5,%6,%7}, {%8,%9}, {%0,%1,%2,%3};"
        : "+f"(c[0]), "+f"(c[1]), "+f"(c[2]), "+f"(c[3])
        : "r"(a[0]), "r"(a[1]), "r"(a[2]), "r"(a[3]), "r"(b[0]), "r"(b[1]));
}
__device__ __forceinline__ void split2(float x, float y, u32& hp, u32& lp) {
    bf hx = __float2bfloat16(x), hy = __float2bfloat16(y);
    bf lx = __float2bfloat16(x - __bfloat162float(hx));
    bf ly = __float2bfloat16(y - __bfloat162float(hy));
    hp = (u32)__bfloat16_as_ushort(hx) | ((u32)__bfloat16_as_ushort(hy) << 16);
    lp = (u32)__bfloat16_as_ushort(lx) | ((u32)__bfloat16_as_ushort(ly) << 16);
}

// ------------------------- bf16-split tensor-core GEMM, cp.async pipelined -----
// Per batch z: C[i,j] = act(sum_l A[i,l]*B[j,l] + bias[j]); strides aB/bB/cB/biasB per z.
// OMODE: 0 = fp32 C; 2 = bf16 hi/lo (Ch, Cl).
template<int WN, int OMODE, bool GELU>
__global__ void __launch_bounds__(256) gemm_mma(
    const bf* __restrict__ Ah, const bf* __restrict__ Al,
    const bf* __restrict__ Bh, const bf* __restrict__ Bl,
    const float* __restrict__ bias, float* __restrict__ C,
    bf* __restrict__ Ch, bf* __restrict__ Cl,
    int K, int lda, int ldb, int ldc,
    long aB, long bB, long cB, long biasB)
{
    constexpr int BN = 2 * WN;
    constexpr int STR = 40;
    constexpr int ASZ = 128 * STR;
    constexpr int BSZ = BN * STR;
    constexpr int STAGE = 2 * ASZ + 2 * BSZ;

    extern __shared__ __align__(16) bf sm[];

    int z = blockIdx.z;
    Ah += z * aB;  Al += z * aB;
    Bh += z * bB;  Bl += z * bB;
    if (bias) bias += z * biasB;
    long coff = z * cB;

    int i0 = blockIdx.y * 128;
    int j0 = blockIdx.x * BN;
    int tid = threadIdx.x;
    int lane = tid & 31, wid = tid >> 5;
    int wm = wid & 3, wn = wid >> 2;

    float acc[2][WN / 8][4] = {};
    const int nch = K / 32;

    auto load_stage = [&](int c, int s) {
        long kc = (long)c * 32;
        u32 base = s2u(sm + s * STAGE);
        #pragma unroll
        for (int t = 0; t < 2; t++) {
            int idx = tid + t * 256;
            int r = idx >> 2, sg = idx & 3;
            long go = (long)(i0 + r) * lda + kc + sg * 8;
            u32 so = (u32)(r * STR + sg * 8) * 2;
            cpa16(base + so, Ah + go);
            cpa16(base + ASZ * 2 + so, Al + go);
        }
        #pragma unroll
        for (int t = 0; t < BN / 64; t++) {
            int idx = tid + t * 256;
            int r = idx >> 2, sg = idx & 3;
            long go = (long)(j0 + r) * ldb + kc + sg * 8;
            u32 so = (u32)(r * STR + sg * 8) * 2;
            cpa16(base + 4 * ASZ + so, Bh + go);
            cpa16(base + 4 * ASZ + 2 * BSZ + so, Bl + go);
        }
    };

    load_stage(0, 0);
    cpcommit();

    for (int c = 0; c < nch; c++) {
        if (c + 1 < nch) {
            load_stage(c + 1, (c + 1) & 1);
            cpcommit();
            cpwait1();
        } else {
            cpwait0();
        }
        __syncthreads();

        const bf* sAh = sm + (c & 1) * STAGE;
        const bf* sAl = sAh + ASZ;
        const bf* sBh = sAl + ASZ;
        const bf* sBl = sBh + BSZ;

        #pragma unroll
        for (int ks = 0; ks < 2; ks++) {
            u32 afh[2][4], afl[2][4];
            #pragma unroll
            for (int mt = 0; mt < 2; mt++) {
                int row = wm * 32 + mt * 16 + (lane & 15);
                int col = ks * 16 + (lane >> 4) * 8;
                ldsm_x4(afh[mt], s2u(&sAh[row * STR + col]));
                ldsm_x4(afl[mt], s2u(&sAl[row * STR + col]));
            }
            #pragma unroll
            for (int nt = 0; nt < WN / 8; nt++) {
                int brow = wn * WN + nt * 8 + (lane & 7);
                int bcol = ks * 16 + ((lane >> 3) & 1) * 8;
                u32 bh[2], bl[2];
                ldsm_x2(bh, s2u(&sBh[brow * STR + bcol]));
                ldsm_x2(bl, s2u(&sBl[brow * STR + bcol]));
                #pragma unroll
                for (int mt = 0; mt < 2; mt++) {
                    mma16816(acc[mt][nt], afh[mt], bh);
                    mma16816(acc[mt][nt], afh[mt], bl);
                    mma16816(acc[mt][nt], afl[mt], bh);
                }
            }
        }
        __syncthreads();
    }

    int grp = lane >> 2, qd = lane & 3;
    #pragma unroll
    for (int mt = 0; mt < 2; mt++) {
        #pragma unroll
        for (int nt = 0; nt < WN / 8; nt++) {
            int n = j0 + wn * WN + nt * 8 + qd * 2;
            float b0 = 0.f, b1 = 0.f;
            if (bias) { b0 = bias[n]; b1 = bias[n + 1]; }
            #pragma unroll
            for (int rh = 0; rh < 2; rh++) {
                int m = i0 + wm * 32 + mt * 16 + grp + rh * 8;
                float x = acc[mt][nt][rh * 2 + 0] + b0;
                float y = acc[mt][nt][rh * 2 + 1] + b1;
                if (GELU) {
                    x = 0.5f * x * (1.f + erff(x * 0.70710678118654752f));
                    y = 0.5f * y * (1.f + erff(y * 0.70710678118654752f));
                }
                long off = coff + (long)m * ldc + n;
                if (OMODE == 0) {
                    *(float2*)&C[off] = make_float2(x, y);
                } else {
                    u32 hp, lp;
                    split2(x, y, hp, lp);
                    *(u32*)&Ch[off] = hp;
                    *(u32*)&Cl[off] = lp;
                }
            }
        }
    }
}

// ------------------------- flash attention (packed QKV, 2 streams) -------------------------
// QKV: [stream][token][1536] (Q 0-511, K 512-1023, V 1024-1535). O: [stream][token][512].
#define KVT 64
#define FSTR 72
#define FQSZ (128 * FSTR)
#define FKSZ (KVT * FSTR)
#define FSTG (4 * FKSZ)
#define FSMEM ((2 * FQSZ + 2 * FSTG) * 2)   // 110,592 B

__global__ void __launch_bounds__(256) flash_k(
    const bf* __restrict__ QKVh, const bf* __restrict__ QKVl,
    bf* __restrict__ Oh, bf* __restrict__ Ol,
    const unsigned* __restrict__ tptr)
{
    extern __shared__ __align__(16) bf fsm[];
    bf* sQh = fsm;
    bf* sQl = fsm + FQSZ;
    bf* stg = fsm + 2 * FQSZ;

    int q0 = blockIdx.x * 128;
    int y = blockIdx.y;
    int strm = y >> 5;             // 0 / 1
    int z = y & 31;
    int b = z / NHH, h = z - b * NHH;
    long qbase = (long)strm * NTOK * NQKV + (long)b * SS * NQKV + h * DD;
    long obase = (long)strm * TOKE + (long)b * SS * EE;

    int tid = threadIdx.x, lane = tid & 31, w = tid >> 5;
    int grp = lane >> 2, qd = lane & 3;

    #pragma unroll
    for (int t = 0; t < 4; t++) {
        int idx = tid + t * 256;
        int r = idx >> 3, sg = idx & 7;
        long go = qbase + (long)(q0 + r) * NQKV + sg * 8;
        u32 so = (u32)(r * FSTR + sg * 8) * 2;
        cpa16(s2u(sQh) + so, QKVh + go);
        cpa16(s2u(sQl) + so, QKVl + go);
    }
    auto load_kv = [&](int c, int s) {
        bf* st = stg + s * FSTG;
        int kv0 = c * KVT;
        #pragma unroll
        for (int t = 0; t < 2; t++) {
            int idx = tid + t * 256;
            int r = idx >> 3, sg = idx & 7;
            u32 so = (u32)(r * FSTR + sg * 8) * 2;
            long gk = qbase + 512 + (long)(kv0 + r) * NQKV + sg * 8;
            cpa16(s2u(st) + so, QKVh + gk);
            cpa16(s2u(st + FKSZ) + so, QKVl + gk);
            long gv = qbase + 1024 + (long)(kv0 + r) * NQKV + sg * 8;
            cpa16(s2u(st + 2 * FKSZ) + so, QKVh + gv);
            cpa16(s2u(st + 3 * FKSZ) + so, QKVl + gv);
        }
    };
    load_kv(0, 0);
    cpcommit();

    float scl;
    {
        unsigned u = *tptr;
        float f = __uint_as_float(u);
        float temp = (f > 1e-6f && f < 1e6f) ? f : (float)(int)u;
        scl = 0.125f / temp;
    }

    float m0 = -1e30f, m1 = -1e30f, l0 = 0.f, l1 = 0.f;
    float acc_o[8][4] = {};

    const int NT = SS / KVT;
    for (int c = 0; c < NT; c++) {
        if (c + 1 < NT) { load_kv(c + 1, (c + 1) & 1); cpcommit(); cpwait1(); }
        else cpwait0();
        __syncthreads();
        bf* st = stg + (c & 1) * FSTG;
        bf* sKh = st;
        bf* sKl = st + FKSZ;
        bf* sVh = st + 2 * FKSZ;
        bf* sVl = st + 3 * FKSZ;

        float s_[8][4] = {};
        #pragma unroll
        for (int t = 0; t < 4; t++) {
            u32 ah4[4], al4[4];
            int arow = w * 16 + (lane & 15);
            int acol = t * 16 + (lane >> 4) * 8;
            ldsm_x4(ah4, s2u(&sQh[arow * FSTR + acol]));
            ldsm_x4(al4, s2u(&sQl[arow * FSTR + acol]));
            #pragma unroll
            for (int j = 0; j < 8; j++) {
                int brow = j * 8 + (lane & 7);
                int bcol = t * 16 + ((lane >> 3) & 1) * 8;
                u32 bh2[2], bl2[2];
                ldsm_x2(bh2, s2u(&sKh[brow * FSTR + bcol]));
                ldsm_x2(bl2, s2u(&sKl[brow * FSTR + bcol]));
                mma16816(s_[j], ah4, bh2);
                mma16816(s_[j], ah4, bl2);
                mma16816(s_[j], al4, bh2);
            }
        }
        float t0 = -1e30f, t1 = -1e30f;
        #pragma unroll
        for (int j = 0; j < 8; j++) {
            s_[j][0] *= scl; s_[j][1] *= scl; s_[j][2] *= scl; s_[j][3] *= scl;
            t0 = fmaxf(t0, fmaxf(s_[j][0], s_[j][1]));
            t1 = fmaxf(t1, fmaxf(s_[j][2], s_[j][3]));
        }
        t0 = fmaxf(t0, __shfl_xor_sync(0xffffffffu, t0, 1));
        t0 = fmaxf(t0, __shfl_xor_sync(0xffffffffu, t0, 2));
        t1 = fmaxf(t1, __shfl_xor_sync(0xffffffffu, t1, 1));
        t1 = fmaxf(t1, __shfl_xor_sync(0xffffffffu, t1, 2));
        float nm0 = fmaxf(m0, t0), nm1 = fmaxf(m1, t1);
        float corr0 = __expf(m0 - nm0), corr1 = __expf(m1 - nm1);
        m0 = nm0; m1 = nm1;
        float sum0 = 0.f, sum1 = 0.f;
        #pragma unroll
        for (int j = 0; j < 8; j++) {
            s_[j][0] = __expf(s_[j][0] - m0);
            s_[j][1] = __expf(s_[j][1] - m0);
            s_[j][2] = __expf(s_[j][2] - m1);
            s_[j][3] = __expf(s_[j][3] - m1);
            sum0 += s_[j][0] + s_[j][1];
            sum1 += s_[j][2] + s_[j][3];
        }
        sum0 += __shfl_xor_sync(0xffffffffu, sum0, 1);
        sum0 += __shfl_xor_sync(0xffffffffu, sum0, 2);
        sum1 += __shfl_xor_sync(0xffffffffu, sum1, 1);
        sum1 += __shfl_xor_sync(0xffffffffu, sum1, 2);
        l0 = l0 * corr0 + sum0;
        l1 = l1 * corr1 + sum1;
        #pragma unroll
        for (int n = 0; n < 8; n++) {
            acc_o[n][0] *= corr0; acc_o[n][1] *= corr0;
            acc_o[n][2] *= corr1; acc_o[n][3] *= corr1;
        }
        #pragma unroll
        for (int t = 0; t < 4; t++) {
            u32 pah[4], pal[4];
            split2(s_[2 * t][0],     s_[2 * t][1],     pah[0], pal[0]);
            split2(s_[2 * t][2],     s_[2 * t][3],     pah[1], pal[1]);
            split2(s_[2 * t + 1][0], s_[2 * t + 1][1], pah[2], pal[2]);
            split2(s_[2 * t + 1][2], s_[2 * t + 1][3], pah[3], pal[3]);
            int vrow = t * 16 + (lane & 15);
            #pragma unroll
            for (int n = 0; n < 8; n++) {
                u32 bh2[2], bl2[2];
                ldsm_x2t(bh2, s2u(&sVh[vrow * FSTR + n * 8]));
                ldsm_x2t(bl2, s2u(&sVl[vrow * FSTR + n * 8]));
                mma16816(acc_o[n], pah, bh2);
                mma16816(acc_o[n], pah, bl2);
                mma16816(acc_o[n], pal, bh2);
            }
        }
        __syncthreads();
    }

    float inv0 = 1.f / l0, inv1 = 1.f / l1;
    int r0 = q0 + w * 16 + grp;
    #pragma unroll
    for (int n = 0; n < 8; n++) {
        int col = h * DD + n * 8 + qd * 2;
        {
            long off = obase + (long)r0 * EE + col;
            u32 hp, lp;
            split2(acc_o[n][0] * inv0, acc_o[n][1] * inv0, hp, lp);
            *(u32*)&Oh[off] = hp;
            *(u32*)&Ol[off] = lp;
        }
        {
            long off = obase + (long)(r0 + 8) * EE + col;
            u32 hp, lp;
            split2(acc_o[n][2] * inv1, acc_o[n][3] * inv1, hp, lp);
            *(u32*)&Oh[off] = hp;
            *(u32*)&Ol[off] = lp;
        }
    }
}

// ------------------------- elementwise hi/lo split -------------------------
__global__ void split_k(const float* __restrict__ x, bf* __restrict__ h,
                        bf* __restrict__ l, long n)
{
    long i = ((long)blockIdx.x * blockDim.x + threadIdx.x) * 4;
    if (i >= n) return;
    float4 v = *(const float4*)(x + i);
    u32 hp[2], lp[2];
    split2(v.x, v.y, hp[0], lp[0]);
    split2(v.z, v.w, hp[1], lp[1]);
    *(uint2*)(h + i) = make_uint2(hp[0], hp[1]);
    *(uint2*)(l + i) = make_uint2(lp[0], lp[1]);
}

// ------------------------- transpose + split (weights preprocessing) -------------------------
__global__ void tsplit_k(const float* __restrict__ src, bf* __restrict__ h,
                         bf* __restrict__ l,
                         int lds, int ldd, long sB, long sH, long dB, long dH, int nh)
{
    __shared__ float sm[32][33];
    int z = blockIdx.z;
    int bb = z / nh, hh = z - bb * nh;
    src += bb * sB + hh * sH;
    h   += bb * dB + hh * dH;
    l   += bb * dB + hh * dH;
    int r0 = blockIdx.y * 32, c0 = blockIdx.x * 32;
    int tx = threadIdx.x, ty = threadIdx.y;
    #pragma unroll
    for (int i = 0; i < 4; i++)
        sm[ty + 8 * i][tx] = src[(long)(r0 + ty + 8 * i) * lds + c0 + tx];
    __syncthreads();
    #pragma unroll
    for (int i = 0; i < 4; i++) {
        int n = c0 + ty + 8 * i, k = r0 + tx;
        float v = sm[tx][ty + 8 * i];
        bf hv = __float2bfloat16(v);
        bf lv = __float2bfloat16(v - __bfloat162float(hv));
        h[(long)n * ldd + k] = hv;
        l[(long)n * ldd + k] = lv;
    }
}

// ------------------------- bias packing -------------------------
__global__ void packb_k(const float* __restrict__ qb, const float* __restrict__ kb,
                        const float* __restrict__ vb, float* __restrict__ dst)
{
    int i = blockIdx.y;
    int t = blockIdx.x * 256 + threadIdx.x;
    dst[i * NQKV + t]        = qb[i * EE + t];
    dst[i * NQKV + 512 + t]  = kb[i * EE + t];
    dst[i * NQKV + 1024 + t] = vb[i * EE + t];
}

// ------------------------- residual + layernorm (+ optional split out) -------------------------
__global__ void ln_k(const float* __restrict__ x, const float* __restrict__ res,
                     const float* __restrict__ gamma, const float* __restrict__ beta,
                     float* __restrict__ out,
                     bf* __restrict__ oh = nullptr,
                     bf* __restrict__ ol = nullptr)
{
    long row = blockIdx.x;
    int t = threadIdx.x;
    float4 v = ((const float4*)(x + row * EE))[t];
    if (res) {
        float4 r = ((const float4*)(res + row * EE))[t];
        v.x += r.x; v.y += r.y; v.z += r.z; v.w += r.w;
    }
    float s = v.x + v.y + v.z + v.w;
    float q = v.x * v.x + v.y * v.y + v.z * v.z + v.w * v.w;
    #pragma unroll
    for (int o = 16; o; o >>= 1) {
        s += __shfl_xor_sync(0xffffffffu, s, o);
        q += __shfl_xor_sync(0xffffffffu, q, o);
    }
    __shared__ float shS[4], shQ[4];
    int w = t >> 5;
    if ((t & 31) == 0) { shS[w] = s; shQ[w] = q; }
    __syncthreads();
    s = shS[0] + shS[1] + shS[2] + shS[3];
    q = shQ[0] + shQ[1] + shQ[2] + shQ[3];
    float mean = s * (1.f / EE);
    float var = q * (1.f / EE) - mean * mean;
    float rstd = rsqrtf(var + 1e-5f);
    float4 g = ((const float4*)gamma)[t];
    float4 b = ((const float4*)beta)[t];
    float4 o;
    o.x = (v.x - mean) * rstd * g.x + b.x;
    o.y = (v.y - mean) * rstd * g.y + b.y;
    o.z = (v.z - mean) * rstd * g.z + b.z;
    o.w = (v.w - mean) * rstd * g.w + b.w;
    ((float4*)(out + row * EE))[t] = o;
    if (oh) {
        u32 hp[2], lp[2];
        split2(o.x, o.y, hp[0], lp[0]);
        split2(o.z, o.w, hp[1], lp[1]);
        *(uint2*)(oh + row * EE + t * 4) = make_uint2(hp[0], hp[1]);
        *(uint2*)(ol + row * EE + t * 4) = make_uint2(lp[0], lp[1]);
    }
}

// ------------------------- gate + mix -------------------------
__global__ void gate_mix_k(const float* __restrict__ x, const float* __restrict__ cr,
                           const float* __restrict__ gw, const float* __restrict__ gb,
                           float* __restrict__ out)
{
    long row = blockIdx.x;
    int t = threadIdx.x;
    float4 xv = ((const float4*)(x + row * EE))[t];
    float4 cv = ((const float4*)(cr + row * EE))[t];
    int k0 = t * 4;
    float l0 = 0.f, l1 = 0.f;
    float xs[4] = {xv.x, xv.y, xv.z, xv.w};
    float cs[4] = {cv.x, cv.y, cv.z, cv.w};
    #pragma unroll
    for (int e = 0; e < 4; e++) {
        int k = k0 + e;
        l0 += xs[e] * gw[k * 2 + 0] + cs[e] * gw[(EE + k) * 2 + 0];
        l1 += xs[e] * gw[k * 2 + 1] + cs[e] * gw[(EE + k) * 2 + 1];
    }
    #pragma unroll
    for (int o = 16; o; o >>= 1) {
        l0 += __shfl_xor_sync(0xffffffffu, l0, o);
        l1 += __shfl_xor_sync(0xffffffffu, l1, o);
    }
    __shared__ float sh0[4], sh1[4];
    int w = t >> 5;
    if ((t & 31) == 0) { sh0[w] = l0; sh1[w] = l1; }
    __syncthreads();
    l0 = sh0[0] + sh0[1] + sh0[2] + sh0[3] + gb[0];
    l1 = sh1[0] + sh1[1] + sh1[2] + sh1[3] + gb[1];
    float m = fmaxf(l0, l1);
    float e0 = __expf(l0 - m), e1 = __expf(l1 - m);
    float g0 = e0 / (e0 + e1), g1 = e1 / (e0 + e1);
    float4 o;
    o.x = xv.x * g0 + cv.x * g1;
    o.y = xv.y * g0 + cv.y * g1;
    o.z = xv.z * g0 + cv.z * g1;
    o.w = xv.w * g0 + cv.w * g1;
    ((float4*)(out + row * EE))[t] = o;
}

// ------------------------- host orchestration -------------------------
static float* sym(const void* s) { void* p = nullptr; cudaGetSymbolAddress(&p, s); return (float*)p; }
static bf* symb(const void* s)   { void* p = nullptr; cudaGetSymbolAddress(&p, s); return (bf*)p; }

#define SMEM64 ((2 * 128 * 40 + 2 * 128 * 40) * 2 * 2)   // 81920 B

// batched (z=2) dense GEMM wrappers
static void bg_f32(const bf* ah, const bf* al, const bf* bh, const bf* bl, long aB, long bB,
                   const float* bias, long biasB, float* C, long cB, int M, int N, int K, int ldc) {
    dim3 grid(N / 128, M / 128, 2);
    gemm_mma<64, 0, false><<<grid, 256, SMEM64>>>(ah, al, bh, bl, bias, C, nullptr, nullptr,
        K, K, K, ldc, aB, bB, cB, biasB);
}
static void bg_sp(const bf* ah, const bf* al, const bf* bh, const bf* bl, long aB, long bB,
                  const float* bias, long biasB, bf* Ch, bf* Cl, long cB,
                  int M, int N, int K, int ldc, bool gelu) {
    dim3 grid(N / 128, M / 128, 2);
    if (gelu)
        gemm_mma<64, 2, true><<<grid, 256, SMEM64>>>(ah, al, bh, bl, bias, nullptr, Ch, Cl,
            K, K, K, ldc, aB, bB, cB, biasB);
    else
        gemm_mma<64, 2, false><<<grid, 256, SMEM64>>>(ah, al, bh, bl, bias, nullptr, Ch, Cl,
            K, K, K, ldc, aB, bB, cB, biasB);
}

extern "C" void kernel_launch(void* const* d_in, const int* in_sizes, int n_in,
                              void* d_out, int out_size)
{
    const float* body_feats = (const float*)d_in[0];
    const float* limb_feats = (const float*)d_in[1];
    const float* attn_qw = (const float*)d_in[2];
    const float* attn_qb = (const float*)d_in[3];
    const float* attn_kw = (const float*)d_in[4];
    const float* attn_kb = (const float*)d_in[5];
    const float* attn_vw = (const float*)d_in[6];
    const float* attn_vb = (const float*)d_in[7];
    const float* attn_ow = (const float*)d_in[8];
    const float* attn_ob = (const float*)d_in[9];
    const float* ffn_w1 = (const float*)d_in[10];
    const float* ffn_b1 = (const float*)d_in[11];
    const float* ffn_w2 = (const float*)d_in[12];
    const float* ffn_b2 = (const float*)d_in[13];
    const float* nsc = (const float*)d_in[14];
    const float* nbi = (const float*)d_in[15];
    const float* gw = (const float*)d_in[16];
    const float* gb = (const float*)d_in[17];
    const unsigned* temp = (const unsigned*)d_in[18];

    cudaFuncSetAttribute(gemm_mma<64, 0, false>, cudaFuncAttributeMaxDynamicSharedMemorySize, SMEM64);
    cudaFuncSetAttribute(gemm_mma<64, 2, false>, cudaFuncAttributeMaxDynamicSharedMemorySize, SMEM64);
    cudaFuncSetAttribute(gemm_mma<64, 2, true>,  cudaFuncAttributeMaxDynamicSharedMemorySize, SMEM64);
    cudaFuncSetAttribute(flash_k, cudaFuncAttributeMaxDynamicSharedMemorySize, FSMEM);

    float* out = (float*)d_out;

    float* tmp  = sym(g_tmp);
    float* bl   = sym(g_bl);
    float* cross = sym(g_cross);
    float* mix  = sym(g_mix);
    float* ffn  = sym(g_ffn);
    bf *xh = symb(g_xh), *xl = symb(g_xl);
    bf *s1h = symb(g_s1h), *s1l = symb(g_s1l);
    bf *qkvh = symb(g_qkvh), *qkvl = symb(g_qkvl);
    bf *atth = symb(g_atth), *attl = symb(g_attl);
    bf *hidh = symb(g_hidh), *hidl = symb(g_hidl);
    bf *wqh = symb(g_wqkvh), *wql = symb(g_wqkvl);
    bf *owh = symb(g_owth), *owl = symb(g_owtl);
    bf *w1h = symb(g_w1th), *w1l = symb(g_w1tl);
    bf *w2h = symb(g_w2th), *w2l = symb(g_w2tl);
    const float* qkvb = sym(g_qkvb);

    const long QKV_B = (long)NTOK * NQKV;
    const long HID_B = (long)NTOK * 4 * EE;
    const long WQKV_B = (long)NQKV * EE;
    const long WEE_B = (long)EE * EE;
    const long WFF_B = (long)EE * 4 * EE;

    // ---- preprocessing ----
    {
        dim3 blk(32, 8);
        dim3 gE(EE / 32, EE / 32, 4);
        tsplit_k<<<gE, blk>>>(attn_qw, wqh, wql, EE, EE, WEE_B, 0, WQKV_B, 0, 1);
        tsplit_k<<<gE, blk>>>(attn_kw, wqh + (long)512 * EE, wql + (long)512 * EE, EE, EE,
                              WEE_B, 0, WQKV_B, 0, 1);
        tsplit_k<<<gE, blk>>>(attn_vw, wqh + (long)1024 * EE, wql + (long)1024 * EE, EE, EE,
                              WEE_B, 0, WQKV_B, 0, 1);
        tsplit_k<<<gE, blk>>>(attn_ow, owh, owl, EE, EE, WEE_B, 0, WEE_B, 0, 1);
        dim3 g1(4 * EE / 32, EE / 32, 2);
        tsplit_k<<<g1, blk>>>(ffn_w1, w1h, w1l, 4 * EE, EE, WFF_B, 0, WFF_B, 0, 1);
        dim3 g2(EE / 32, 4 * EE / 32, 2);
        tsplit_k<<<g2, blk>>>(ffn_w2, w2h, w2l, EE, 4 * EE, WFF_B, 0, WFF_B, 0, 1);
        packb_k<<<dim3(2, 4), 256>>>(attn_qb, attn_kb, attn_vb, sym(g_qkvb));
    }

    // ---- input splits (body -> [0], limb -> [1]) ----
    split_k<<<(unsigned)(TOKE / 1024), 256>>>(body_feats, xh, xl, TOKE);
    split_k<<<(unsigned)(TOKE / 1024), 256>>>(limb_feats, xh + TOKE, xl + TOKE, TOKE);

    // ---- self attention (batched over body/limb) ----
    bg_sp(xh, xl, wqh, wql, TOKE, WQKV_B, qkvb, NQKV,
          qkvh, qkvl, QKV_B, NTOK, NQKV, EE, NQKV, false);
    flash_k<<<dim3(SS / 128, 2 * NB), 256, FSMEM>>>(qkvh, qkvl, atth, attl, temp);
    bg_f32(atth, attl, owh, owl, TOKE, WEE_B, attn_ob, EE, tmp, TOKE, NTOK, EE, EE, EE);

    // norm1: body uses gamma 0, limb gamma 3
    ln_k<<<NTOK, 128>>>(body_feats, tmp, nsc + 0 * EE, nbi + 0 * EE, bl, s1h, s1l);
    ln_k<<<NTOK, 128>>>(limb_feats, tmp + TOKE, nsc + 3 * EE, nbi + 3 * EE,
                        bl + TOKE, s1h + TOKE, s1l + TOKE);

    // ---- cross attention (batched: z=0 crossB [attn 2], z=1 crossL [attn 3]) ----
    // Q: z=0 body (s1[0]), z=1 limb (s1[1])
    bg_sp(s1h, s1l, wqh + 2 * WQKV_B, wql + 2 * WQKV_B, TOKE, WQKV_B,
          qkvb + 2 * NQKV, NQKV, qkvh, qkvl, QKV_B, NTOK, 512, EE, NQKV, false);
    // KV: z=0 limb (s1[1]), z=1 body (s1[0])  -> base s1+TOKE, stride -TOKE
    bg_sp(s1h + TOKE, s1l + TOKE, wqh + 2 * WQKV_B + (long)512 * EE,
          wql + 2 * WQKV_B + (long)512 * EE, -TOKE, WQKV_B,
          qkvb + 2 * NQKV + 512, NQKV, qkvh + 512, qkvl + 512, QKV_B,
          NTOK, 1024, EE, NQKV, false);
    flash_k<<<dim3(SS / 128, 2 * NB), 256, FSMEM>>>(qkvh, qkvl, atth, attl, temp);
    bg_f32(atth, attl, owh + 2 * WEE_B, owl + 2 * WEE_B, TOKE, WEE_B,
           attn_ob + 2 * EE, EE, cross, TOKE, NTOK, EE, EE, EE);

    // ---- gates + norm2 (gamma 1 on BOTH streams — faithful) ----
    gate_mix_k<<<2 * NTOK, 128>>>(bl, cross, gw, gb, mix);
    ln_k<<<2 * NTOK, 128>>>(mix, nullptr, nsc + 1 * EE, nbi + 1 * EE, bl, s1h, s1l);

    // ---- FFN (batched) ----
    bg_sp(s1h, s1l, w1h, w1l, TOKE, WFF_B, ffn_b1, 4 * EE,
          hidh, hidl, HID_B, NTOK, 4 * EE, EE, 4 * EE, true);
    bg_f32(hidh, hidl, w2h, w2l, HID_B, WFF_B, ffn_b2, EE, ffn, TOKE, NTOK, EE, 4 * EE, EE);

    // final norms: body gamma 2 -> out[0], limb gamma 5 -> out[1]
    ln_k<<<NTOK, 128>>>(bl, ffn, nsc + 2 * EE, nbi + 2 * EE, out);
    ln_k<<<NTOK, 128>>>(bl + TOKE, ffn + TOKE, nsc + 5 * EE, nbi + 5 * EE, out + TOKE);
}

// round 12
// speedup vs baseline: 3.9688x; 1.1623x over previous
#include <cuda_runtime.h>
#include <cuda_bf16.h>
#include <math.h>

typedef unsigned int u32;
typedef unsigned long long u64;
typedef __nv_bfloat16 bf;

#define BB 4
#define SS 1024
#define EE 512
#define NHH 8
#define DD 64
#define NTOK (BB*SS)          // 4096
#define TOKE ((long)NTOK*EE)  // 2,097,152
#define NB (BB*NHH)           // 32
#define NQKV 1536

#define WEE_B ((long)EE*EE)
#define WQKV_B ((long)NQKV*EE)
#define WFF_B ((long)EE*4*EE)
#define QKV_B ((long)NTOK*NQKV)
#define HID_B ((long)NTOK*4*EE)

// ------------------------- fp32 scratch ([2] = body, limb) -------------------------
__device__ float g_tmp[2*NTOK*EE];
__device__ float g_bl[2*NTOK*EE];
__device__ float g_cross[2*NTOK*EE];
__device__ float g_mix[2*NTOK*EE];
__device__ float g_ffn[2*NTOK*EE];
__device__ float g_qkvb[4*NQKV];

// ------------------------- bf16 split scratch (16B aligned) -------------------------
__device__ __align__(16) bf g_xh[2*NTOK*EE], g_xl[2*NTOK*EE];
__device__ __align__(16) bf g_s1h[2*NTOK*EE], g_s1l[2*NTOK*EE];
__device__ __align__(16) bf g_qkvh[(long)2*NTOK*NQKV], g_qkvl[(long)2*NTOK*NQKV];
__device__ __align__(16) bf g_atth[2*NTOK*EE], g_attl[2*NTOK*EE];
__device__ __align__(16) bf g_hidh[(long)2*NTOK*4*EE], g_hidl[(long)2*NTOK*4*EE];
__device__ __align__(16) bf g_wqkvh[(long)4*NQKV*EE], g_wqkvl[(long)4*NQKV*EE];
__device__ __align__(16) bf g_owth[4*EE*EE], g_owtl[4*EE*EE];
__device__ __align__(16) bf g_w1th[(long)2*EE*4*EE], g_w1tl[(long)2*EE*4*EE];
__device__ __align__(16) bf g_w2th[(long)2*EE*4*EE], g_w2tl[(long)2*EE*4*EE];

// ------------------------- asm helpers -------------------------
__device__ __forceinline__ u32 s2u(const void* p) {
    u32 a;
    asm("{ .reg .u64 t; cvta.to.shared.u64 t, %1; cvt.u32.u64 %0, t; }" : "=r"(a) : "l"(p));
    return a;
}
__device__ __forceinline__ void cpa16(u32 saddr, const void* g) {
    asm volatile("cp.async.cg.shared.global [%0], [%1], 16;" :: "r"(saddr), "l"(g));
}
__device__ __forceinline__ void cpcommit() { asm volatile("cp.async.commit_group;"); }
__device__ __forceinline__ void cpwait1()  { asm volatile("cp.async.wait_group 1;"); }
__device__ __forceinline__ void cpwait0()  { asm volatile("cp.async.wait_group 0;"); }

__device__ __forceinline__ void ldsm_x4(u32 r[4], u32 addr) {
    asm volatile("ldmatrix.sync.aligned.m8n8.x4.shared.b16 {%0,%1,%2,%3}, [%4];"
                 : "=r"(r[0]), "=r"(r[1]), "=r"(r[2]), "=r"(r[3]) : "r"(addr));
}
__device__ __forceinline__ void ldsm_x4t(u32 r[4], u32 addr) {
    asm volatile("ldmatrix.sync.aligned.m8n8.x4.trans.shared.b16 {%0,%1,%2,%3}, [%4];"
                 : "=r"(r[0]), "=r"(r[1]), "=r"(r[2]), "=r"(r[3]) : "r"(addr));
}
__device__ __forceinline__ void mma16816(float c[4], const u32 a[4], const u32 b0, const u32 b1) {
    asm volatile(
        "mma.sync.aligned.m16n8k16.row.col.f32.bf16.bf16.f32 "
        "{%0,%1,%2,%3}, {%4,%5,%6,%7}, {%8,%9}, {%0,%1,%2,%3};"
        : "+f"(c[0]), "+f"(c[1]), "+f"(c[2]), "+f"(c[3])
        : "r"(a[0]), "r"(a[1]), "r"(a[2]), "r"(a[3]), "r"(b0), "r"(b1));
}
__device__ __forceinline__ void split2(float x, float y, u32& hp, u32& lp) {
    bf hx = __float2bfloat16(x), hy = __float2bfloat16(y);
    bf lx = __float2bfloat16(x - __bfloat162float(hx));
    bf ly = __float2bfloat16(y - __bfloat162float(hy));
    hp = (u32)__bfloat16_as_ushort(hx) | ((u32)__bfloat16_as_ushort(hy) << 16);
    lp = (u32)__bfloat16_as_ushort(lx) | ((u32)__bfloat16_as_ushort(ly) << 16);
}

// ------------------------- bf16-split tensor-core GEMM, cp.async pipelined -----
// Per batch z: C[i,j] = act(sum_l A[i,l]*B[j,l] + bias[j]); strides per z.
// OMODE: 0 = fp32 C; 2 = bf16 hi/lo (Ch, Cl).
template<int WN, int OMODE, bool GELU>
__global__ void __launch_bounds__(256) gemm_mma(
    const bf* __restrict__ Ah, const bf* __restrict__ Al,
    const bf* __restrict__ Bh, const bf* __restrict__ Bl,
    const float* __restrict__ bias, float* __restrict__ C,
    bf* __restrict__ Ch, bf* __restrict__ Cl,
    int K, int lda, int ldb, int ldc,
    long aB, long bB, long cB, long biasB)
{
    constexpr int BN = 2 * WN;
    constexpr int STR = 40;
    constexpr int ASZ = 128 * STR;
    constexpr int BSZ = BN * STR;
    constexpr int STAGE = 2 * ASZ + 2 * BSZ;

    extern __shared__ __align__(16) bf sm[];

    int z = blockIdx.z;
    Ah += z * aB;  Al += z * aB;
    Bh += z * bB;  Bl += z * bB;
    if (bias) bias += z * biasB;
    long coff = z * cB;

    int i0 = blockIdx.y * 128;
    int j0 = blockIdx.x * BN;
    int tid = threadIdx.x;
    int lane = tid & 31, wid = tid >> 5;
    int wm = wid & 3, wn = wid >> 2;

    float acc[2][WN / 8][4] = {};
    const int nch = K / 32;

    auto load_stage = [&](int c, int s) {
        long kc = (long)c * 32;
        u32 base = s2u(sm + s * STAGE);
        #pragma unroll
        for (int t = 0; t < 2; t++) {
            int idx = tid + t * 256;
            int r = idx >> 2, sg = idx & 3;
            long go = (long)(i0 + r) * lda + kc + sg * 8;
            u32 so = (u32)(r * STR + sg * 8) * 2;
            cpa16(base + so, Ah + go);
            cpa16(base + ASZ * 2 + so, Al + go);
        }
        #pragma unroll
        for (int t = 0; t < BN / 64; t++) {
            int idx = tid + t * 256;
            int r = idx >> 2, sg = idx & 3;
            long go = (long)(j0 + r) * ldb + kc + sg * 8;
            u32 so = (u32)(r * STR + sg * 8) * 2;
            cpa16(base + 4 * ASZ + so, Bh + go);
            cpa16(base + 4 * ASZ + 2 * BSZ + so, Bl + go);
        }
    };

    load_stage(0, 0);
    cpcommit();

    for (int c = 0; c < nch; c++) {
        if (c + 1 < nch) {
            load_stage(c + 1, (c + 1) & 1);
            cpcommit();
            cpwait1();
        } else {
            cpwait0();
        }
        __syncthreads();

        const bf* sAh = sm + (c & 1) * STAGE;
        const bf* sAl = sAh + ASZ;
        const bf* sBh = sAl + ASZ;
        const bf* sBl = sBh + BSZ;

        #pragma unroll
        for (int ks = 0; ks < 2; ks++) {
            u32 afh[2][4], afl[2][4];
            #pragma unroll
            for (int mt = 0; mt < 2; mt++) {
                int row = wm * 32 + mt * 16 + (lane & 15);
                int col = ks * 16 + (lane >> 4) * 8;
                ldsm_x4(afh[mt], s2u(&sAh[row * STR + col]));
                ldsm_x4(afl[mt], s2u(&sAl[row * STR + col]));
            }
            // B: pairs of n-tiles via ldmatrix.x4
            int sel = lane >> 3;
            #pragma unroll
            for (int np = 0; np < WN / 16; np++) {
                int brow = wn * WN + (np * 2 + (sel >> 1)) * 8 + (lane & 7);
                int bcol = ks * 16 + (sel & 1) * 8;
                u32 bh4[4], bl4[4];
                ldsm_x4(bh4, s2u(&sBh[brow * STR + bcol]));
                ldsm_x4(bl4, s2u(&sBl[brow * STR + bcol]));
                #pragma unroll
                for (int q = 0; q < 2; q++) {
                    int nt = np * 2 + q;
                    #pragma unroll
                    for (int mt = 0; mt < 2; mt++) {
                        mma16816(acc[mt][nt], afh[mt], bh4[2 * q], bh4[2 * q + 1]);
                        mma16816(acc[mt][nt], afh[mt], bl4[2 * q], bl4[2 * q + 1]);
                        mma16816(acc[mt][nt], afl[mt], bh4[2 * q], bh4[2 * q + 1]);
                    }
                }
            }
        }
        __syncthreads();
    }

    int grp = lane >> 2, qd = lane & 3;
    #pragma unroll
    for (int mt = 0; mt < 2; mt++) {
        #pragma unroll
        for (int nt = 0; nt < WN / 8; nt++) {
            int n = j0 + wn * WN + nt * 8 + qd * 2;
            float b0 = 0.f, b1 = 0.f;
            if (bias) { b0 = bias[n]; b1 = bias[n + 1]; }
            #pragma unroll
            for (int rh = 0; rh < 2; rh++) {
                int m = i0 + wm * 32 + mt * 16 + grp + rh * 8;
                float x = acc[mt][nt][rh * 2 + 0] + b0;
                float y = acc[mt][nt][rh * 2 + 1] + b1;
                if (GELU) {
                    x = 0.5f * x * (1.f + erff(x * 0.70710678118654752f));
                    y = 0.5f * y * (1.f + erff(y * 0.70710678118654752f));
                }
                long off = coff + (long)m * ldc + n;
                if (OMODE == 0) {
                    *(float2*)&C[off] = make_float2(x, y);
                } else {
                    u32 hp, lp;
                    split2(x, y, hp, lp);
                    *(u32*)&Ch[off] = hp;
                    *(u32*)&Cl[off] = lp;
                }
            }
        }
    }
}

// ------------------------- flash attention (packed QKV, 2 streams) -------------------------
#define KVT 64
#define FSTR 72
#define FQSZ (128 * FSTR)
#define FKSZ (KVT * FSTR)
#define FSTG (4 * FKSZ)
#define FSMEM ((2 * FQSZ + 2 * FSTG) * 2)   // 110,592 B

__global__ void __launch_bounds__(256) flash_k(
    const bf* __restrict__ QKVh, const bf* __restrict__ QKVl,
    bf* __restrict__ Oh, bf* __restrict__ Ol,
    const unsigned* __restrict__ tptr)
{
    extern __shared__ __align__(16) bf fsm[];
    bf* sQh = fsm;
    bf* sQl = fsm + FQSZ;
    bf* stg = fsm + 2 * FQSZ;

    int q0 = blockIdx.x * 128;
    int y = blockIdx.y;
    int strm = y >> 5;
    int z = y & 31;
    int b = z / NHH, h = z - b * NHH;
    long qbase = (long)strm * NTOK * NQKV + (long)b * SS * NQKV + h * DD;
    long obase = (long)strm * TOKE + (long)b * SS * EE;

    int tid = threadIdx.x, lane = tid & 31, w = tid >> 5;
    int grp = lane >> 2, qd = lane & 3;
    int sel = lane >> 3;

    #pragma unroll
    for (int t = 0; t < 4; t++) {
        int idx = tid + t * 256;
        int r = idx >> 3, sg = idx & 7;
        long go = qbase + (long)(q0 + r) * NQKV + sg * 8;
        u32 so = (u32)(r * FSTR + sg * 8) * 2;
        cpa16(s2u(sQh) + so, QKVh + go);
        cpa16(s2u(sQl) + so, QKVl + go);
    }
    auto load_kv = [&](int c, int s) {
        bf* st = stg + s * FSTG;
        int kv0 = c * KVT;
        #pragma unroll
        for (int t = 0; t < 2; t++) {
            int idx = tid + t * 256;
            int r = idx >> 3, sg = idx & 7;
            u32 so = (u32)(r * FSTR + sg * 8) * 2;
            long gk = qbase + 512 + (long)(kv0 + r) * NQKV + sg * 8;
            cpa16(s2u(st) + so, QKVh + gk);
            cpa16(s2u(st + FKSZ) + so, QKVl + gk);
            long gv = qbase + 1024 + (long)(kv0 + r) * NQKV + sg * 8;
            cpa16(s2u(st + 2 * FKSZ) + so, QKVh + gv);
            cpa16(s2u(st + 3 * FKSZ) + so, QKVl + gv);
        }
    };
    load_kv(0, 0);
    cpcommit();

    float scl;
    {
        unsigned u = *tptr;
        float f = __uint_as_float(u);
        float temp = (f > 1e-6f && f < 1e6f) ? f : (float)(int)u;
        scl = 0.125f / temp;
    }

    float m0 = -1e30f, m1 = -1e30f, l0 = 0.f, l1 = 0.f;
    float acc_o[8][4] = {};

    const int NT = SS / KVT;
    for (int c = 0; c < NT; c++) {
        if (c + 1 < NT) { load_kv(c + 1, (c + 1) & 1); cpcommit(); cpwait1(); }
        else cpwait0();
        __syncthreads();
        bf* st = stg + (c & 1) * FSTG;
        bf* sKh = st;
        bf* sKl = st + FKSZ;
        bf* sVh = st + 2 * FKSZ;
        bf* sVl = st + 3 * FKSZ;

        // ---- S = Q K^T ----
        float s_[8][4] = {};
        #pragma unroll
        for (int t = 0; t < 4; t++) {
            u32 ah4[4], al4[4];
            int arow = w * 16 + (lane & 15);
            int acol = t * 16 + (lane >> 4) * 8;
            ldsm_x4(ah4, s2u(&sQh[arow * FSTR + acol]));
            ldsm_x4(al4, s2u(&sQl[arow * FSTR + acol]));
            #pragma unroll
            for (int jp = 0; jp < 4; jp++) {
                int brow = (jp * 2 + (sel >> 1)) * 8 + (lane & 7);
                int bcol = t * 16 + (sel & 1) * 8;
                u32 bh4[4], bl4[4];
                ldsm_x4(bh4, s2u(&sKh[brow * FSTR + bcol]));
                ldsm_x4(bl4, s2u(&sKl[brow * FSTR + bcol]));
                #pragma unroll
                for (int q = 0; q < 2; q++) {
                    int j = jp * 2 + q;
                    mma16816(s_[j], ah4, bh4[2 * q], bh4[2 * q + 1]);
                    mma16816(s_[j], ah4, bl4[2 * q], bl4[2 * q + 1]);
                    mma16816(s_[j], al4, bh4[2 * q], bh4[2 * q + 1]);
                }
            }
        }
        // ---- online softmax ----
        float t0 = -1e30f, t1 = -1e30f;
        #pragma unroll
        for (int j = 0; j < 8; j++) {
            s_[j][0] *= scl; s_[j][1] *= scl; s_[j][2] *= scl; s_[j][3] *= scl;
            t0 = fmaxf(t0, fmaxf(s_[j][0], s_[j][1]));
            t1 = fmaxf(t1, fmaxf(s_[j][2], s_[j][3]));
        }
        t0 = fmaxf(t0, __shfl_xor_sync(0xffffffffu, t0, 1));
        t0 = fmaxf(t0, __shfl_xor_sync(0xffffffffu, t0, 2));
        t1 = fmaxf(t1, __shfl_xor_sync(0xffffffffu, t1, 1));
        t1 = fmaxf(t1, __shfl_xor_sync(0xffffffffu, t1, 2));
        float nm0 = fmaxf(m0, t0), nm1 = fmaxf(m1, t1);
        float corr0 = __expf(m0 - nm0), corr1 = __expf(m1 - nm1);
        m0 = nm0; m1 = nm1;
        float sum0 = 0.f, sum1 = 0.f;
        #pragma unroll
        for (int j = 0; j < 8; j++) {
            s_[j][0] = __expf(s_[j][0] - m0);
            s_[j][1] = __expf(s_[j][1] - m0);
            s_[j][2] = __expf(s_[j][2] - m1);
            s_[j][3] = __expf(s_[j][3] - m1);
            sum0 += s_[j][0] + s_[j][1];
            sum1 += s_[j][2] + s_[j][3];
        }
        sum0 += __shfl_xor_sync(0xffffffffu, sum0, 1);
        sum0 += __shfl_xor_sync(0xffffffffu, sum0, 2);
        sum1 += __shfl_xor_sync(0xffffffffu, sum1, 1);
        sum1 += __shfl_xor_sync(0xffffffffu, sum1, 2);
        l0 = l0 * corr0 + sum0;
        l1 = l1 * corr1 + sum1;
        #pragma unroll
        for (int n = 0; n < 8; n++) {
            acc_o[n][0] *= corr0; acc_o[n][1] *= corr0;
            acc_o[n][2] *= corr1; acc_o[n][3] *= corr1;
        }
        // ---- O += P @ V  (V [kv, d]; x4 trans loads, pairs of d-tiles) ----
        #pragma unroll
        for (int t = 0; t < 4; t++) {
            u32 pah[4], pal[4];
            split2(s_[2 * t][0],     s_[2 * t][1],     pah[0], pal[0]);
            split2(s_[2 * t][2],     s_[2 * t][3],     pah[1], pal[1]);
            split2(s_[2 * t + 1][0], s_[2 * t + 1][1], pah[2], pal[2]);
            split2(s_[2 * t + 1][2], s_[2 * t + 1][3], pah[3], pal[3]);
            int vrow = t * 16 + (lane & 15);
            #pragma unroll
            for (int np = 0; np < 4; np++) {
                int vcol = (np * 2 + (lane >> 4)) * 8;
                u32 bh4[4], bl4[4];
                ldsm_x4t(bh4, s2u(&sVh[vrow * FSTR + vcol]));
                ldsm_x4t(bl4, s2u(&sVl[vrow * FSTR + vcol]));
                #pragma unroll
                for (int q = 0; q < 2; q++) {
                    int n = np * 2 + q;
                    mma16816(acc_o[n], pah, bh4[2 * q], bh4[2 * q + 1]);
                    mma16816(acc_o[n], pah, bl4[2 * q], bl4[2 * q + 1]);
                    mma16816(acc_o[n], pal, bh4[2 * q], bh4[2 * q + 1]);
                }
            }
        }
        __syncthreads();
    }

    float inv0 = 1.f / l0, inv1 = 1.f / l1;
    int r0 = q0 + w * 16 + grp;
    #pragma unroll
    for (int n = 0; n < 8; n++) {
        int col = h * DD + n * 8 + qd * 2;
        {
            long off = obase + (long)r0 * EE + col;
            u32 hp, lp;
            split2(acc_o[n][0] * inv0, acc_o[n][1] * inv0, hp, lp);
            *(u32*)&Oh[off] = hp;
            *(u32*)&Ol[off] = lp;
        }
        {
            long off = obase + (long)(r0 + 8) * EE + col;
            u32 hp, lp;
            split2(acc_o[n][2] * inv1, acc_o[n][3] * inv1, hp, lp);
            *(u32*)&Oh[off] = hp;
            *(u32*)&Ol[off] = lp;
        }
    }
}

// ------------------------- combined input split (both streams) -------------------------
__global__ void insplit_k(const float* __restrict__ b0, const float* __restrict__ b1)
{
    int strm = blockIdx.y;
    const float* x = strm ? b1 : b0;
    long i = ((long)blockIdx.x * blockDim.x + threadIdx.x) * 4;
    float4 v = *(const float4*)(x + i);
    u32 hp[2], lp[2];
    split2(v.x, v.y, hp[0], lp[0]);
    split2(v.z, v.w, hp[1], lp[1]);
    long o = (long)strm * TOKE + i;
    *(uint2*)(g_xh + o) = make_uint2(hp[0], hp[1]);
    *(uint2*)(g_xl + o) = make_uint2(lp[0], lp[1]);
}

// ------------------------- one-launch weight preprocessing -------------------------
// 8192 tiles of 32x32 transpose+split across all weight tensors.
__global__ void wprep_k(const float* __restrict__ qw, const float* __restrict__ kw,
                        const float* __restrict__ vw, const float* __restrict__ ow,
                        const float* __restrict__ w1, const float* __restrict__ w2)
{
    __shared__ float sm[32][33];
    int t = blockIdx.x;
    const float* src;
    bf *dh, *dl;
    int lds, ldd, ry, cx;

    if (t < 4096) {
        int g = t >> 10, rem = t & 1023;
        int b = rem >> 8, tt = rem & 255;
        ry = tt >> 4; cx = tt & 15;
        lds = 512; ldd = 512;
        const float* s4 = (g == 0) ? qw : (g == 1) ? kw : (g == 2) ? vw : ow;
        src = s4 + (long)b * WEE_B;
        if (g < 3) {
            dh = g_wqkvh + (long)b * WQKV_B + (long)g * 512 * EE;
            dl = g_wqkvl + (long)b * WQKV_B + (long)g * 512 * EE;
        } else {
            dh = g_owth + (long)b * WEE_B;
            dl = g_owtl + (long)b * WEE_B;
        }
    } else if (t < 6144) {
        int t2 = t - 4096;
        int b = t2 >> 10, tt = t2 & 1023;
        ry = tt >> 6; cx = tt & 63;        // src 512 x 2048
        lds = 2048; ldd = 512;
        src = w1 + (long)b * WFF_B;
        dh = g_w1th + (long)b * WFF_B;
        dl = g_w1tl + (long)b * WFF_B;
    } else {
        int t3 = t - 6144;
        int b = t3 >> 10, tt = t3 & 1023;
        ry = tt >> 4; cx = tt & 15;        // src 2048 x 512
        lds = 512; ldd = 2048;
        src = w2 + (long)b * WFF_B;
        dh = g_w2th + (long)b * WFF_B;
        dl = g_w2tl + (long)b * WFF_B;
    }

    int r0 = ry * 32, c0 = cx * 32;
    int tx = threadIdx.x, ty = threadIdx.y;
    #pragma unroll
    for (int i = 0; i < 4; i++)
        sm[ty + 8 * i][tx] = src[(long)(r0 + ty + 8 * i) * lds + c0 + tx];
    __syncthreads();
    #pragma unroll
    for (int i = 0; i < 4; i++) {
        int n = c0 + ty + 8 * i, k = r0 + tx;
        float v = sm[tx][ty + 8 * i];
        bf hv = __float2bfloat16(v);
        bf lv = __float2bfloat16(v - __bfloat162float(hv));
        dh[(long)n * ldd + k] = hv;
        dl[(long)n * ldd + k] = lv;
    }
}

// ------------------------- bias packing -------------------------
__global__ void packb_k(const float* __restrict__ qb, const float* __restrict__ kb,
                        const float* __restrict__ vb, float* __restrict__ dst)
{
    int i = blockIdx.y;
    int t = blockIdx.x * 256 + threadIdx.x;
    dst[i * NQKV + t]        = qb[i * EE + t];
    dst[i * NQKV + 512 + t]  = kb[i * EE + t];
    dst[i * NQKV + 1024 + t] = vb[i * EE + t];
}

// ------------------------- batched residual + layernorm (+ optional split out) -----
// grid = 2*NTOK rows; rows >= NTOK use (g1, b1_) and x1.
__global__ void ln2_k(const float* __restrict__ x0, const float* __restrict__ x1,
                      const float* __restrict__ res,
                      const float* __restrict__ g0, const float* __restrict__ b0_,
                      const float* __restrict__ g1, const float* __restrict__ b1_,
                      float* __restrict__ out,
                      bf* __restrict__ oh = nullptr,
                      bf* __restrict__ ol = nullptr)
{
    long row = blockIdx.x;
    int strm = row >= NTOK;
    long r = row - (long)strm * NTOK;
    const float* x = (strm ? x1 : x0) + r * EE;
    const float* gamma = strm ? g1 : g0;
    const float* beta  = strm ? b1_ : b0_;
    int t = threadIdx.x;
    float4 v = ((const float4*)x)[t];
    if (res) {
        float4 rr = ((const float4*)(res + row * EE))[t];
        v.x += rr.x; v.y += rr.y; v.z += rr.z; v.w += rr.w;
    }
    float s = v.x + v.y + v.z + v.w;
    float q = v.x * v.x + v.y * v.y + v.z * v.z + v.w * v.w;
    #pragma unroll
    for (int o = 16; o; o >>= 1) {
        s += __shfl_xor_sync(0xffffffffu, s, o);
        q += __shfl_xor_sync(0xffffffffu, q, o);
    }
    __shared__ float shS[4], shQ[4];
    int w = t >> 5;
    if ((t & 31) == 0) { shS[w] = s; shQ[w] = q; }
    __syncthreads();
    s = shS[0] + shS[1] + shS[2] + shS[3];
    q = shQ[0] + shQ[1] + shQ[2] + shQ[3];
    float mean = s * (1.f / EE);
    float var = q * (1.f / EE) - mean * mean;
    float rstd = rsqrtf(var + 1e-5f);
    float4 g = ((const float4*)gamma)[t];
    float4 b = ((const float4*)beta)[t];
    float4 o;
    o.x = (v.x - mean) * rstd * g.x + b.x;
    o.y = (v.y - mean) * rstd * g.y + b.y;
    o.z = (v.z - mean) * rstd * g.z + b.z;
    o.w = (v.w - mean) * rstd * g.w + b.w;
    ((float4*)(out + row * EE))[t] = o;
    if (oh) {
        u32 hp[2], lp[2];
        split2(o.x, o.y, hp[0], lp[0]);
        split2(o.z, o.w, hp[1], lp[1]);
        *(uint2*)(oh + row * EE + t * 4) = make_uint2(hp[0], hp[1]);
        *(uint2*)(ol + row * EE + t * 4) = make_uint2(lp[0], lp[1]);
    }
}

// ------------------------- gate + mix -------------------------
__global__ void gate_mix_k(const float* __restrict__ x, const float* __restrict__ cr,
                           const float* __restrict__ gw, const float* __restrict__ gb,
                           float* __restrict__ out)
{
    long row = blockIdx.x;
    int t = threadIdx.x;
    float4 xv = ((const float4*)(x + row * EE))[t];
    float4 cv = ((const float4*)(cr + row * EE))[t];
    int k0 = t * 4;
    float l0 = 0.f, l1 = 0.f;
    float xs[4] = {xv.x, xv.y, xv.z, xv.w};
    float cs[4] = {cv.x, cv.y, cv.z, cv.w};
    #pragma unroll
    for (int e = 0; e < 4; e++) {
        int k = k0 + e;
        l0 += xs[e] * gw[k * 2 + 0] + cs[e] * gw[(EE + k) * 2 + 0];
        l1 += xs[e] * gw[k * 2 + 1] + cs[e] * gw[(EE + k) * 2 + 1];
    }
    #pragma unroll
    for (int o = 16; o; o >>= 1) {
        l0 += __shfl_xor_sync(0xffffffffu, l0, o);
        l1 += __shfl_xor_sync(0xffffffffu, l1, o);
    }
    __shared__ float sh0[4], sh1[4];
    int w = t >> 5;
    if ((t & 31) == 0) { sh0[w] = l0; sh1[w] = l1; }
    __syncthreads();
    l0 = sh0[0] + sh0[1] + sh0[2] + sh0[3] + gb[0];
    l1 = sh1[0] + sh1[1] + sh1[2] + sh1[3] + gb[1];
    float m = fmaxf(l0, l1);
    float e0 = __expf(l0 - m), e1 = __expf(l1 - m);
    float g0 = e0 / (e0 + e1), g1 = e1 / (e0 + e1);
    float4 o;
    o.x = xv.x * g0 + cv.x * g1;
    o.y = xv.y * g0 + cv.y * g1;
    o.z = xv.z * g0 + cv.z * g1;
    o.w = xv.w * g0 + cv.w * g1;
    ((float4*)(out + row * EE))[t] = o;
}

// ------------------------- host orchestration -------------------------
static float* sym(const void* s) { void* p = nullptr; cudaGetSymbolAddress(&p, s); return (float*)p; }
static bf* symb(const void* s)   { void* p = nullptr; cudaGetSymbolAddress(&p, s); return (bf*)p; }

#define SMEM64 ((2 * 128 * 40 + 2 * 128 * 40) * 2 * 2)   // 81920 B

static void bg_f32(const bf* ah, const bf* al, const bf* bh, const bf* bl, long aB, long bB,
                   const float* bias, long biasB, float* C, long cB, int M, int N, int K, int ldc) {
    dim3 grid(N / 128, M / 128, 2);
    gemm_mma<64, 0, false><<<grid, 256, SMEM64>>>(ah, al, bh, bl, bias, C, nullptr, nullptr,
        K, K, K, ldc, aB, bB, cB, biasB);
}
static void bg_sp(const bf* ah, const bf* al, const bf* bh, const bf* bl, long aB, long bB,
                  const float* bias, long biasB, bf* Ch, bf* Cl, long cB,
                  int M, int N, int K, int ldc, bool gelu) {
    dim3 grid(N / 128, M / 128, 2);
    if (gelu)
        gemm_mma<64, 2, true><<<grid, 256, SMEM64>>>(ah, al, bh, bl, bias, nullptr, Ch, Cl,
            K, K, K, ldc, aB, bB, cB, biasB);
    else
        gemm_mma<64, 2, false><<<grid, 256, SMEM64>>>(ah, al, bh, bl, bias, nullptr, Ch, Cl,
            K, K, K, ldc, aB, bB, cB, biasB);
}

extern "C" void kernel_launch(void* const* d_in, const int* in_sizes, int n_in,
                              void* d_out, int out_size)
{
    const float* body_feats = (const float*)d_in[0];
    const float* limb_feats = (const float*)d_in[1];
    const float* attn_qw = (const float*)d_in[2];
    const float* attn_qb = (const float*)d_in[3];
    const float* attn_kw = (const float*)d_in[4];
    const float* attn_kb = (const float*)d_in[5];
    const float* attn_vw = (const float*)d_in[6];
    const float* attn_vb = (const float*)d_in[7];
    const float* attn_ow = (const float*)d_in[8];
    const float* attn_ob = (const float*)d_in[9];
    const float* ffn_w1 = (const float*)d_in[10];
    const float* ffn_b1 = (const float*)d_in[11];
    const float* ffn_w2 = (const float*)d_in[12];
    const float* ffn_b2 = (const float*)d_in[13];
    const float* nsc = (const float*)d_in[14];
    const float* nbi = (const float*)d_in[15];
    const float* gw = (const float*)d_in[16];
    const float* gb = (const float*)d_in[17];
    const unsigned* temp = (const unsigned*)d_in[18];

    cudaFuncSetAttribute(gemm_mma<64, 0, false>, cudaFuncAttributeMaxDynamicSharedMemorySize, SMEM64);
    cudaFuncSetAttribute(gemm_mma<64, 2, false>, cudaFuncAttributeMaxDynamicSharedMemorySize, SMEM64);
    cudaFuncSetAttribute(gemm_mma<64, 2, true>,  cudaFuncAttributeMaxDynamicSharedMemorySize, SMEM64);
    cudaFuncSetAttribute(flash_k, cudaFuncAttributeMaxDynamicSharedMemorySize, FSMEM);

    float* out = (float*)d_out;

    float* tmp  = sym(g_tmp);
    float* bl   = sym(g_bl);
    float* cross = sym(g_cross);
    float* mix  = sym(g_mix);
    float* ffn  = sym(g_ffn);
    bf *xh = symb(g_xh), *xl = symb(g_xl);
    bf *s1h = symb(g_s1h), *s1l = symb(g_s1l);
    bf *qkvh = symb(g_qkvh), *qkvl = symb(g_qkvl);
    bf *atth = symb(g_atth), *attl = symb(g_attl);
    bf *hidh = symb(g_hidh), *hidl = symb(g_hidl);
    bf *wqh = symb(g_wqkvh), *wql = symb(g_wqkvl);
    bf *owh = symb(g_owth), *owl = symb(g_owtl);
    bf *w1h = symb(g_w1th), *w1l = symb(g_w1tl);
    bf *w2h = symb(g_w2th), *w2l = symb(g_w2tl);
    const float* qkvb = sym(g_qkvb);

    // ---- preprocessing (2 launches) ----
    wprep_k<<<8192, dim3(32, 8)>>>(attn_qw, attn_kw, attn_vw, attn_ow, ffn_w1, ffn_w2);
    packb_k<<<dim3(2, 4), 256>>>(attn_qb, attn_kb, attn_vb, sym(g_qkvb));

    // ---- input splits (1 launch) ----
    insplit_k<<<dim3((unsigned)(TOKE / 1024), 2), 256>>>(body_feats, limb_feats);

    // ---- self attention (batched over body/limb) ----
    bg_sp(xh, xl, wqh, wql, TOKE, WQKV_B, qkvb, NQKV,
          qkvh, qkvl, QKV_B, NTOK, NQKV, EE, NQKV, false);
    flash_k<<<dim3(SS / 128, 2 * NB), 256, FSMEM>>>(qkvh, qkvl, atth, attl, temp);
    bg_f32(atth, attl, owh, owl, TOKE, WEE_B, attn_ob, EE, tmp, TOKE, NTOK, EE, EE, EE);

    // norm1 (batched): body gamma 0, limb gamma 3
    ln2_k<<<2 * NTOK, 128>>>(body_feats, limb_feats, tmp,
                             nsc + 0 * EE, nbi + 0 * EE, nsc + 3 * EE, nbi + 3 * EE,
                             bl, s1h, s1l);

    // ---- cross attention ----
    bg_sp(s1h, s1l, wqh + 2 * WQKV_B, wql + 2 * WQKV_B, TOKE, WQKV_B,
          qkvb + 2 * NQKV, NQKV, qkvh, qkvl, QKV_B, NTOK, 512, EE, NQKV, false);
    bg_sp(s1h + TOKE, s1l + TOKE, wqh + 2 * WQKV_B + (long)512 * EE,
          wql + 2 * WQKV_B + (long)512 * EE, -TOKE, WQKV_B,
          qkvb + 2 * NQKV + 512, NQKV, qkvh + 512, qkvl + 512, QKV_B,
          NTOK, 1024, EE, NQKV, false);
    flash_k<<<dim3(SS / 128, 2 * NB), 256, FSMEM>>>(qkvh, qkvl, atth, attl, temp);
    bg_f32(atth, attl, owh + 2 * WEE_B, owl + 2 * WEE_B, TOKE, WEE_B,
           attn_ob + 2 * EE, EE, cross, TOKE, NTOK, EE, EE, EE);

    // ---- gates + norm2 (gamma 1 on BOTH streams — faithful) ----
    gate_mix_k<<<2 * NTOK, 128>>>(bl, cross, gw, gb, mix);
    ln2_k<<<2 * NTOK, 128>>>(mix, mix + TOKE, nullptr,
                             nsc + 1 * EE, nbi + 1 * EE, nsc + 1 * EE, nbi + 1 * EE,
                             bl, s1h, s1l);

    // ---- FFN (batched) ----
    bg_sp(s1h, s1l, w1h, w1l, TOKE, WFF_B, ffn_b1, 4 * EE,
          hidh, hidl, HID_B, NTOK, 4 * EE, EE, 4 * EE, true);
    bg_f32(hidh, hidl, w2h, w2l, HID_B, WFF_B, ffn_b2, EE, ffn, TOKE, NTOK, EE, 4 * EE, EE);

    // final norms (batched): body gamma 2, limb gamma 5 -> out
    ln2_k<<<2 * NTOK, 128>>>(bl, bl + TOKE, ffn,
                             nsc + 2 * EE, nbi + 2 * EE, nsc + 5 * EE, nbi + 5 * EE,
                             out, nullptr, nullptr);
}

// round 13
// speedup vs baseline: 4.0138x; 1.0113x over previous
#include <cuda_runtime.h>
#include <cuda_bf16.h>
#include <math.h>

typedef unsigned int u32;
typedef unsigned long long u64;
typedef __nv_bfloat16 bf;

#define BB 4
#define SS 1024
#define EE 512
#define NHH 8
#define DD 64
#define NTOK (BB*SS)          // 4096
#define TOKE ((long)NTOK*EE)  // 2,097,152
#define NB (BB*NHH)           // 32
#define NQKV 1536

#define WEE_B ((long)EE*EE)
#define WQKV_B ((long)NQKV*EE)
#define WFF_B ((long)EE*4*EE)
#define QKV_B ((long)NTOK*NQKV)
#define HID_B ((long)NTOK*4*EE)

// ------------------------- fp32 scratch ([2] = body, limb) -------------------------
__device__ float g_tmp[2*NTOK*EE];
__device__ float g_bl[2*NTOK*EE];
__device__ float g_cross[2*NTOK*EE];
__device__ float g_ffn[2*NTOK*EE];
__device__ float g_qkvb[4*NQKV];

// ------------------------- bf16 split scratch (16B aligned) -------------------------
__device__ __align__(16) bf g_xh[2*NTOK*EE], g_xl[2*NTOK*EE];
__device__ __align__(16) bf g_s1h[2*NTOK*EE], g_s1l[2*NTOK*EE];
__device__ __align__(16) bf g_qkvh[(long)2*NTOK*NQKV], g_qkvl[(long)2*NTOK*NQKV];
__device__ __align__(16) bf g_atth[2*NTOK*EE], g_attl[2*NTOK*EE];
__device__ __align__(16) bf g_hidh[(long)2*NTOK*4*EE], g_hidl[(long)2*NTOK*4*EE];
__device__ __align__(16) bf g_wqkvh[(long)4*NQKV*EE], g_wqkvl[(long)4*NQKV*EE];
__device__ __align__(16) bf g_owth[4*EE*EE], g_owtl[4*EE*EE];
__device__ __align__(16) bf g_w1th[(long)2*EE*4*EE], g_w1tl[(long)2*EE*4*EE];
__device__ __align__(16) bf g_w2th[(long)2*EE*4*EE], g_w2tl[(long)2*EE*4*EE];

// ------------------------- asm helpers -------------------------
__device__ __forceinline__ u32 s2u(const void* p) {
    u32 a;
    asm("{ .reg .u64 t; cvta.to.shared.u64 t, %1; cvt.u32.u64 %0, t; }" : "=r"(a) : "l"(p));
    return a;
}
__device__ __forceinline__ void cpa16(u32 saddr, const void* g) {
    asm volatile("cp.async.cg.shared.global [%0], [%1], 16;" :: "r"(saddr), "l"(g));
}
__device__ __forceinline__ void cpcommit() { asm volatile("cp.async.commit_group;"); }
__device__ __forceinline__ void cpwait1()  { asm volatile("cp.async.wait_group 1;"); }
__device__ __forceinline__ void cpwait0()  { asm volatile("cp.async.wait_group 0;"); }

__device__ __forceinline__ void ldsm_x4(u32 r[4], u32 addr) {
    asm volatile("ldmatrix.sync.aligned.m8n8.x4.shared.b16 {%0,%1,%2,%3}, [%4];"
                 : "=r"(r[0]), "=r"(r[1]), "=r"(r[2]), "=r"(r[3]) : "r"(addr));
}
__device__ __forceinline__ void ldsm_x4t(u32 r[4], u32 addr) {
    asm volatile("ldmatrix.sync.aligned.m8n8.x4.trans.shared.b16 {%0,%1,%2,%3}, [%4];"
                 : "=r"(r[0]), "=r"(r[1]), "=r"(r[2]), "=r"(r[3]) : "r"(addr));
}
__device__ __forceinline__ void mma16816(float c[4], const u32 a[4], const u32 b0, const u32 b1) {
    asm volatile(
        "mma.sync.aligned.m16n8k16.row.col.f32.bf16.bf16.f32 "
        "{%0,%1,%2,%3}, {%4,%5,%6,%7}, {%8,%9}, {%0,%1,%2,%3};"
        : "+f"(c[0]), "+f"(c[1]), "+f"(c[2]), "+f"(c[3])
        : "r"(a[0]), "r"(a[1]), "r"(a[2]), "r"(a[3]), "r"(b0), "r"(b1));
}
__device__ __forceinline__ void split2(float x, float y, u32& hp, u32& lp) {
    bf hx = __float2bfloat16(x), hy = __float2bfloat16(y);
    bf lx = __float2bfloat16(x - __bfloat162float(hx));
    bf ly = __float2bfloat16(y - __bfloat162float(hy));
    hp = (u32)__bfloat16_as_ushort(hx) | ((u32)__bfloat16_as_ushort(hy) << 16);
    lp = (u32)__bfloat16_as_ushort(lx) | ((u32)__bfloat16_as_ushort(ly) << 16);
}

// ------------------------- bf16-split tensor-core GEMM, cp.async pipelined -----
// Per batch z: C[i,j] = act(sum_l A[i,l]*B[j,l] + bias[j]).
// A-offset rule: column tiles with j0 < jsplit use z*aB; others use aOff2 + z*aB2
// (enables fused cross Q/KV with swapped streams). OMODE: 0 fp32; 2 bf16 hi/lo.
template<int WN, int OMODE, bool GELU>
__global__ void __launch_bounds__(256) gemm_mma(
    const bf* __restrict__ Ah, const bf* __restrict__ Al,
    const bf* __restrict__ Bh, const bf* __restrict__ Bl,
    const float* __restrict__ bias, float* __restrict__ C,
    bf* __restrict__ Ch, bf* __restrict__ Cl,
    int K, int lda, int ldb, int ldc,
    long aB, long bB, long cB, long biasB,
    int jsplit, long aOff2, long aB2)
{
    constexpr int BN = 2 * WN;
    constexpr int STR = 40;
    constexpr int ASZ = 128 * STR;
    constexpr int BSZ = BN * STR;
    constexpr int STAGE = 2 * ASZ + 2 * BSZ;

    extern __shared__ __align__(16) bf sm[];

    int z = blockIdx.z;
    int j0 = blockIdx.x * BN;
    long aoff = (j0 < jsplit) ? z * aB : aOff2 + z * aB2;
    Ah += aoff;  Al += aoff;
    Bh += z * bB;  Bl += z * bB;
    if (bias) bias += z * biasB;
    long coff = z * cB;

    int i0 = blockIdx.y * 128;
    int tid = threadIdx.x;
    int lane = tid & 31, wid = tid >> 5;
    int wm = wid & 3, wn = wid >> 2;

    float acc[2][WN / 8][4] = {};
    const int nch = K / 32;

    auto load_stage = [&](int c, int s) {
        long kc = (long)c * 32;
        u32 base = s2u(sm + s * STAGE);
        #pragma unroll
        for (int t = 0; t < 2; t++) {
            int idx = tid + t * 256;
            int r = idx >> 2, sg = idx & 3;
            long go = (long)(i0 + r) * lda + kc + sg * 8;
            u32 so = (u32)(r * STR + sg * 8) * 2;
            cpa16(base + so, Ah + go);
            cpa16(base + ASZ * 2 + so, Al + go);
        }
        #pragma unroll
        for (int t = 0; t < BN / 64; t++) {
            int idx = tid + t * 256;
            int r = idx >> 2, sg = idx & 3;
            long go = (long)(j0 + r) * ldb + kc + sg * 8;
            u32 so = (u32)(r * STR + sg * 8) * 2;
            cpa16(base + 4 * ASZ + so, Bh + go);
            cpa16(base + 4 * ASZ + 2 * BSZ + so, Bl + go);
        }
    };

    load_stage(0, 0);
    cpcommit();

    for (int c = 0; c < nch; c++) {
        if (c + 1 < nch) {
            load_stage(c + 1, (c + 1) & 1);
            cpcommit();
            cpwait1();
        } else {
            cpwait0();
        }
        __syncthreads();

        const bf* sAh = sm + (c & 1) * STAGE;
        const bf* sAl = sAh + ASZ;
        const bf* sBh = sAl + ASZ;
        const bf* sBl = sBh + BSZ;

        #pragma unroll
        for (int ks = 0; ks < 2; ks++) {
            u32 afh[2][4], afl[2][4];
            #pragma unroll
            for (int mt = 0; mt < 2; mt++) {
                int row = wm * 32 + mt * 16 + (lane & 15);
                int col = ks * 16 + (lane >> 4) * 8;
                ldsm_x4(afh[mt], s2u(&sAh[row * STR + col]));
                ldsm_x4(afl[mt], s2u(&sAl[row * STR + col]));
            }
            int sel = lane >> 3;
            #pragma unroll
            for (int np = 0; np < WN / 16; np++) {
                int brow = wn * WN + (np * 2 + (sel >> 1)) * 8 + (lane & 7);
                int bcol = ks * 16 + (sel & 1) * 8;
                u32 bh4[4], bl4[4];
                ldsm_x4(bh4, s2u(&sBh[brow * STR + bcol]));
                ldsm_x4(bl4, s2u(&sBl[brow * STR + bcol]));
                #pragma unroll
                for (int q = 0; q < 2; q++) {
                    int nt = np * 2 + q;
                    #pragma unroll
                    for (int mt = 0; mt < 2; mt++) {
                        mma16816(acc[mt][nt], afh[mt], bh4[2 * q], bh4[2 * q + 1]);
                        mma16816(acc[mt][nt], afh[mt], bl4[2 * q], bl4[2 * q + 1]);
                        mma16816(acc[mt][nt], afl[mt], bh4[2 * q], bh4[2 * q + 1]);
                    }
                }
            }
        }
        __syncthreads();
    }

    int grp = lane >> 2, qd = lane & 3;
    #pragma unroll
    for (int mt = 0; mt < 2; mt++) {
        #pragma unroll
        for (int nt = 0; nt < WN / 8; nt++) {
            int n = j0 + wn * WN + nt * 8 + qd * 2;
            float b0 = 0.f, b1 = 0.f;
            if (bias) { b0 = bias[n]; b1 = bias[n + 1]; }
            #pragma unroll
            for (int rh = 0; rh < 2; rh++) {
                int m = i0 + wm * 32 + mt * 16 + grp + rh * 8;
                float x = acc[mt][nt][rh * 2 + 0] + b0;
                float y = acc[mt][nt][rh * 2 + 1] + b1;
                if (GELU) {
                    x = 0.5f * x * (1.f + erff(x * 0.70710678118654752f));
                    y = 0.5f * y * (1.f + erff(y * 0.70710678118654752f));
                }
                long off = coff + (long)m * ldc + n;
                if (OMODE == 0) {
                    *(float2*)&C[off] = make_float2(x, y);
                } else {
                    u32 hp, lp;
                    split2(x, y, hp, lp);
                    *(u32*)&Ch[off] = hp;
                    *(u32*)&Cl[off] = lp;
                }
            }
        }
    }
}

// ------------------------- flash attention (packed QKV, 2 streams) -------------------------
#define KVT 64
#define FSTR 72
#define FQSZ (128 * FSTR)
#define FKSZ (KVT * FSTR)
#define FSTG (4 * FKSZ)
#define FSMEM ((2 * FQSZ + 2 * FSTG) * 2)   // 110,592 B

__global__ void __launch_bounds__(256) flash_k(
    const bf* __restrict__ QKVh, const bf* __restrict__ QKVl,
    bf* __restrict__ Oh, bf* __restrict__ Ol,
    const unsigned* __restrict__ tptr)
{
    extern __shared__ __align__(16) bf fsm[];
    bf* sQh = fsm;
    bf* sQl = fsm + FQSZ;
    bf* stg = fsm + 2 * FQSZ;

    int q0 = blockIdx.x * 128;
    int y = blockIdx.y;
    int strm = y >> 5;
    int z = y & 31;
    int b = z / NHH, h = z - b * NHH;
    long qbase = (long)strm * NTOK * NQKV + (long)b * SS * NQKV + h * DD;
    long obase = (long)strm * TOKE + (long)b * SS * EE;

    int tid = threadIdx.x, lane = tid & 31, w = tid >> 5;
    int grp = lane >> 2, qd = lane & 3;
    int sel = lane >> 3;

    #pragma unroll
    for (int t = 0; t < 4; t++) {
        int idx = tid + t * 256;
        int r = idx >> 3, sg = idx & 7;
        long go = qbase + (long)(q0 + r) * NQKV + sg * 8;
        u32 so = (u32)(r * FSTR + sg * 8) * 2;
        cpa16(s2u(sQh) + so, QKVh + go);
        cpa16(s2u(sQl) + so, QKVl + go);
    }
    auto load_kv = [&](int c, int s) {
        bf* st = stg + s * FSTG;
        int kv0 = c * KVT;
        #pragma unroll
        for (int t = 0; t < 2; t++) {
            int idx = tid + t * 256;
            int r = idx >> 3, sg = idx & 7;
            u32 so = (u32)(r * FSTR + sg * 8) * 2;
            long gk = qbase + 512 + (long)(kv0 + r) * NQKV + sg * 8;
            cpa16(s2u(st) + so, QKVh + gk);
            cpa16(s2u(st + FKSZ) + so, QKVl + gk);
            long gv = qbase + 1024 + (long)(kv0 + r) * NQKV + sg * 8;
            cpa16(s2u(st + 2 * FKSZ) + so, QKVh + gv);
            cpa16(s2u(st + 3 * FKSZ) + so, QKVl + gv);
        }
    };
    load_kv(0, 0);
    cpcommit();

    float scl;
    {
        unsigned u = *tptr;
        float f = __uint_as_float(u);
        float temp = (f > 1e-6f && f < 1e6f) ? f : (float)(int)u;
        scl = 0.125f / temp;
    }

    float m0 = -1e30f, m1 = -1e30f, l0 = 0.f, l1 = 0.f;
    float acc_o[8][4] = {};

    const int NT = SS / KVT;
    for (int c = 0; c < NT; c++) {
        if (c + 1 < NT) { load_kv(c + 1, (c + 1) & 1); cpcommit(); cpwait1(); }
        else cpwait0();
        __syncthreads();
        bf* st = stg + (c & 1) * FSTG;
        bf* sKh = st;
        bf* sKl = st + FKSZ;
        bf* sVh = st + 2 * FKSZ;
        bf* sVl = st + 3 * FKSZ;

        float s_[8][4] = {};
        #pragma unroll
        for (int t = 0; t < 4; t++) {
            u32 ah4[4], al4[4];
            int arow = w * 16 + (lane & 15);
            int acol = t * 16 + (lane >> 4) * 8;
            ldsm_x4(ah4, s2u(&sQh[arow * FSTR + acol]));
            ldsm_x4(al4, s2u(&sQl[arow * FSTR + acol]));
            #pragma unroll
            for (int jp = 0; jp < 4; jp++) {
                int brow = (jp * 2 + (sel >> 1)) * 8 + (lane & 7);
                int bcol = t * 16 + (sel & 1) * 8;
                u32 bh4[4], bl4[4];
                ldsm_x4(bh4, s2u(&sKh[brow * FSTR + bcol]));
                ldsm_x4(bl4, s2u(&sKl[brow * FSTR + bcol]));
                #pragma unroll
                for (int q = 0; q < 2; q++) {
                    int j = jp * 2 + q;
                    mma16816(s_[j], ah4, bh4[2 * q], bh4[2 * q + 1]);
                    mma16816(s_[j], ah4, bl4[2 * q], bl4[2 * q + 1]);
                    mma16816(s_[j], al4, bh4[2 * q], bh4[2 * q + 1]);
                }
            }
        }
        float t0 = -1e30f, t1 = -1e30f;
        #pragma unroll
        for (int j = 0; j < 8; j++) {
            s_[j][0] *= scl; s_[j][1] *= scl; s_[j][2] *= scl; s_[j][3] *= scl;
            t0 = fmaxf(t0, fmaxf(s_[j][0], s_[j][1]));
            t1 = fmaxf(t1, fmaxf(s_[j][2], s_[j][3]));
        }
        t0 = fmaxf(t0, __shfl_xor_sync(0xffffffffu, t0, 1));
        t0 = fmaxf(t0, __shfl_xor_sync(0xffffffffu, t0, 2));
        t1 = fmaxf(t1, __shfl_xor_sync(0xffffffffu, t1, 1));
        t1 = fmaxf(t1, __shfl_xor_sync(0xffffffffu, t1, 2));
        float nm0 = fmaxf(m0, t0), nm1 = fmaxf(m1, t1);
        float corr0 = __expf(m0 - nm0), corr1 = __expf(m1 - nm1);
        m0 = nm0; m1 = nm1;
        float sum0 = 0.f, sum1 = 0.f;
        #pragma unroll
        for (int j = 0; j < 8; j++) {
            s_[j][0] = __expf(s_[j][0] - m0);
            s_[j][1] = __expf(s_[j][1] - m0);
            s_[j][2] = __expf(s_[j][2] - m1);
            s_[j][3] = __expf(s_[j][3] - m1);
            sum0 += s_[j][0] + s_[j][1];
            sum1 += s_[j][2] + s_[j][3];
        }
        sum0 += __shfl_xor_sync(0xffffffffu, sum0, 1);
        sum0 += __shfl_xor_sync(0xffffffffu, sum0, 2);
        sum1 += __shfl_xor_sync(0xffffffffu, sum1, 1);
        sum1 += __shfl_xor_sync(0xffffffffu, sum1, 2);
        l0 = l0 * corr0 + sum0;
        l1 = l1 * corr1 + sum1;
        #pragma unroll
        for (int n = 0; n < 8; n++) {
            acc_o[n][0] *= corr0; acc_o[n][1] *= corr0;
            acc_o[n][2] *= corr1; acc_o[n][3] *= corr1;
        }
        #pragma unroll
        for (int t = 0; t < 4; t++) {
            u32 pah[4], pal[4];
            split2(s_[2 * t][0],     s_[2 * t][1],     pah[0], pal[0]);
            split2(s_[2 * t][2],     s_[2 * t][3],     pah[1], pal[1]);
            split2(s_[2 * t + 1][0], s_[2 * t + 1][1], pah[2], pal[2]);
            split2(s_[2 * t + 1][2], s_[2 * t + 1][3], pah[3], pal[3]);
            int vrow = t * 16 + (lane & 15);
            #pragma unroll
            for (int np = 0; np < 4; np++) {
                int vcol = (np * 2 + (lane >> 4)) * 8;
                u32 bh4[4], bl4[4];
                ldsm_x4t(bh4, s2u(&sVh[vrow * FSTR + vcol]));
                ldsm_x4t(bl4, s2u(&sVl[vrow * FSTR + vcol]));
                #pragma unroll
                for (int q = 0; q < 2; q++) {
                    int n = np * 2 + q;
                    mma16816(acc_o[n], pah, bh4[2 * q], bh4[2 * q + 1]);
                    mma16816(acc_o[n], pah, bl4[2 * q], bl4[2 * q + 1]);
                    mma16816(acc_o[n], pal, bh4[2 * q], bh4[2 * q + 1]);
                }
            }
        }
        __syncthreads();
    }

    float inv0 = 1.f / l0, inv1 = 1.f / l1;
    int r0 = q0 + w * 16 + grp;
    #pragma unroll
    for (int n = 0; n < 8; n++) {
        int col = h * DD + n * 8 + qd * 2;
        {
            long off = obase + (long)r0 * EE + col;
            u32 hp, lp;
            split2(acc_o[n][0] * inv0, acc_o[n][1] * inv0, hp, lp);
            *(u32*)&Oh[off] = hp;
            *(u32*)&Ol[off] = lp;
        }
        {
            long off = obase + (long)(r0 + 8) * EE + col;
            u32 hp, lp;
            split2(acc_o[n][2] * inv1, acc_o[n][3] * inv1, hp, lp);
            *(u32*)&Oh[off] = hp;
            *(u32*)&Ol[off] = lp;
        }
    }
}

// ------------------------- ONE-launch preprocessing -------------------------
// blocks [0,8192): weight transpose+split; [8192,8200): bias pack;
// [8200,12296): input hi/lo splits for both streams.
__global__ void prep_k(const float* __restrict__ qw, const float* __restrict__ kw,
                       const float* __restrict__ vw, const float* __restrict__ ow,
                       const float* __restrict__ w1, const float* __restrict__ w2,
                       const float* __restrict__ qb, const float* __restrict__ kb,
                       const float* __restrict__ vb,
                       const float* __restrict__ in0, const float* __restrict__ in1)
{
    int t = blockIdx.x;
    int tx = threadIdx.x, ty = threadIdx.y;
    int ltid = ty * 32 + tx;

    if (t >= 8200) {
        // input splits: 4096 blocks, 1024 elems each
        int idx = t - 8200;
        int strm = idx >> 11;
        long i = (long)(idx & 2047) * 1024 + ltid * 4;
        const float* x = strm ? in1 : in0;
        float4 v = *(const float4*)(x + i);
        u32 hp[2], lp[2];
        split2(v.x, v.y, hp[0], lp[0]);
        split2(v.z, v.w, hp[1], lp[1]);
        long o = (long)strm * TOKE + i;
        *(uint2*)(g_xh + o) = make_uint2(hp[0], hp[1]);
        *(uint2*)(g_xl + o) = make_uint2(lp[0], lp[1]);
        return;
    }
    if (t >= 8192) {
        // bias pack: 8 blocks
        int blk = t - 8192;
        int i = blk >> 1;
        int tt = (blk & 1) * 256 + ltid;
        g_qkvb[i * NQKV + tt]        = qb[i * EE + tt];
        g_qkvb[i * NQKV + 512 + tt]  = kb[i * EE + tt];
        g_qkvb[i * NQKV + 1024 + tt] = vb[i * EE + tt];
        return;
    }

    __shared__ float sm[32][33];
    const float* src;
    bf *dh, *dl;
    int lds, ldd, ry, cx;

    if (t < 4096) {
        int g = t >> 10, rem = t & 1023;
        int b = rem >> 8, tt = rem & 255;
        ry = tt >> 4; cx = tt & 15;
        lds = 512; ldd = 512;
        const float* s4 = (g == 0) ? qw : (g == 1) ? kw : (g == 2) ? vw : ow;
        src = s4 + (long)b * WEE_B;
        if (g < 3) {
            dh = g_wqkvh + (long)b * WQKV_B + (long)g * 512 * EE;
            dl = g_wqkvl + (long)b * WQKV_B + (long)g * 512 * EE;
        } else {
            dh = g_owth + (long)b * WEE_B;
            dl = g_owtl + (long)b * WEE_B;
        }
    } else if (t < 6144) {
        int t2 = t - 4096;
        int b = t2 >> 10, tt = t2 & 1023;
        ry = tt >> 6; cx = tt & 63;
        lds = 2048; ldd = 512;
        src = w1 + (long)b * WFF_B;
        dh = g_w1th + (long)b * WFF_B;
        dl = g_w1tl + (long)b * WFF_B;
    } else {
        int t3 = t - 6144;
        int b = t3 >> 10, tt = t3 & 1023;
        ry = tt >> 4; cx = tt & 15;
        lds = 512; ldd = 2048;
        src = w2 + (long)b * WFF_B;
        dh = g_w2th + (long)b * WFF_B;
        dl = g_w2tl + (long)b * WFF_B;
    }

    int r0 = ry * 32, c0 = cx * 32;
    #pragma unroll
    for (int i = 0; i < 4; i++)
        sm[ty + 8 * i][tx] = src[(long)(r0 + ty + 8 * i) * lds + c0 + tx];
    __syncthreads();
    #pragma unroll
    for (int i = 0; i < 4; i++) {
        int n = c0 + ty + 8 * i, k = r0 + tx;
        float v = sm[tx][ty + 8 * i];
        bf hv = __float2bfloat16(v);
        bf lv = __float2bfloat16(v - __bfloat162float(hv));
        dh[(long)n * ldd + k] = hv;
        dl[(long)n * ldd + k] = lv;
    }
}

// ------------------------- batched residual + layernorm (+ optional split out) -----
__global__ void ln2_k(const float* __restrict__ x0, const float* __restrict__ x1,
                      const float* __restrict__ res,
                      const float* __restrict__ g0, const float* __restrict__ b0_,
                      const float* __restrict__ g1, const float* __restrict__ b1_,
                      float* __restrict__ out,
                      bf* __restrict__ oh = nullptr,
                      bf* __restrict__ ol = nullptr)
{
    long row = blockIdx.x;
    int strm = row >= NTOK;
    long r = row - (long)strm * NTOK;
    const float* x = (strm ? x1 : x0) + r * EE;
    const float* gamma = strm ? g1 : g0;
    const float* beta  = strm ? b1_ : b0_;
    int t = threadIdx.x;
    float4 v = ((const float4*)x)[t];
    if (res) {
        float4 rr = ((const float4*)(res + row * EE))[t];
        v.x += rr.x; v.y += rr.y; v.z += rr.z; v.w += rr.w;
    }
    float s = v.x + v.y + v.z + v.w;
    float q = v.x * v.x + v.y * v.y + v.z * v.z + v.w * v.w;
    #pragma unroll
    for (int o = 16; o; o >>= 1) {
        s += __shfl_xor_sync(0xffffffffu, s, o);
        q += __shfl_xor_sync(0xffffffffu, q, o);
    }
    __shared__ float shS[4], shQ[4];
    int w = t >> 5;
    if ((t & 31) == 0) { shS[w] = s; shQ[w] = q; }
    __syncthreads();
    s = shS[0] + shS[1] + shS[2] + shS[3];
    q = shQ[0] + shQ[1] + shQ[2] + shQ[3];
    float mean = s * (1.f / EE);
    float var = q * (1.f / EE) - mean * mean;
    float rstd = rsqrtf(var + 1e-5f);
    float4 g = ((const float4*)gamma)[t];
    float4 b = ((const float4*)beta)[t];
    float4 o;
    o.x = (v.x - mean) * rstd * g.x + b.x;
    o.y = (v.y - mean) * rstd * g.y + b.y;
    o.z = (v.z - mean) * rstd * g.z + b.z;
    o.w = (v.w - mean) * rstd * g.w + b.w;
    ((float4*)(out + row * EE))[t] = o;
    if (oh) {
        u32 hp[2], lp[2];
        split2(o.x, o.y, hp[0], lp[0]);
        split2(o.z, o.w, hp[1], lp[1]);
        *(uint2*)(oh + row * EE + t * 4) = make_uint2(hp[0], hp[1]);
        *(uint2*)(ol + row * EE + t * 4) = make_uint2(lp[0], lp[1]);
    }
}

// ------------------------- fused gate + mix + norm2 (gamma shared) -------------------------
__global__ void gate_mix_ln_k(const float* __restrict__ x, const float* __restrict__ cr,
                              const float* __restrict__ gw, const float* __restrict__ gb,
                              const float* __restrict__ gamma, const float* __restrict__ beta,
                              float* __restrict__ out,
                              bf* __restrict__ oh, bf* __restrict__ ol)
{
    long row = blockIdx.x;
    int t = threadIdx.x;
    float4 xv = ((const float4*)(x + row * EE))[t];
    float4 cv = ((const float4*)(cr + row * EE))[t];
    int k0 = t * 4;
    float l0 = 0.f, l1 = 0.f;
    float xs[4] = {xv.x, xv.y, xv.z, xv.w};
    float cs[4] = {cv.x, cv.y, cv.z, cv.w};
    #pragma unroll
    for (int e = 0; e < 4; e++) {
        int k = k0 + e;
        l0 += xs[e] * gw[k * 2 + 0] + cs[e] * gw[(EE + k) * 2 + 0];
        l1 += xs[e] * gw[k * 2 + 1] + cs[e] * gw[(EE + k) * 2 + 1];
    }
    #pragma unroll
    for (int o = 16; o; o >>= 1) {
        l0 += __shfl_xor_sync(0xffffffffu, l0, o);
        l1 += __shfl_xor_sync(0xffffffffu, l1, o);
    }
    __shared__ float sh0[4], sh1[4];
    int w = t >> 5;
    if ((t & 31) == 0) { sh0[w] = l0; sh1[w] = l1; }
    __syncthreads();
    l0 = sh0[0] + sh0[1] + sh0[2] + sh0[3] + gb[0];
    l1 = sh1[0] + sh1[1] + sh1[2] + sh1[3] + gb[1];
    float mx = fmaxf(l0, l1);
    float e0 = __expf(l0 - mx), e1 = __expf(l1 - mx);
    float gg0 = e0 / (e0 + e1), gg1 = e1 / (e0 + e1);
    float4 v;
    v.x = xv.x * gg0 + cv.x * gg1;
    v.y = xv.y * gg0 + cv.y * gg1;
    v.z = xv.z * gg0 + cv.z * gg1;
    v.w = xv.w * gg0 + cv.w * gg1;

    // ---- LayerNorm on mixed value (in registers) ----
    float s = v.x + v.y + v.z + v.w;
    float q = v.x * v.x + v.y * v.y + v.z * v.z + v.w * v.w;
    #pragma unroll
    for (int o = 16; o; o >>= 1) {
        s += __shfl_xor_sync(0xffffffffu, s, o);
        q += __shfl_xor_sync(0xffffffffu, q, o);
    }
    __syncthreads();
    if ((t & 31) == 0) { sh0[w] = s; sh1[w] = q; }
    __syncthreads();
    s = sh0[0] + sh0[1] + sh0[2] + sh0[3];
    q = sh1[0] + sh1[1] + sh1[2] + sh1[3];
    float mean = s * (1.f / EE);
    float var = q * (1.f / EE) - mean * mean;
    float rstd = rsqrtf(var + 1e-5f);
    float4 g = ((const float4*)gamma)[t];
    float4 b = ((const float4*)beta)[t];
    float4 o;
    o.x = (v.x - mean) * rstd * g.x + b.x;
    o.y = (v.y - mean) * rstd * g.y + b.y;
    o.z = (v.z - mean) * rstd * g.z + b.z;
    o.w = (v.w - mean) * rstd * g.w + b.w;
    ((float4*)(out + row * EE))[t] = o;
    u32 hp[2], lp[2];
    split2(o.x, o.y, hp[0], lp[0]);
    split2(o.z, o.w, hp[1], lp[1]);
    *(uint2*)(oh + row * EE + t * 4) = make_uint2(hp[0], hp[1]);
    *(uint2*)(ol + row * EE + t * 4) = make_uint2(lp[0], lp[1]);
}

// ------------------------- host orchestration -------------------------
static float* sym(const void* s) { void* p = nullptr; cudaGetSymbolAddress(&p, s); return (float*)p; }
static bf* symb(const void* s)   { void* p = nullptr; cudaGetSymbolAddress(&p, s); return (bf*)p; }

#define SMEM64 ((2 * 128 * 40 + 2 * 128 * 40) * 2 * 2)   // 81920 B
#define JBIG (1 << 30)

static void bg_f32(const bf* ah, const bf* al, const bf* bh, const bf* bl, long aB, long bB,
                   const float* bias, long biasB, float* C, long cB, int M, int N, int K, int ldc) {
    dim3 grid(N / 128, M / 128, 2);
    gemm_mma<64, 0, false><<<grid, 256, SMEM64>>>(ah, al, bh, bl, bias, C, nullptr, nullptr,
        K, K, K, ldc, aB, bB, cB, biasB, JBIG, 0, 0);
}
static void bg_sp(const bf* ah, const bf* al, const bf* bh, const bf* bl, long aB, long bB,
                  const float* bias, long biasB, bf* Ch, bf* Cl, long cB,
                  int M, int N, int K, int ldc, bool gelu,
                  int jsplit = JBIG, long aOff2 = 0, long aB2 = 0) {
    dim3 grid(N / 128, M / 128, 2);
    if (gelu)
        gemm_mma<64, 2, true><<<grid, 256, SMEM64>>>(ah, al, bh, bl, bias, nullptr, Ch, Cl,
            K, K, K, ldc, aB, bB, cB, biasB, jsplit, aOff2, aB2);
    else
        gemm_mma<64, 2, false><<<grid, 256, SMEM64>>>(ah, al, bh, bl, bias, nullptr, Ch, Cl,
            K, K, K, ldc, aB, bB, cB, biasB, jsplit, aOff2, aB2);
}

extern "C" void kernel_launch(void* const* d_in, const int* in_sizes, int n_in,
                              void* d_out, int out_size)
{
    const float* body_feats = (const float*)d_in[0];
    const float* limb_feats = (const float*)d_in[1];
    const float* attn_qw = (const float*)d_in[2];
    const float* attn_qb = (const float*)d_in[3];
    const float* attn_kw = (const float*)d_in[4];
    const float* attn_kb = (const float*)d_in[5];
    const float* attn_vw = (const float*)d_in[6];
    const float* attn_vb = (const float*)d_in[7];
    const float* attn_ow = (const float*)d_in[8];
    const float* attn_ob = (const float*)d_in[9];
    const float* ffn_w1 = (const float*)d_in[10];
    const float* ffn_b1 = (const float*)d_in[11];
    const float* ffn_w2 = (const float*)d_in[12];
    const float* ffn_b2 = (const float*)d_in[13];
    const float* nsc = (const float*)d_in[14];
    const float* nbi = (const float*)d_in[15];
    const float* gw = (const float*)d_in[16];
    const float* gb = (const float*)d_in[17];
    const unsigned* temp = (const unsigned*)d_in[18];

    cudaFuncSetAttribute(gemm_mma<64, 0, false>, cudaFuncAttributeMaxDynamicSharedMemorySize, SMEM64);
    cudaFuncSetAttribute(gemm_mma<64, 2, false>, cudaFuncAttributeMaxDynamicSharedMemorySize, SMEM64);
    cudaFuncSetAttribute(gemm_mma<64, 2, true>,  cudaFuncAttributeMaxDynamicSharedMemorySize, SMEM64);
    cudaFuncSetAttribute(flash_k, cudaFuncAttributeMaxDynamicSharedMemorySize, FSMEM);

    float* out = (float*)d_out;

    float* tmp  = sym(g_tmp);
    float* bl   = sym(g_bl);
    float* cross = sym(g_cross);
    float* ffn  = sym(g_ffn);
    bf *xh = symb(g_xh), *xl = symb(g_xl);
    bf *s1h = symb(g_s1h), *s1l = symb(g_s1l);
    bf *qkvh = symb(g_qkvh), *qkvl = symb(g_qkvl);
    bf *atth = symb(g_atth), *attl = symb(g_attl);
    bf *hidh = symb(g_hidh), *hidl = symb(g_hidl);
    bf *wqh = symb(g_wqkvh), *wql = symb(g_wqkvl);
    bf *owh = symb(g_owth), *owl = symb(g_owtl);
    bf *w1h = symb(g_w1th), *w1l = symb(g_w1tl);
    bf *w2h = symb(g_w2th), *w2l = symb(g_w2tl);
    const float* qkvb = sym(g_qkvb);

    // ---- preprocessing (ONE launch) ----
    prep_k<<<12296, dim3(32, 8)>>>(attn_qw, attn_kw, attn_vw, attn_ow, ffn_w1, ffn_w2,
                                   attn_qb, attn_kb, attn_vb, body_feats, limb_feats);

    // ---- self attention (batched over body/limb) ----
    bg_sp(xh, xl, wqh, wql, TOKE, WQKV_B, qkvb, NQKV,
          qkvh, qkvl, QKV_B, NTOK, NQKV, EE, NQKV, false);
    flash_k<<<dim3(SS / 128, 2 * NB), 256, FSMEM>>>(qkvh, qkvl, atth, attl, temp);
    bg_f32(atth, attl, owh, owl, TOKE, WEE_B, attn_ob, EE, tmp, TOKE, NTOK, EE, EE, EE);

    // norm1 (batched): body gamma 0, limb gamma 3
    ln2_k<<<2 * NTOK, 128>>>(body_feats, limb_feats, tmp,
                             nsc + 0 * EE, nbi + 0 * EE, nsc + 3 * EE, nbi + 3 * EE,
                             bl, s1h, s1l);

    // ---- cross attention: ONE fused QKV launch ----
    // cols [0,512): Q from s1[z] (stride +TOKE); cols [512,1536): KV from s1[1-z]
    bg_sp(s1h, s1l, wqh + 2 * WQKV_B, wql + 2 * WQKV_B, TOKE, WQKV_B,
          qkvb + 2 * NQKV, NQKV, qkvh, qkvl, QKV_B, NTOK, NQKV, EE, NQKV, false,
          /*jsplit=*/512, /*aOff2=*/TOKE, /*aB2=*/-TOKE);
    flash_k<<<dim3(SS / 128, 2 * NB), 256, FSMEM>>>(qkvh, qkvl, atth, attl, temp);
    bg_f32(atth, attl, owh + 2 * WEE_B, owl + 2 * WEE_B, TOKE, WEE_B,
           attn_ob + 2 * EE, EE, cross, TOKE, NTOK, EE, EE, EE);

    // ---- fused gate + mix + norm2 (gamma 1 on BOTH streams — faithful) ----
    gate_mix_ln_k<<<2 * NTOK, 128>>>(bl, cross, gw, gb,
                                     nsc + 1 * EE, nbi + 1 * EE, bl, s1h, s1l);

    // ---- FFN (batched) ----
    bg_sp(s1h, s1l, w1h, w1l, TOKE, WFF_B, ffn_b1, 4 * EE,
          hidh, hidl, HID_B, NTOK, 4 * EE, EE, 4 * EE, true);
    bg_f32(hidh, hidl, w2h, w2l, HID_B, WFF_B, ffn_b2, EE, ffn, TOKE, NTOK, EE, 4 * EE, EE);

    // final norms (batched): body gamma 2, limb gamma 5 -> out
    ln2_k<<<2 * NTOK, 128>>>(bl, bl + TOKE, ffn,
                             nsc + 2 * EE, nbi + 2 * EE, nsc + 5 * EE, nbi + 5 * EE,
                             out, nullptr, nullptr);
}